// round 2
// baseline (speedup 1.0000x reference)
#include <cuda_runtime.h>

#define NN 50000
#define EE 800000
#define HH 128
#define PP 16

// ---------------- scratch (device globals; no allocation allowed) -----------
__device__ float g_h[NN * HH];
__device__ float g_m1[NN * HH];
__device__ float g_m2[NN * HH];
__device__ float g_macc[NN * HH];
__device__ float g_mi[NN * HH];
__device__ float g_t[NN * HH];
__device__ float g_scat[NN * 2];
__device__ int   g_cnt[NN];
__device__ float g_Wc[HH * HH];
__device__ float g_bc[HH];

// ---------------- helpers ---------------------------------------------------
__device__ __forceinline__ void red_add_v4(float* p, float a, float b, float c, float d) {
    asm volatile("red.global.add.v4.f32 [%0], {%1,%2,%3,%4};"
                 :: "l"(p), "f"(a), "f"(b), "f"(c), "f"(d) : "memory");
}
__device__ __forceinline__ void red_add_v2(float* p, float a, float b) {
    asm volatile("red.global.add.v2.f32 [%0], {%1,%2};"
                 :: "l"(p), "f"(a), "f"(b) : "memory");
}

// ---------------- tiny kernels ----------------------------------------------
__global__ void zero_cnt_kernel() {
    int i = blockIdx.x * blockDim.x + threadIdx.x;
    if (i < NN) g_cnt[i] = 0;
}

__global__ void count_kernel(const int* __restrict__ ei) {
    int e = blockIdx.x * blockDim.x + threadIdx.x;
    if (e < EE) atomicAdd(&g_cnt[ei[e]], 1);
}

__global__ void zero_accum_kernel() {
    int i = blockIdx.x * blockDim.x + threadIdx.x;
    int stride = gridDim.x * blockDim.x;
    for (int k = i; k < NN * HH; k += stride) g_macc[k] = 0.f;
    for (int k = i; k < NN * 2; k += stride) g_scat[k] = 0.f;
}

// Wc = e_W2 @ c_W1  (128x128),  bc = e_b2 @ c_W1 + c_b1
__global__ void prep_wc_kernel(const float* __restrict__ eW2, const float* __restrict__ cW1,
                               const float* __restrict__ eb2, const float* __restrict__ cb1) {
    int i = blockIdx.x, j = threadIdx.x;
    float s = 0.f;
    for (int k = 0; k < HH; k++) s += eW2[i * HH + k] * cW1[k * HH + j];
    g_Wc[i * HH + j] = s;
    if (i == 0) {
        float t = 0.f;
        for (int k = 0; k < HH; k++) t += eb2[k] * cW1[k * HH + j];
        g_bc[j] = t + cb1[j];
    }
}

// h = h0 @ emb_W + emb_b  ([N,16] @ [16,128])
__global__ void embed_kernel(const float* __restrict__ h0, const float* __restrict__ W,
                             const float* __restrict__ b) {
    int row = blockIdx.x * 2 + (threadIdx.x >> 7);
    int j = threadIdx.x & 127;
    if (row >= NN) return;
    float s = b[j];
#pragma unroll
    for (int k = 0; k < PP; k++) s += h0[row * PP + k] * W[k * HH + j];
    g_h[row * HH + j] = s;
}

// ---------------- generic node GEMM -----------------------------------------
// C[M,128] = act( A1@B1 (+ A2@B2) + bias*(cnt? cnt[m]:1) (+ resid) )
// tile: 64 rows x 128 cols, 256 threads, thread-tile 4x8
#define NG_SMEM ((64 * 129 + 128 * 128 + 128) * 4)

__global__ void node_gemm(const float* __restrict__ A1, const float* __restrict__ B1,
                          const float* __restrict__ A2, const float* __restrict__ B2,
                          const float* __restrict__ bias, const int* __restrict__ cnt,
                          const float* __restrict__ resid, float* __restrict__ C,
                          int M, int do_relu) {
    extern __shared__ float sm[];
    float* As = sm;                 // 64*129
    float* Bs = sm + 64 * 129;      // 128*128
    float* bs = Bs + 128 * 128;     // 128
    const int tid = threadIdx.x;
    const int tx = tid & 15, ty = tid >> 4;
    const int m0 = blockIdx.x * 64;

    if (tid < 128) bs[tid] = bias ? bias[tid] : 0.f;

    float acc[4][8];
#pragma unroll
    for (int i = 0; i < 4; i++)
#pragma unroll
        for (int j = 0; j < 8; j++) acc[i][j] = 0.f;

    const int nsrc = A2 ? 2 : 1;
    for (int s = 0; s < nsrc; s++) {
        const float* A = s ? A2 : A1;
        const float* B = s ? B2 : B1;
        // load A tile 64x128 (guarded)
        for (int idx = tid; idx < 64 * 32; idx += 256) {
            int r = idx >> 5, c4 = (idx & 31) << 2;
            int gr = m0 + r;
            float4 v = (gr < M) ? *(const float4*)&A[gr * HH + c4] : make_float4(0, 0, 0, 0);
            As[r * 129 + c4 + 0] = v.x;
            As[r * 129 + c4 + 1] = v.y;
            As[r * 129 + c4 + 2] = v.z;
            As[r * 129 + c4 + 3] = v.w;
        }
        // load B 128x128
        for (int idx = tid; idx < 128 * 32; idx += 256) {
            int r = idx >> 5, c4 = (idx & 31) << 2;
            *(float4*)&Bs[r * HH + c4] = *(const float4*)&B[r * HH + c4];
        }
        __syncthreads();
#pragma unroll 4
        for (int k = 0; k < 128; k++) {
            float a[4];
#pragma unroll
            for (int i = 0; i < 4; i++) a[i] = As[(ty * 4 + i) * 129 + k];
            float4 b0 = *(float4*)&Bs[k * HH + tx * 8];
            float4 b1 = *(float4*)&Bs[k * HH + tx * 8 + 4];
#pragma unroll
            for (int i = 0; i < 4; i++) {
                acc[i][0] += a[i] * b0.x; acc[i][1] += a[i] * b0.y;
                acc[i][2] += a[i] * b0.z; acc[i][3] += a[i] * b0.w;
                acc[i][4] += a[i] * b1.x; acc[i][5] += a[i] * b1.y;
                acc[i][6] += a[i] * b1.z; acc[i][7] += a[i] * b1.w;
            }
        }
        __syncthreads();
    }
    // epilogue
#pragma unroll
    for (int i = 0; i < 4; i++) {
        int m = m0 + ty * 4 + i;
        if (m >= M) continue;
        float bm = cnt ? (float)cnt[m] : 1.f;
        float o[8];
#pragma unroll
        for (int j = 0; j < 8; j++) o[j] = acc[i][j] + bs[tx * 8 + j] * bm;
        if (resid) {
            float4 r0 = *(const float4*)&resid[m * HH + tx * 8];
            float4 r1 = *(const float4*)&resid[m * HH + tx * 8 + 4];
            o[0] += r0.x; o[1] += r0.y; o[2] += r0.z; o[3] += r0.w;
            o[4] += r1.x; o[5] += r1.y; o[6] += r1.z; o[7] += r1.w;
        }
        if (do_relu) {
#pragma unroll
            for (int j = 0; j < 8; j++) o[j] = fmaxf(o[j], 0.f);
        }
        *(float4*)&C[m * HH + tx * 8]     = make_float4(o[0], o[1], o[2], o[3]);
        *(float4*)&C[m * HH + tx * 8 + 4] = make_float4(o[4], o[5], o[6], o[7]);
    }
}

// ---------------- edge kernel ------------------------------------------------
// Per 64-edge tile:
//  phase 1: z = m1[row] + m2[col] + rel_dist*wd + b1; r = relu(z);
//           red-add r into g_macc[row] (v4)
//  phase 2 (last layer only): u = r @ Wc + bc; coord = relu(u)@cW2 + cb2;
//           red-add rel_pos2*coord into g_scat[row] (v2)
#define EK_SMEM ((16384 + 64 * 129 + 4 * 128 + 3 * 64 + 64 * 17 + 128) * 4)

template <bool DO_COORD>
__global__ void edge_kernel(const float* __restrict__ x, const int* __restrict__ ei,
                            const float* __restrict__ eW1, const float* __restrict__ eb1,
                            const float* __restrict__ cW2, const float* __restrict__ cb2) {
    extern __shared__ float sm[];
    float* Wc_s  = sm;                    // 16384
    float* r_s   = sm + 16384;            // 64*129
    float* wd_s  = r_s + 64 * 129;        // 128
    float* b1_s  = wd_s + 128;            // 128
    float* bc_s  = b1_s + 128;            // 128
    float* cw2_s = bc_s + 128;            // 128
    float* p2a_s = cw2_s + 128;           // 64
    float* p2b_s = p2a_s + 64;            // 64
    float* rd_s  = p2b_s + 64;            // 64
    float* red_s = rd_s + 64;             // 64*17
    int* row_s = (int*)(red_s + 64 * 17); // 64
    int* col_s = row_s + 64;              // 64

    const int tid = threadIdx.x;
    if (tid < 128) {
        wd_s[tid] = eW1[256 * HH + tid];
        b1_s[tid] = eb1[tid];
        if (DO_COORD) { bc_s[tid] = g_bc[tid]; cw2_s[tid] = cW2[tid]; }
    }
    if (tid < 64) {
        int eg = blockIdx.x * 64 + tid;
        int r = ei[eg], c = ei[EE + eg];
        row_s[tid] = r; col_s[tid] = c;
        float2 xr = *(const float2*)&x[2 * r];
        float2 xc = *(const float2*)&x[2 * c];
        float dx = xr.x - xc.x, dy = xr.y - xc.y;
        rd_s[tid]  = dx * dx + dy * dy;
        p2a_s[tid] = dx * dx - dy * dy;   // rel_dist*cos(2th)
        p2b_s[tid] = 2.f * dx * dy;       // rel_dist*sin(2th)
    }
    if (DO_COORD) {
        for (int idx = tid; idx < 4096; idx += 256)
            *(float4*)&Wc_s[idx * 4] = *(const float4*)&g_Wc[idx * 4];
    }
    __syncthreads();

    // phase 1: one warp per edge row (coalesced m1/m2 row reads)
#pragma unroll
    for (int s = 0; s < 8; s++) {
        int item = tid + s * 256;
        int e = item >> 5, j = (item & 31) << 2;
        int r = row_s[e], c = col_s[e];
        float rd = rd_s[e];
        float4 a  = *(const float4*)&g_m1[r * HH + j];
        float4 b  = *(const float4*)&g_m2[c * HH + j];
        float4 w  = *(const float4*)&wd_s[j];
        float4 bb = *(const float4*)&b1_s[j];
        float v0 = fmaxf(a.x + b.x + rd * w.x + bb.x, 0.f);
        float v1 = fmaxf(a.y + b.y + rd * w.y + bb.y, 0.f);
        float v2 = fmaxf(a.z + b.z + rd * w.z + bb.z, 0.f);
        float v3 = fmaxf(a.w + b.w + rd * w.w + bb.w, 0.f);
        red_add_v4(&g_macc[r * HH + j], v0, v1, v2, v3);
        if (DO_COORD) {
            r_s[e * 129 + j + 0] = v0; r_s[e * 129 + j + 1] = v1;
            r_s[e * 129 + j + 2] = v2; r_s[e * 129 + j + 3] = v3;
        }
    }
    if (!DO_COORD) return;
    __syncthreads();

    // phase 2: 64x128 = r @ Wc, relu, dot with cW2
    const int tx = tid & 15, ty = tid >> 4;
    float acc[4][8];
#pragma unroll
    for (int i = 0; i < 4; i++)
#pragma unroll
        for (int j = 0; j < 8; j++) acc[i][j] = 0.f;
#pragma unroll 4
    for (int k = 0; k < 128; k++) {
        float a[4];
#pragma unroll
        for (int i = 0; i < 4; i++) a[i] = r_s[(ty * 4 + i) * 129 + k];
        float4 b0 = *(float4*)&Wc_s[k * HH + tx * 8];
        float4 b1 = *(float4*)&Wc_s[k * HH + tx * 8 + 4];
#pragma unroll
        for (int i = 0; i < 4; i++) {
            acc[i][0] += a[i] * b0.x; acc[i][1] += a[i] * b0.y;
            acc[i][2] += a[i] * b0.z; acc[i][3] += a[i] * b0.w;
            acc[i][4] += a[i] * b1.x; acc[i][5] += a[i] * b1.y;
            acc[i][6] += a[i] * b1.z; acc[i][7] += a[i] * b1.w;
        }
    }
    float cp[4];
#pragma unroll
    for (int i = 0; i < 4; i++) {
        cp[i] = 0.f;
#pragma unroll
        for (int j = 0; j < 8; j++) {
            float u = acc[i][j] + bc_s[tx * 8 + j];
            cp[i] += fmaxf(u, 0.f) * cw2_s[tx * 8 + j];
        }
        red_s[(ty * 4 + i) * 17 + tx] = cp[i];
    }
    __syncthreads();
    if (tid < 64) {
        float csum = cb2[0];
#pragma unroll
        for (int t = 0; t < 16; t++) csum += red_s[tid * 17 + t];
        red_add_v2(&g_scat[2 * row_s[tid]], p2a_s[tid] * csum, p2b_s[tid] * csum);
    }
}

// ---------------- v epilogue -------------------------------------------------
// v = t @ v_W2 + v_b2 + scat/denom, then L2-normalize. t = relu(h@vW1+vb1) in g_t.
__global__ void v_final_kernel(const float* __restrict__ vW2, const float* __restrict__ vb2,
                               float* __restrict__ outv) {
    int row = blockIdx.x;
    int k = threadIdx.x;
    float tv = g_t[row * HH + k];
    float p0 = tv * vW2[k * 2 + 0];
    float p1 = tv * vW2[k * 2 + 1];
#pragma unroll
    for (int o = 16; o; o >>= 1) {
        p0 += __shfl_down_sync(0xffffffffu, p0, o);
        p1 += __shfl_down_sync(0xffffffffu, p1, o);
    }
    __shared__ float s0[4], s1[4];
    if ((k & 31) == 0) { s0[k >> 5] = p0; s1[k >> 5] = p1; }
    __syncthreads();
    if (k == 0) {
        float v0 = vb2[0], v1 = vb2[1];
#pragma unroll
        for (int w = 0; w < 4; w++) { v0 += s0[w]; v1 += s1[w]; }
        float d = fmaxf((float)g_cnt[row], 1.f);
        v0 += g_scat[2 * row] / d;
        v1 += g_scat[2 * row + 1] / d;
        float n = fmaxf(sqrtf(v0 * v0 + v1 * v1), 1e-12f);
        outv[2 * row] = v0 / n;
        outv[2 * row + 1] = v1 / n;
    }
}

__global__ void copy_x_kernel(const float* __restrict__ x, float* __restrict__ outx) {
    int i = blockIdx.x * blockDim.x + threadIdx.x;
    if (i < NN * 2) outx[i] = x[i];
}

// ---------------- launcher ---------------------------------------------------
extern "C" void kernel_launch(void* const* d_in, const int* in_sizes, int n_in,
                              void* d_out, int out_size) {
    const float* h0   = (const float*)d_in[0];
    const float* x    = (const float*)d_in[1];
    const int*   ei   = (const int*)d_in[2];
    const float* embW = (const float*)d_in[3];
    const float* embB = (const float*)d_in[4];
    const float* eW1  = (const float*)d_in[5];
    const float* eb1  = (const float*)d_in[6];
    const float* eW2  = (const float*)d_in[7];
    const float* eb2  = (const float*)d_in[8];
    const float* nW1  = (const float*)d_in[9];
    const float* nb1  = (const float*)d_in[10];
    const float* nW2  = (const float*)d_in[11];
    const float* nb2  = (const float*)d_in[12];
    const float* vW1  = (const float*)d_in[13];
    const float* vb1  = (const float*)d_in[14];
    const float* vW2  = (const float*)d_in[15];
    const float* vb2  = (const float*)d_in[16];
    const float* cW1  = (const float*)d_in[17];
    const float* cb1  = (const float*)d_in[18];
    const float* cW2  = (const float*)d_in[19];
    const float* cb2  = (const float*)d_in[20];

    float* out   = (float*)d_out;
    float* out_h = out;
    float* out_x = out + NN * HH;
    float* out_v = out + NN * HH + NN * 2;

    float *p_h, *p_m1, *p_m2, *p_macc, *p_mi, *p_t;
    int* p_cnt;
    cudaGetSymbolAddress((void**)&p_h,    g_h);
    cudaGetSymbolAddress((void**)&p_m1,   g_m1);
    cudaGetSymbolAddress((void**)&p_m2,   g_m2);
    cudaGetSymbolAddress((void**)&p_macc, g_macc);
    cudaGetSymbolAddress((void**)&p_mi,   g_mi);
    cudaGetSymbolAddress((void**)&p_t,    g_t);
    cudaGetSymbolAddress((void**)&p_cnt,  g_cnt);

    cudaFuncSetAttribute(node_gemm, cudaFuncAttributeMaxDynamicSharedMemorySize, NG_SMEM);
    cudaFuncSetAttribute(edge_kernel<false>, cudaFuncAttributeMaxDynamicSharedMemorySize, EK_SMEM);
    cudaFuncSetAttribute(edge_kernel<true>, cudaFuncAttributeMaxDynamicSharedMemorySize, EK_SMEM);

    const int GB = (NN + 63) / 64;

    zero_cnt_kernel<<<(NN + 255) / 256, 256>>>();
    count_kernel<<<(EE + 255) / 256, 256>>>(ei);
    prep_wc_kernel<<<128, 128>>>(eW2, cW1, eb2, cb1);
    embed_kernel<<<NN / 2, 256>>>(h0, embW, embB);

    for (int layer = 0; layer < 2; layer++) {
        zero_accum_kernel<<<2048, 256>>>();
        // m1 = h @ eW1[0:128]   (NO bias here: the edge kernel adds eb1 exactly once)
        node_gemm<<<GB, 256, NG_SMEM>>>(p_h, eW1, nullptr, nullptr, nullptr, nullptr, nullptr,
                                        p_m1, NN, 0);
        // m2 = h @ eW1[128:256]
        node_gemm<<<GB, 256, NG_SMEM>>>(p_h, eW1 + 128 * HH, nullptr, nullptr, nullptr, nullptr,
                                        nullptr, p_m2, NN, 0);
        if (layer == 0)
            edge_kernel<false><<<EE / 64, 256, EK_SMEM>>>(x, ei, eW1, eb1, cW2, cb2);
        else
            edge_kernel<true><<<EE / 64, 256, EK_SMEM>>>(x, ei, eW1, eb1, cW2, cb2);
        // m_i = macc @ eW2 + cnt * eb2
        node_gemm<<<GB, 256, NG_SMEM>>>(p_macc, eW2, nullptr, nullptr, eb2, p_cnt, nullptr,
                                        p_mi, NN, 0);
        // t = relu(h @ nW1[0:128] + m_i @ nW1[128:256] + nb1)
        node_gemm<<<GB, 256, NG_SMEM>>>(p_h, nW1, p_mi, nW1 + 128 * HH, nb1, nullptr, nullptr,
                                        p_t, NN, 1);
        // h = h + t @ nW2 + nb2   (last layer writes directly into d_out's h region)
        float* hdst = (layer == 1) ? out_h : p_h;
        node_gemm<<<GB, 256, NG_SMEM>>>(p_t, nW2, nullptr, nullptr, nb2, nullptr, p_h,
                                        hdst, NN, 0);
    }

    // t = relu(h @ vW1 + vb1)
    node_gemm<<<GB, 256, NG_SMEM>>>(out_h, vW1, nullptr, nullptr, vb1, nullptr, nullptr,
                                    p_t, NN, 1);
    v_final_kernel<<<NN, 128>>>(vW2, vb2, out_v);
    copy_x_kernel<<<(NN * 2 + 255) / 256, 256>>>(x, out_x);
}

// round 6
// speedup vs baseline: 2.4911x; 2.4911x over previous
#include <cuda_runtime.h>
#include <cuda_bf16.h>
#include <cstdint>

#define NN 50000
#define EE 800000
#define HH 128
#define PP 16

// ---------------- scratch (device globals; no allocation allowed) -----------
__device__ float g_h[NN * HH];
__device__ float g_m1[NN * HH];
__device__ float g_m2[NN * HH];
__device__ float g_macc[NN * HH];
__device__ float g_mi[NN * HH];
__device__ float g_t[NN * HH];
__device__ float g_scat[NN * 2];
__device__ int   g_cnt[NN];
__device__ float g_bc[HH];
__device__ __nv_bfloat16 g_Bhi[HH * HH];  // B[n][k] = Wc[k][n], hi part
__device__ __nv_bfloat16 g_Blo[HH * HH];  // lo part

// ---------------- PTX helpers ------------------------------------------------
__device__ __forceinline__ void red_add_v4(float* p, float a, float b, float c, float d) {
    asm volatile("red.global.add.v4.f32 [%0], {%1,%2,%3,%4};"
                 :: "l"(p), "f"(a), "f"(b), "f"(c), "f"(d) : "memory");
}
__device__ __forceinline__ void red_add_v2(float* p, float a, float b) {
    asm volatile("red.global.add.v2.f32 [%0], {%1,%2};"
                 :: "l"(p), "f"(a), "f"(b) : "memory");
}
__device__ __forceinline__ uint32_t smem_u32(const void* p) {
    uint32_t a;
    asm("{ .reg .u64 t; cvta.to.shared.u64 t, %1; cvt.u32.u64 %0, t; }" : "=r"(a) : "l"(p));
    return a;
}
__device__ __forceinline__ void ldmx4(uint32_t* r, uint32_t a) {
    asm volatile("ldmatrix.sync.aligned.m8n8.x4.shared.b16 {%0,%1,%2,%3}, [%4];"
                 : "=r"(r[0]), "=r"(r[1]), "=r"(r[2]), "=r"(r[3]) : "r"(a));
}
__device__ __forceinline__ void ldmx2(uint32_t& r0, uint32_t& r1, uint32_t a) {
    asm volatile("ldmatrix.sync.aligned.m8n8.x2.shared.b16 {%0,%1}, [%2];"
                 : "=r"(r0), "=r"(r1) : "r"(a));
}
__device__ __forceinline__ void mma_bf16(float* c, const uint32_t* a, uint32_t b0, uint32_t b1) {
    asm volatile(
        "mma.sync.aligned.m16n8k16.row.col.f32.bf16.bf16.f32 "
        "{%0,%1,%2,%3}, {%4,%5,%6,%7}, {%8,%9}, {%0,%1,%2,%3};"
        : "+f"(c[0]), "+f"(c[1]), "+f"(c[2]), "+f"(c[3])
        : "r"(a[0]), "r"(a[1]), "r"(a[2]), "r"(a[3]), "r"(b0), "r"(b1));
}

// ---------------- tiny kernels ----------------------------------------------
__global__ void zero_cnt_kernel() {
    int i = blockIdx.x * blockDim.x + threadIdx.x;
    if (i < NN) g_cnt[i] = 0;
}

__global__ void count_kernel(const int* __restrict__ ei) {
    int e = blockIdx.x * blockDim.x + threadIdx.x;
    if (e < EE) atomicAdd(&g_cnt[ei[e]], 1);
}

__global__ void zero_accum_kernel() {
    int i = blockIdx.x * blockDim.x + threadIdx.x;
    int stride = gridDim.x * blockDim.x;
    for (int k = i; k < NN * HH; k += stride) g_macc[k] = 0.f;
    for (int k = i; k < NN * 2; k += stride) g_scat[k] = 0.f;
}

// Wc = e_W2 @ c_W1; store transposed bf16 hi/lo: B[n][k] = Wc[k][n].
// bc = e_b2 @ c_W1 + c_b1
__global__ void prep_wc_kernel(const float* __restrict__ eW2, const float* __restrict__ cW1,
                               const float* __restrict__ eb2, const float* __restrict__ cb1) {
    int i = blockIdx.x, j = threadIdx.x;   // Wc[i][j]
    float s = 0.f;
    for (int k = 0; k < HH; k++) s += eW2[i * HH + k] * cW1[k * HH + j];
    __nv_bfloat16 hi = __float2bfloat16(s);
    __nv_bfloat16 lo = __float2bfloat16(s - __bfloat162float(hi));
    g_Bhi[j * HH + i] = hi;   // B[n=j][k=i]
    g_Blo[j * HH + i] = lo;
    if (i == 0) {
        float t = 0.f;
        for (int k = 0; k < HH; k++) t += eb2[k] * cW1[k * HH + j];
        g_bc[j] = t + cb1[j];
    }
}

// h = h0 @ emb_W + emb_b
__global__ void embed_kernel(const float* __restrict__ h0, const float* __restrict__ W,
                             const float* __restrict__ b) {
    int row = blockIdx.x * 2 + (threadIdx.x >> 7);
    int j = threadIdx.x & 127;
    if (row >= NN) return;
    float s = b[j];
#pragma unroll
    for (int k = 0; k < PP; k++) s += h0[row * PP + k] * W[k * HH + j];
    g_h[row * HH + j] = s;
}

// ---------------- generic node GEMM -----------------------------------------
#define NG_SMEM ((64 * 129 + 128 * 128 + 128) * 4)

__global__ void node_gemm(const float* __restrict__ A1, const float* __restrict__ B1,
                          const float* __restrict__ A2, const float* __restrict__ B2,
                          const float* __restrict__ bias, const int* __restrict__ cnt,
                          const float* __restrict__ resid, float* __restrict__ C,
                          int M, int do_relu) {
    extern __shared__ float sm[];
    float* As = sm;
    float* Bs = sm + 64 * 129;
    float* bs = Bs + 128 * 128;
    const int tid = threadIdx.x;
    const int tx = tid & 15, ty = tid >> 4;
    const int m0 = blockIdx.x * 64;

    if (tid < 128) bs[tid] = bias ? bias[tid] : 0.f;

    float acc[4][8];
#pragma unroll
    for (int i = 0; i < 4; i++)
#pragma unroll
        for (int j = 0; j < 8; j++) acc[i][j] = 0.f;

    const int nsrc = A2 ? 2 : 1;
    for (int s = 0; s < nsrc; s++) {
        const float* A = s ? A2 : A1;
        const float* B = s ? B2 : B1;
        for (int idx = tid; idx < 64 * 32; idx += 256) {
            int r = idx >> 5, c4 = (idx & 31) << 2;
            int gr = m0 + r;
            float4 v = (gr < M) ? *(const float4*)&A[gr * HH + c4] : make_float4(0, 0, 0, 0);
            As[r * 129 + c4 + 0] = v.x; As[r * 129 + c4 + 1] = v.y;
            As[r * 129 + c4 + 2] = v.z; As[r * 129 + c4 + 3] = v.w;
        }
        for (int idx = tid; idx < 128 * 32; idx += 256) {
            int r = idx >> 5, c4 = (idx & 31) << 2;
            *(float4*)&Bs[r * HH + c4] = *(const float4*)&B[r * HH + c4];
        }
        __syncthreads();
#pragma unroll 4
        for (int k = 0; k < 128; k++) {
            float a[4];
#pragma unroll
            for (int i = 0; i < 4; i++) a[i] = As[(ty * 4 + i) * 129 + k];
            float4 b0 = *(float4*)&Bs[k * HH + tx * 8];
            float4 b1 = *(float4*)&Bs[k * HH + tx * 8 + 4];
#pragma unroll
            for (int i = 0; i < 4; i++) {
                acc[i][0] += a[i] * b0.x; acc[i][1] += a[i] * b0.y;
                acc[i][2] += a[i] * b0.z; acc[i][3] += a[i] * b0.w;
                acc[i][4] += a[i] * b1.x; acc[i][5] += a[i] * b1.y;
                acc[i][6] += a[i] * b1.z; acc[i][7] += a[i] * b1.w;
            }
        }
        __syncthreads();
    }
#pragma unroll
    for (int i = 0; i < 4; i++) {
        int m = m0 + ty * 4 + i;
        if (m >= M) continue;
        float bm = cnt ? (float)cnt[m] : 1.f;
        float o[8];
#pragma unroll
        for (int j = 0; j < 8; j++) o[j] = acc[i][j] + bs[tx * 8 + j] * bm;
        if (resid) {
            float4 r0 = *(const float4*)&resid[m * HH + tx * 8];
            float4 r1 = *(const float4*)&resid[m * HH + tx * 8 + 4];
            o[0] += r0.x; o[1] += r0.y; o[2] += r0.z; o[3] += r0.w;
            o[4] += r1.x; o[5] += r1.y; o[6] += r1.z; o[7] += r1.w;
        }
        if (do_relu) {
#pragma unroll
            for (int j = 0; j < 8; j++) o[j] = fmaxf(o[j], 0.f);
        }
        *(float4*)&C[m * HH + tx * 8]     = make_float4(o[0], o[1], o[2], o[3]);
        *(float4*)&C[m * HH + tx * 8 + 4] = make_float4(o[4], o[5], o[6], o[7]);
    }
}

// ---------------- edge kernel, layer 0 (no coord) -----------------------------
__global__ void edge1_kernel(const float* __restrict__ x, const int* __restrict__ ei,
                             const float* __restrict__ eW1, const float* __restrict__ eb1) {
    __shared__ float wd_s[128], b1_s[128], rd_s[128];
    __shared__ int row_s[128], col_s[128];
    const int tid = threadIdx.x;
    if (tid < 128) {
        wd_s[tid] = eW1[256 * HH + tid];
        b1_s[tid] = eb1[tid];
        int eg = blockIdx.x * 128 + tid;
        int r = ei[eg], c = ei[EE + eg];
        row_s[tid] = r; col_s[tid] = c;
        float2 xr = *(const float2*)&x[2 * r];
        float2 xc = *(const float2*)&x[2 * c];
        float dx = xr.x - xc.x, dy = xr.y - xc.y;
        rd_s[tid] = dx * dx + dy * dy;
    }
    __syncthreads();
#pragma unroll
    for (int s = 0; s < 16; s++) {
        int item = tid + s * 256;
        int e = item >> 5, j = (item & 31) << 2;
        int r = row_s[e], c = col_s[e];
        float rd = rd_s[e];
        float4 a  = *(const float4*)&g_m1[r * HH + j];
        float4 b  = *(const float4*)&g_m2[c * HH + j];
        float4 w  = *(const float4*)&wd_s[j];
        float4 bb = *(const float4*)&b1_s[j];
        float v0 = fmaxf(a.x + b.x + rd * w.x + bb.x, 0.f);
        float v1 = fmaxf(a.y + b.y + rd * w.y + bb.y, 0.f);
        float v2 = fmaxf(a.z + b.z + rd * w.z + bb.z, 0.f);
        float v3 = fmaxf(a.w + b.w + rd * w.w + bb.w, 0.f);
        red_add_v4(&g_macc[r * HH + j], v0, v1, v2, v3);
    }
}

// ---------------- edge kernel, layer 1 (fused coord via mma.sync) ------------
// 128 edges / block, 256 threads (8 warps).
// A tiles (r hi/lo bf16) in SMEM, row stride 136 bf16 (272 B) for conflict-free
// ldmatrix. B = Wc^T fragments preloaded to registers (staged via A buffers).
// Warp w owns output columns n in [w*16, w*16+16): 2 n-tiles of 8.
#define EK2_ASTRIDE 272
#define EK2_A_HI 0
#define EK2_A_LO 34816
#define EK2_MISC 69632
#define EK2_SMEM (EK2_MISC + 5120)

__global__ void __launch_bounds__(256)
edge2_kernel(const float* __restrict__ x, const int* __restrict__ ei,
             const float* __restrict__ eW1, const float* __restrict__ eb1,
             const float* __restrict__ cW2, const float* __restrict__ cb2) {
    extern __shared__ char smc[];
    char* A_hi = smc + EK2_A_HI;
    char* A_lo = smc + EK2_A_LO;
    float* misc   = (float*)(smc + EK2_MISC);
    float* wd_s   = misc;          // 128
    float* b1_s   = misc + 128;
    float* bc_s   = misc + 256;
    float* cw2_s  = misc + 384;
    float* p2a_s  = misc + 512;
    float* p2b_s  = misc + 640;
    float* rd_s   = misc + 768;
    float* coordp = misc + 896;    // 128 per-edge coord partials
    int* row_s = (int*)(misc + 1024);
    int* col_s = (int*)(misc + 1152);

    const int tid = threadIdx.x;
    const int wid = tid >> 5, lane = tid & 31;

    // ---- stage B (Wc^T) hi into A_hi, lo into A_lo; misc loads -------------
    if (tid < 128) {
        wd_s[tid]  = eW1[256 * HH + tid];
        b1_s[tid]  = eb1[tid];
        bc_s[tid]  = g_bc[tid];
        cw2_s[tid] = cW2[tid];
        coordp[tid] = 0.f;
        int eg = blockIdx.x * 128 + tid;
        int r = ei[eg], c = ei[EE + eg];
        row_s[tid] = r; col_s[tid] = c;
        float2 xr = *(const float2*)&x[2 * r];
        float2 xc = *(const float2*)&x[2 * c];
        float dx = xr.x - xc.x, dy = xr.y - xc.y;
        rd_s[tid]  = dx * dx + dy * dy;
        p2a_s[tid] = dx * dx - dy * dy;
        p2b_s[tid] = 2.f * dx * dy;
    }
    for (int idx = tid; idx < 8192; idx += 256) {
        int n = idx >> 6, kp = idx & 63;
        uint32_t vh = ((const uint32_t*)g_Bhi)[idx];
        uint32_t vl = ((const uint32_t*)g_Blo)[idx];
        int off = n * EK2_ASTRIDE + kp * 4;
        *(uint32_t*)(A_hi + off) = vh;
        *(uint32_t*)(A_lo + off) = vl;
    }
    __syncthreads();

    // ---- preload B fragments into registers --------------------------------
    uint32_t bh[2][8][2], bl[2][8][2];
    {
        uint32_t hbase = smem_u32(A_hi);
        uint32_t lbase = smem_u32(A_lo);
        int roff = (lane & 7) * EK2_ASTRIDE + ((lane >> 3) & 1) * 16;
#pragma unroll
        for (int nt = 0; nt < 2; nt++)
#pragma unroll
            for (int k = 0; k < 8; k++) {
                uint32_t a = (wid * 16 + nt * 8) * EK2_ASTRIDE + k * 32 + roff;
                ldmx2(bh[nt][k][0], bh[nt][k][1], hbase + a);
                ldmx2(bl[nt][k][0], bl[nt][k][1], lbase + a);
            }
    }
    __syncthreads();

    // ---- phase 1: relu preact, REDG scatter to macc, write A tiles ---------
#pragma unroll
    for (int s = 0; s < 16; s++) {
        int item = tid + s * 256;
        int e = item >> 5, j = (item & 31) << 2;
        int r = row_s[e], c = col_s[e];
        float rd = rd_s[e];
        float4 a  = *(const float4*)&g_m1[r * HH + j];
        float4 b  = *(const float4*)&g_m2[c * HH + j];
        float4 w  = *(const float4*)&wd_s[j];
        float4 bb = *(const float4*)&b1_s[j];
        float v0 = fmaxf(a.x + b.x + rd * w.x + bb.x, 0.f);
        float v1 = fmaxf(a.y + b.y + rd * w.y + bb.y, 0.f);
        float v2 = fmaxf(a.z + b.z + rd * w.z + bb.z, 0.f);
        float v3 = fmaxf(a.w + b.w + rd * w.w + bb.w, 0.f);
        red_add_v4(&g_macc[r * HH + j], v0, v1, v2, v3);
        __nv_bfloat16 h0 = __float2bfloat16(v0), h1 = __float2bfloat16(v1);
        __nv_bfloat16 h2 = __float2bfloat16(v2), h3 = __float2bfloat16(v3);
        __nv_bfloat16 l0 = __float2bfloat16(v0 - __bfloat162float(h0));
        __nv_bfloat16 l1 = __float2bfloat16(v1 - __bfloat162float(h1));
        __nv_bfloat16 l2 = __float2bfloat16(v2 - __bfloat162float(h2));
        __nv_bfloat16 l3 = __float2bfloat16(v3 - __bfloat162float(h3));
        uint2 hv, lv;
        hv.x = ((uint32_t)__bfloat16_as_ushort(h1) << 16) | __bfloat16_as_ushort(h0);
        hv.y = ((uint32_t)__bfloat16_as_ushort(h3) << 16) | __bfloat16_as_ushort(h2);
        lv.x = ((uint32_t)__bfloat16_as_ushort(l1) << 16) | __bfloat16_as_ushort(l0);
        lv.y = ((uint32_t)__bfloat16_as_ushort(l3) << 16) | __bfloat16_as_ushort(l2);
        int off = e * EK2_ASTRIDE + j * 2;
        *(uint2*)(A_hi + off) = hv;
        *(uint2*)(A_lo + off) = lv;
    }
    __syncthreads();

    // ---- phase 2: C = A @ Wc via mma (hi*hi + hi*lo + lo*hi), fused coord --
    {
        uint32_t hbase = smem_u32(A_hi);
        uint32_t lbase = smem_u32(A_lo);
        int aroff = (lane & 15) * EK2_ASTRIDE + ((lane >> 4) & 1) * 16;
#pragma unroll
        for (int m = 0; m < 8; m++) {
            float acc[2][4];
#pragma unroll
            for (int nt = 0; nt < 2; nt++)
#pragma unroll
                for (int q = 0; q < 4; q++) acc[nt][q] = 0.f;
#pragma unroll
            for (int k = 0; k < 8; k++) {
                uint32_t a = (m * 16) * EK2_ASTRIDE + k * 32 + aroff;
                uint32_t ah[4], al[4];
                ldmx4(ah, hbase + a);
                ldmx4(al, lbase + a);
#pragma unroll
                for (int nt = 0; nt < 2; nt++) {
                    mma_bf16(acc[nt], ah, bh[nt][k][0], bh[nt][k][1]);
                    mma_bf16(acc[nt], ah, bl[nt][k][0], bl[nt][k][1]);
                    mma_bf16(acc[nt], al, bh[nt][k][0], bh[nt][k][1]);
                }
            }
            // epilogue for this m-tile: relu(c + bc)*cw2, reduce over n
            int r0 = m * 16 + (lane >> 2);
            float p0 = 0.f, p1 = 0.f;
#pragma unroll
            for (int nt = 0; nt < 2; nt++) {
                int n = wid * 16 + nt * 8 + (lane & 3) * 2;
                p0 += fmaxf(acc[nt][0] + bc_s[n], 0.f) * cw2_s[n]
                    + fmaxf(acc[nt][1] + bc_s[n + 1], 0.f) * cw2_s[n + 1];
                p1 += fmaxf(acc[nt][2] + bc_s[n], 0.f) * cw2_s[n]
                    + fmaxf(acc[nt][3] + bc_s[n + 1], 0.f) * cw2_s[n + 1];
            }
            p0 += __shfl_xor_sync(0xffffffffu, p0, 1);
            p0 += __shfl_xor_sync(0xffffffffu, p0, 2);
            p1 += __shfl_xor_sync(0xffffffffu, p1, 1);
            p1 += __shfl_xor_sync(0xffffffffu, p1, 2);
            if ((lane & 3) == 0) {
                atomicAdd(&coordp[r0], p0);
                atomicAdd(&coordp[r0 + 8], p1);
            }
        }
    }
    __syncthreads();
    if (tid < 128) {
        float csum = coordp[tid] + cb2[0];
        red_add_v2(&g_scat[2 * row_s[tid]], p2a_s[tid] * csum, p2b_s[tid] * csum);
    }
}

// ---------------- v epilogue -------------------------------------------------
__global__ void v_final_kernel(const float* __restrict__ vW2, const float* __restrict__ vb2,
                               float* __restrict__ outv) {
    int row = blockIdx.x;
    int k = threadIdx.x;
    float tv = g_t[row * HH + k];
    float p0 = tv * vW2[k * 2 + 0];
    float p1 = tv * vW2[k * 2 + 1];
#pragma unroll
    for (int o = 16; o; o >>= 1) {
        p0 += __shfl_down_sync(0xffffffffu, p0, o);
        p1 += __shfl_down_sync(0xffffffffu, p1, o);
    }
    __shared__ float s0[4], s1[4];
    if ((k & 31) == 0) { s0[k >> 5] = p0; s1[k >> 5] = p1; }
    __syncthreads();
    if (k == 0) {
        float v0 = vb2[0], v1 = vb2[1];
#pragma unroll
        for (int w = 0; w < 4; w++) { v0 += s0[w]; v1 += s1[w]; }
        float d = fmaxf((float)g_cnt[row], 1.f);
        v0 += g_scat[2 * row] / d;
        v1 += g_scat[2 * row + 1] / d;
        float n = fmaxf(sqrtf(v0 * v0 + v1 * v1), 1e-12f);
        outv[2 * row] = v0 / n;
        outv[2 * row + 1] = v1 / n;
    }
}

__global__ void copy_x_kernel(const float* __restrict__ x, float* __restrict__ outx) {
    int i = blockIdx.x * blockDim.x + threadIdx.x;
    if (i < NN * 2) outx[i] = x[i];
}

// ---------------- launcher ---------------------------------------------------
extern "C" void kernel_launch(void* const* d_in, const int* in_sizes, int n_in,
                              void* d_out, int out_size) {
    const float* h0   = (const float*)d_in[0];
    const float* x    = (const float*)d_in[1];
    const int*   ei   = (const int*)d_in[2];
    const float* embW = (const float*)d_in[3];
    const float* embB = (const float*)d_in[4];
    const float* eW1  = (const float*)d_in[5];
    const float* eb1  = (const float*)d_in[6];
    const float* eW2  = (const float*)d_in[7];
    const float* eb2  = (const float*)d_in[8];
    const float* nW1  = (const float*)d_in[9];
    const float* nb1  = (const float*)d_in[10];
    const float* nW2  = (const float*)d_in[11];
    const float* nb2  = (const float*)d_in[12];
    const float* vW1  = (const float*)d_in[13];
    const float* vb1  = (const float*)d_in[14];
    const float* vW2  = (const float*)d_in[15];
    const float* vb2  = (const float*)d_in[16];
    const float* cW1  = (const float*)d_in[17];
    const float* cb1  = (const float*)d_in[18];
    const float* cW2  = (const float*)d_in[19];
    const float* cb2  = (const float*)d_in[20];

    float* out   = (float*)d_out;
    float* out_h = out;
    float* out_x = out + NN * HH;
    float* out_v = out + NN * HH + NN * 2;

    float *p_h, *p_macc, *p_mi, *p_t, *p_m1, *p_m2;
    int* p_cnt;
    cudaGetSymbolAddress((void**)&p_h,    g_h);
    cudaGetSymbolAddress((void**)&p_macc, g_macc);
    cudaGetSymbolAddress((void**)&p_mi,   g_mi);
    cudaGetSymbolAddress((void**)&p_t,    g_t);
    cudaGetSymbolAddress((void**)&p_cnt,  g_cnt);
    cudaGetSymbolAddress((void**)&p_m1,   g_m1);
    cudaGetSymbolAddress((void**)&p_m2,   g_m2);

    cudaFuncSetAttribute(node_gemm, cudaFuncAttributeMaxDynamicSharedMemorySize, NG_SMEM);
    cudaFuncSetAttribute(edge2_kernel, cudaFuncAttributeMaxDynamicSharedMemorySize, EK2_SMEM);

    const int GB = (NN + 63) / 64;

    zero_cnt_kernel<<<(NN + 255) / 256, 256>>>();
    count_kernel<<<(EE + 255) / 256, 256>>>(ei);
    prep_wc_kernel<<<128, 128>>>(eW2, cW1, eb2, cb1);
    embed_kernel<<<NN / 2, 256>>>(h0, embW, embB);

    for (int layer = 0; layer < 2; layer++) {
        zero_accum_kernel<<<2048, 256>>>();
        // m1 = h @ eW1[0:128]  (edge kernels add eb1 exactly once)
        node_gemm<<<GB, 256, NG_SMEM>>>(p_h, eW1, nullptr, nullptr, nullptr, nullptr, nullptr,
                                        p_m1, NN, 0);
        // m2 = h @ eW1[128:256]
        node_gemm<<<GB, 256, NG_SMEM>>>(p_h, eW1 + 128 * HH, nullptr, nullptr, nullptr, nullptr,
                                        nullptr, p_m2, NN, 0);
        if (layer == 0)
            edge1_kernel<<<EE / 128, 256>>>(x, ei, eW1, eb1);
        else
            edge2_kernel<<<EE / 128, 256, EK2_SMEM>>>(x, ei, eW1, eb1, cW2, cb2);
        // m_i = macc @ eW2 + cnt * eb2
        node_gemm<<<GB, 256, NG_SMEM>>>(p_macc, eW2, nullptr, nullptr, eb2, p_cnt, nullptr,
                                        p_mi, NN, 0);
        // t = relu(h @ nW1[0:128] + m_i @ nW1[128:256] + nb1)
        node_gemm<<<GB, 256, NG_SMEM>>>(p_h, nW1, p_mi, nW1 + 128 * HH, nb1, nullptr, nullptr,
                                        p_t, NN, 1);
        // h = h + t @ nW2 + nb2
        float* hdst = (layer == 1) ? out_h : p_h;
        node_gemm<<<GB, 256, NG_SMEM>>>(p_t, nW2, nullptr, nullptr, nb2, nullptr, p_h,
                                        hdst, NN, 0);
    }

    // t = relu(h @ vW1 + vb1)
    node_gemm<<<GB, 256, NG_SMEM>>>(out_h, vW1, nullptr, nullptr, vb1, nullptr, nullptr,
                                    p_t, NN, 1);
    v_final_kernel<<<NN, 128>>>(vW2, vb2, out_v);
    copy_x_kernel<<<(NN * 2 + 255) / 256, 256>>>(x, out_x);
}

// round 7
// speedup vs baseline: 2.7334x; 1.0973x over previous
#include <cuda_runtime.h>
#include <cuda_bf16.h>
#include <cstdint>

#define NN 50000
#define EE 800000
#define HH 128
#define PP 16
#define SCAN_B 196   // ceil(NN/256)

// ---------------- scratch (device globals; no allocation allowed) -----------
__device__ float g_h[NN * HH];
__device__ float g_m1[NN * HH];
__device__ float g_m2[NN * HH];
__device__ float g_macc[NN * HH];
__device__ float g_t[NN * HH];
__device__ float g_scat[NN * 2];
__device__ int   g_cnt[NN];
__device__ int   g_off[NN + 1];
__device__ int   g_cur[NN];
__device__ int   g_bsum[SCAN_B];
__device__ int   g_rows[EE];
__device__ int   g_cols[EE];
__device__ float g_bc[HH];
__device__ float g_Wme[HH * HH];
__device__ float g_bme[HH];
__device__ __nv_bfloat16 g_Bhi[HH * HH];  // B[n][k] = Wc[k][n], hi part
__device__ __nv_bfloat16 g_Blo[HH * HH];  // lo part

// ---------------- PTX helpers ------------------------------------------------
__device__ __forceinline__ void red_add_v2(float* p, float a, float b) {
    asm volatile("red.global.add.v2.f32 [%0], {%1,%2};"
                 :: "l"(p), "f"(a), "f"(b) : "memory");
}
__device__ __forceinline__ uint32_t smem_u32(const void* p) {
    uint32_t a;
    asm("{ .reg .u64 t; cvta.to.shared.u64 t, %1; cvt.u32.u64 %0, t; }" : "=r"(a) : "l"(p));
    return a;
}
__device__ __forceinline__ void ldmx4(uint32_t* r, uint32_t a) {
    asm volatile("ldmatrix.sync.aligned.m8n8.x4.shared.b16 {%0,%1,%2,%3}, [%4];"
                 : "=r"(r[0]), "=r"(r[1]), "=r"(r[2]), "=r"(r[3]) : "r"(a));
}
__device__ __forceinline__ void ldmx2(uint32_t& r0, uint32_t& r1, uint32_t a) {
    asm volatile("ldmatrix.sync.aligned.m8n8.x2.shared.b16 {%0,%1}, [%2];"
                 : "=r"(r0), "=r"(r1) : "r"(a));
}
__device__ __forceinline__ void mma_bf16(float* c, const uint32_t* a, uint32_t b0, uint32_t b1) {
    asm volatile(
        "mma.sync.aligned.m16n8k16.row.col.f32.bf16.bf16.f32 "
        "{%0,%1,%2,%3}, {%4,%5,%6,%7}, {%8,%9}, {%0,%1,%2,%3};"
        : "+f"(c[0]), "+f"(c[1]), "+f"(c[2]), "+f"(c[3])
        : "r"(a[0]), "r"(a[1]), "r"(a[2]), "r"(a[3]), "r"(b0), "r"(b1));
}

// ---------------- sort pipeline ----------------------------------------------
__global__ void zero_cnt_scat_kernel() {
    int i = blockIdx.x * blockDim.x + threadIdx.x;
    if (i < NN) g_cnt[i] = 0;
    if (i < NN * 2) g_scat[i] = 0.f;
}

__global__ void count_kernel(const int* __restrict__ ei) {
    int e = blockIdx.x * blockDim.x + threadIdx.x;
    if (e < EE) atomicAdd(&g_cnt[ei[e]], 1);
}

__global__ void scan1_kernel() {   // per-block sums of cnt
    __shared__ int sm[256];
    int b = blockIdx.x, t = threadIdx.x, i = b * 256 + t;
    int v = (i < NN) ? g_cnt[i] : 0;
    sm[t] = v; __syncthreads();
    for (int o = 128; o; o >>= 1) {
        if (t < o) sm[t] += sm[t + o];
        __syncthreads();
    }
    if (t == 0) g_bsum[b] = sm[0];
}

__global__ void scan2_kernel() {   // exclusive scan of block sums (1 thread)
    if (threadIdx.x == 0 && blockIdx.x == 0) {
        int s = 0;
        for (int b = 0; b < SCAN_B; b++) { int t = g_bsum[b]; g_bsum[b] = s; s += t; }
        g_off[NN] = EE;
    }
}

__global__ void scan3_kernel() {   // intra-block exclusive scan + base
    __shared__ int sm[256];
    int b = blockIdx.x, t = threadIdx.x, i = b * 256 + t;
    int v = (i < NN) ? g_cnt[i] : 0;
    sm[t] = v; __syncthreads();
    for (int o = 1; o < 256; o <<= 1) {
        int add = (t >= o) ? sm[t - o] : 0;
        __syncthreads();
        sm[t] += add;
        __syncthreads();
    }
    if (i < NN) {
        int off = g_bsum[b] + sm[t] - v;
        g_off[i] = off;
        g_cur[i] = off;
    }
}

__global__ void scatter_kernel(const int* __restrict__ ei) {
    int e = blockIdx.x * blockDim.x + threadIdx.x;
    if (e < EE) {
        int r = ei[e];
        int pos = atomicAdd(&g_cur[r], 1);
        g_rows[pos] = r;
        g_cols[pos] = ei[EE + e];
    }
}

// ---------------- prep kernels ------------------------------------------------
// Wc = e_W2 @ c_W1 stored transposed bf16 hi/lo; bc = e_b2 @ c_W1 + c_b1
__global__ void prep_wc_kernel(const float* __restrict__ eW2, const float* __restrict__ cW1,
                               const float* __restrict__ eb2, const float* __restrict__ cb1) {
    int i = blockIdx.x, j = threadIdx.x;
    float s = 0.f;
    for (int k = 0; k < HH; k++) s += eW2[i * HH + k] * cW1[k * HH + j];
    __nv_bfloat16 hi = __float2bfloat16(s);
    __nv_bfloat16 lo = __float2bfloat16(s - __bfloat162float(hi));
    g_Bhi[j * HH + i] = hi;
    g_Blo[j * HH + i] = lo;
    if (i == 0) {
        float t = 0.f;
        for (int k = 0; k < HH; k++) t += eb2[k] * cW1[k * HH + j];
        g_bc[j] = t + cb1[j];
    }
}

// W_me = e_W2 @ nW1[128:256]; b_me = e_b2 @ nW1[128:256]
__global__ void prep_wme_kernel(const float* __restrict__ eW2, const float* __restrict__ nW1b,
                                const float* __restrict__ eb2) {
    int i = blockIdx.x, j = threadIdx.x;
    float s = 0.f;
    for (int k = 0; k < HH; k++) s += eW2[i * HH + k] * nW1b[k * HH + j];
    g_Wme[i * HH + j] = s;
    if (i == 0) {
        float t = 0.f;
        for (int k = 0; k < HH; k++) t += eb2[k] * nW1b[k * HH + j];
        g_bme[j] = t;
    }
}

// h = h0 @ emb_W + emb_b
__global__ void embed_kernel(const float* __restrict__ h0, const float* __restrict__ W,
                             const float* __restrict__ b) {
    int row = blockIdx.x * 2 + (threadIdx.x >> 7);
    int j = threadIdx.x & 127;
    if (row >= NN) return;
    float s = b[j];
#pragma unroll
    for (int k = 0; k < PP; k++) s += h0[row * PP + k] * W[k * HH + j];
    g_h[row * HH + j] = s;
}

// ---------------- generic node GEMM -----------------------------------------
// C = act( A1@B1 (+A2@B2) + bias + cnt*bias2 (+resid) )
#define NG_SMEM ((64 * 129 + 128 * 128 + 256) * 4)

__global__ void node_gemm(const float* __restrict__ A1, const float* __restrict__ B1,
                          const float* __restrict__ A2, const float* __restrict__ B2,
                          const float* __restrict__ bias, const float* __restrict__ bias2,
                          const int* __restrict__ cnt,
                          const float* __restrict__ resid, float* __restrict__ C,
                          int M, int do_relu) {
    extern __shared__ float sm[];
    float* As = sm;
    float* Bs = sm + 64 * 129;
    float* bs = Bs + 128 * 128;
    float* bs2 = bs + 128;
    const int tid = threadIdx.x;
    const int tx = tid & 15, ty = tid >> 4;
    const int m0 = blockIdx.x * 64;

    if (tid < 128) {
        bs[tid]  = bias ? bias[tid] : 0.f;
        bs2[tid] = bias2 ? bias2[tid] : 0.f;
    }

    float acc[4][8];
#pragma unroll
    for (int i = 0; i < 4; i++)
#pragma unroll
        for (int j = 0; j < 8; j++) acc[i][j] = 0.f;

    const int nsrc = A2 ? 2 : 1;
    for (int s = 0; s < nsrc; s++) {
        const float* A = s ? A2 : A1;
        const float* B = s ? B2 : B1;
        for (int idx = tid; idx < 64 * 32; idx += 256) {
            int r = idx >> 5, c4 = (idx & 31) << 2;
            int gr = m0 + r;
            float4 v = (gr < M) ? *(const float4*)&A[gr * HH + c4] : make_float4(0, 0, 0, 0);
            As[r * 129 + c4 + 0] = v.x; As[r * 129 + c4 + 1] = v.y;
            As[r * 129 + c4 + 2] = v.z; As[r * 129 + c4 + 3] = v.w;
        }
        for (int idx = tid; idx < 128 * 32; idx += 256) {
            int r = idx >> 5, c4 = (idx & 31) << 2;
            *(float4*)&Bs[r * HH + c4] = *(const float4*)&B[r * HH + c4];
        }
        __syncthreads();
#pragma unroll 4
        for (int k = 0; k < 128; k++) {
            float a[4];
#pragma unroll
            for (int i = 0; i < 4; i++) a[i] = As[(ty * 4 + i) * 129 + k];
            float4 b0 = *(float4*)&Bs[k * HH + tx * 8];
            float4 b1 = *(float4*)&Bs[k * HH + tx * 8 + 4];
#pragma unroll
            for (int i = 0; i < 4; i++) {
                acc[i][0] += a[i] * b0.x; acc[i][1] += a[i] * b0.y;
                acc[i][2] += a[i] * b0.z; acc[i][3] += a[i] * b0.w;
                acc[i][4] += a[i] * b1.x; acc[i][5] += a[i] * b1.y;
                acc[i][6] += a[i] * b1.z; acc[i][7] += a[i] * b1.w;
            }
        }
        __syncthreads();
    }
#pragma unroll
    for (int i = 0; i < 4; i++) {
        int m = m0 + ty * 4 + i;
        if (m >= M) continue;
        float cm = cnt ? (float)cnt[m] : 0.f;
        float o[8];
#pragma unroll
        for (int j = 0; j < 8; j++) o[j] = acc[i][j] + bs[tx * 8 + j] + cm * bs2[tx * 8 + j];
        if (resid) {
            float4 r0 = *(const float4*)&resid[m * HH + tx * 8];
            float4 r1 = *(const float4*)&resid[m * HH + tx * 8 + 4];
            o[0] += r0.x; o[1] += r0.y; o[2] += r0.z; o[3] += r0.w;
            o[4] += r1.x; o[5] += r1.y; o[6] += r1.z; o[7] += r1.w;
        }
        if (do_relu) {
#pragma unroll
            for (int j = 0; j < 8; j++) o[j] = fmaxf(o[j], 0.f);
        }
        *(float4*)&C[m * HH + tx * 8]     = make_float4(o[0], o[1], o[2], o[3]);
        *(float4*)&C[m * HH + tx * 8 + 4] = make_float4(o[4], o[5], o[6], o[7]);
    }
}

// ---------------- dual-output GEMM: m1 = h@B1, m2 = h@B2 ---------------------
__global__ void node_gemm_m12(const float* __restrict__ A, const float* __restrict__ eW1) {
    extern __shared__ float sm[];
    float* As = sm;
    float* Bs = sm + 64 * 129;
    const int tid = threadIdx.x;
    const int tx = tid & 15, ty = tid >> 4;
    const int m0 = blockIdx.x * 64;

    for (int idx = tid; idx < 64 * 32; idx += 256) {
        int r = idx >> 5, c4 = (idx & 31) << 2;
        int gr = m0 + r;
        float4 v = (gr < NN) ? *(const float4*)&A[gr * HH + c4] : make_float4(0, 0, 0, 0);
        As[r * 129 + c4 + 0] = v.x; As[r * 129 + c4 + 1] = v.y;
        As[r * 129 + c4 + 2] = v.z; As[r * 129 + c4 + 3] = v.w;
    }

    for (int s = 0; s < 2; s++) {
        const float* B = eW1 + s * 128 * HH;
        float* C = s ? g_m2 : g_m1;
        for (int idx = tid; idx < 128 * 32; idx += 256) {
            int r = idx >> 5, c4 = (idx & 31) << 2;
            *(float4*)&Bs[r * HH + c4] = *(const float4*)&B[r * HH + c4];
        }
        __syncthreads();
        float acc[4][8];
#pragma unroll
        for (int i = 0; i < 4; i++)
#pragma unroll
            for (int j = 0; j < 8; j++) acc[i][j] = 0.f;
#pragma unroll 4
        for (int k = 0; k < 128; k++) {
            float a[4];
#pragma unroll
            for (int i = 0; i < 4; i++) a[i] = As[(ty * 4 + i) * 129 + k];
            float4 b0 = *(float4*)&Bs[k * HH + tx * 8];
            float4 b1 = *(float4*)&Bs[k * HH + tx * 8 + 4];
#pragma unroll
            for (int i = 0; i < 4; i++) {
                acc[i][0] += a[i] * b0.x; acc[i][1] += a[i] * b0.y;
                acc[i][2] += a[i] * b0.z; acc[i][3] += a[i] * b0.w;
                acc[i][4] += a[i] * b1.x; acc[i][5] += a[i] * b1.y;
                acc[i][6] += a[i] * b1.z; acc[i][7] += a[i] * b1.w;
            }
        }
#pragma unroll
        for (int i = 0; i < 4; i++) {
            int m = m0 + ty * 4 + i;
            if (m >= NN) continue;
            *(float4*)&C[m * HH + tx * 8] =
                make_float4(acc[i][0], acc[i][1], acc[i][2], acc[i][3]);
            *(float4*)&C[m * HH + tx * 8 + 4] =
                make_float4(acc[i][4], acc[i][5], acc[i][6], acc[i][7]);
        }
        __syncthreads();
    }
}

// ---------------- macc gather: one warp per node (no atomics) ----------------
__global__ void macc_gather_kernel(const float* __restrict__ x,
                                   const float* __restrict__ eW1,
                                   const float* __restrict__ eb1) {
    int warp = (blockIdx.x * blockDim.x + threadIdx.x) >> 5;
    int lane = threadIdx.x & 31;
    if (warp >= NN) return;
    int r = warp;
    int j = lane << 2;
    float4 m1v = *(const float4*)&g_m1[r * HH + j];
    float4 wd  = *(const float4*)&eW1[256 * HH + j];
    float4 b1  = *(const float4*)&eb1[j];
    float2 xr  = *(const float2*)&x[2 * r];
    float4 acc = make_float4(0.f, 0.f, 0.f, 0.f);
    int s = g_off[r], e = g_off[r + 1];
    for (int idx = s; idx < e; idx++) {
        int c = __ldg(&g_cols[idx]);
        float2 xc = *(const float2*)&x[2 * c];
        float dx = xr.x - xc.x, dy = xr.y - xc.y;
        float rd = dx * dx + dy * dy;
        float4 m2v = *(const float4*)&g_m2[c * HH + j];
        acc.x += fmaxf(m1v.x + m2v.x + rd * wd.x + b1.x, 0.f);
        acc.y += fmaxf(m1v.y + m2v.y + rd * wd.y + b1.y, 0.f);
        acc.z += fmaxf(m1v.z + m2v.z + rd * wd.z + b1.z, 0.f);
        acc.w += fmaxf(m1v.w + m2v.w + rd * wd.w + b1.w, 0.f);
    }
    *(float4*)&g_macc[r * HH + j] = acc;
}

// ---------------- coord kernel (layer 2 only, mma.sync) ----------------------
#define EK2_ASTRIDE 272
#define EK2_A_HI 0
#define EK2_A_LO 34816
#define EK2_MISC 69632
#define EK2_SMEM (EK2_MISC + 5120)

__global__ void __launch_bounds__(256)
edge2_kernel(const float* __restrict__ x,
             const float* __restrict__ eW1, const float* __restrict__ eb1,
             const float* __restrict__ cW2, const float* __restrict__ cb2) {
    extern __shared__ char smc[];
    char* A_hi = smc + EK2_A_HI;
    char* A_lo = smc + EK2_A_LO;
    float* misc   = (float*)(smc + EK2_MISC);
    float* wd_s   = misc;
    float* b1_s   = misc + 128;
    float* bc_s   = misc + 256;
    float* cw2_s  = misc + 384;
    float* p2a_s  = misc + 512;
    float* p2b_s  = misc + 640;
    float* rd_s   = misc + 768;
    float* coordp = misc + 896;
    int* row_s = (int*)(misc + 1024);
    int* col_s = (int*)(misc + 1152);

    const int tid = threadIdx.x;
    const int wid = tid >> 5, lane = tid & 31;

    if (tid < 128) {
        wd_s[tid]  = eW1[256 * HH + tid];
        b1_s[tid]  = eb1[tid];
        bc_s[tid]  = g_bc[tid];
        cw2_s[tid] = cW2[tid];
        coordp[tid] = 0.f;
        int eg = blockIdx.x * 128 + tid;
        int r = g_rows[eg], c = g_cols[eg];
        row_s[tid] = r; col_s[tid] = c;
        float2 xr = *(const float2*)&x[2 * r];
        float2 xc = *(const float2*)&x[2 * c];
        float dx = xr.x - xc.x, dy = xr.y - xc.y;
        rd_s[tid]  = dx * dx + dy * dy;
        p2a_s[tid] = dx * dx - dy * dy;
        p2b_s[tid] = 2.f * dx * dy;
    }
    for (int idx = tid; idx < 8192; idx += 256) {
        int n = idx >> 6, kp = idx & 63;
        uint32_t vh = ((const uint32_t*)g_Bhi)[idx];
        uint32_t vl = ((const uint32_t*)g_Blo)[idx];
        int off = n * EK2_ASTRIDE + kp * 4;
        *(uint32_t*)(A_hi + off) = vh;
        *(uint32_t*)(A_lo + off) = vl;
    }
    __syncthreads();

    // preload B fragments (Wc^T) into registers
    uint32_t bh[2][8][2], bl[2][8][2];
    {
        uint32_t hbase = smem_u32(A_hi);
        uint32_t lbase = smem_u32(A_lo);
        int roff = (lane & 7) * EK2_ASTRIDE + ((lane >> 3) & 1) * 16;
#pragma unroll
        for (int nt = 0; nt < 2; nt++)
#pragma unroll
            for (int k = 0; k < 8; k++) {
                uint32_t a = (wid * 16 + nt * 8) * EK2_ASTRIDE + k * 32 + roff;
                ldmx2(bh[nt][k][0], bh[nt][k][1], hbase + a);
                ldmx2(bl[nt][k][0], bl[nt][k][1], lbase + a);
            }
    }
    __syncthreads();

    // phase 1: preact (no macc scatter — handled by gather kernel), write A
#pragma unroll
    for (int s = 0; s < 16; s++) {
        int item = tid + s * 256;
        int e = item >> 5, j = (item & 31) << 2;
        int r = row_s[e], c = col_s[e];
        float rd = rd_s[e];
        float4 a  = *(const float4*)&g_m1[r * HH + j];
        float4 b  = *(const float4*)&g_m2[c * HH + j];
        float4 w  = *(const float4*)&wd_s[j];
        float4 bb = *(const float4*)&b1_s[j];
        float v0 = fmaxf(a.x + b.x + rd * w.x + bb.x, 0.f);
        float v1 = fmaxf(a.y + b.y + rd * w.y + bb.y, 0.f);
        float v2 = fmaxf(a.z + b.z + rd * w.z + bb.z, 0.f);
        float v3 = fmaxf(a.w + b.w + rd * w.w + bb.w, 0.f);
        __nv_bfloat16 h0 = __float2bfloat16(v0), h1 = __float2bfloat16(v1);
        __nv_bfloat16 h2 = __float2bfloat16(v2), h3 = __float2bfloat16(v3);
        __nv_bfloat16 l0 = __float2bfloat16(v0 - __bfloat162float(h0));
        __nv_bfloat16 l1 = __float2bfloat16(v1 - __bfloat162float(h1));
        __nv_bfloat16 l2 = __float2bfloat16(v2 - __bfloat162float(h2));
        __nv_bfloat16 l3 = __float2bfloat16(v3 - __bfloat162float(h3));
        uint2 hv, lv;
        hv.x = ((uint32_t)__bfloat16_as_ushort(h1) << 16) | __bfloat16_as_ushort(h0);
        hv.y = ((uint32_t)__bfloat16_as_ushort(h3) << 16) | __bfloat16_as_ushort(h2);
        lv.x = ((uint32_t)__bfloat16_as_ushort(l1) << 16) | __bfloat16_as_ushort(l0);
        lv.y = ((uint32_t)__bfloat16_as_ushort(l3) << 16) | __bfloat16_as_ushort(l2);
        int off = e * EK2_ASTRIDE + j * 2;
        *(uint2*)(A_hi + off) = hv;
        *(uint2*)(A_lo + off) = lv;
    }
    __syncthreads();

    // phase 2: C = A @ Wc via mma (hi*hi + hi*lo + lo*hi), fused coord
    {
        uint32_t hbase = smem_u32(A_hi);
        uint32_t lbase = smem_u32(A_lo);
        int aroff = (lane & 15) * EK2_ASTRIDE + ((lane >> 4) & 1) * 16;
#pragma unroll
        for (int m = 0; m < 8; m++) {
            float acc[2][4];
#pragma unroll
            for (int nt = 0; nt < 2; nt++)
#pragma unroll
                for (int q = 0; q < 4; q++) acc[nt][q] = 0.f;
#pragma unroll
            for (int k = 0; k < 8; k++) {
                uint32_t a = (m * 16) * EK2_ASTRIDE + k * 32 + aroff;
                uint32_t ah[4], al[4];
                ldmx4(ah, hbase + a);
                ldmx4(al, lbase + a);
#pragma unroll
                for (int nt = 0; nt < 2; nt++) {
                    mma_bf16(acc[nt], ah, bh[nt][k][0], bh[nt][k][1]);
                    mma_bf16(acc[nt], ah, bl[nt][k][0], bl[nt][k][1]);
                    mma_bf16(acc[nt], al, bh[nt][k][0], bh[nt][k][1]);
                }
            }
            int r0 = m * 16 + (lane >> 2);
            float p0 = 0.f, p1 = 0.f;
#pragma unroll
            for (int nt = 0; nt < 2; nt++) {
                int n = wid * 16 + nt * 8 + (lane & 3) * 2;
                p0 += fmaxf(acc[nt][0] + bc_s[n], 0.f) * cw2_s[n]
                    + fmaxf(acc[nt][1] + bc_s[n + 1], 0.f) * cw2_s[n + 1];
                p1 += fmaxf(acc[nt][2] + bc_s[n], 0.f) * cw2_s[n]
                    + fmaxf(acc[nt][3] + bc_s[n + 1], 0.f) * cw2_s[n + 1];
            }
            p0 += __shfl_xor_sync(0xffffffffu, p0, 1);
            p0 += __shfl_xor_sync(0xffffffffu, p0, 2);
            p1 += __shfl_xor_sync(0xffffffffu, p1, 1);
            p1 += __shfl_xor_sync(0xffffffffu, p1, 2);
            if ((lane & 3) == 0) {
                atomicAdd(&coordp[r0], p0);
                atomicAdd(&coordp[r0 + 8], p1);
            }
        }
    }
    __syncthreads();
    if (tid < 128) {
        float csum = coordp[tid] + cb2[0];
        red_add_v2(&g_scat[2 * row_s[tid]], p2a_s[tid] * csum, p2b_s[tid] * csum);
    }
}

// ---------------- v epilogue -------------------------------------------------
__global__ void v_final_kernel(const float* __restrict__ vW2, const float* __restrict__ vb2,
                               float* __restrict__ outv) {
    int row = blockIdx.x;
    int k = threadIdx.x;
    float tv = g_t[row * HH + k];
    float p0 = tv * vW2[k * 2 + 0];
    float p1 = tv * vW2[k * 2 + 1];
#pragma unroll
    for (int o = 16; o; o >>= 1) {
        p0 += __shfl_down_sync(0xffffffffu, p0, o);
        p1 += __shfl_down_sync(0xffffffffu, p1, o);
    }
    __shared__ float s0[4], s1[4];
    if ((k & 31) == 0) { s0[k >> 5] = p0; s1[k >> 5] = p1; }
    __syncthreads();
    if (k == 0) {
        float v0 = vb2[0], v1 = vb2[1];
#pragma unroll
        for (int w = 0; w < 4; w++) { v0 += s0[w]; v1 += s1[w]; }
        float d = fmaxf((float)g_cnt[row], 1.f);
        v0 += g_scat[2 * row] / d;
        v1 += g_scat[2 * row + 1] / d;
        float n = fmaxf(sqrtf(v0 * v0 + v1 * v1), 1e-12f);
        outv[2 * row] = v0 / n;
        outv[2 * row + 1] = v1 / n;
    }
}

__global__ void copy_x_kernel(const float* __restrict__ x, float* __restrict__ outx) {
    int i = blockIdx.x * blockDim.x + threadIdx.x;
    if (i < NN * 2) outx[i] = x[i];
}

// ---------------- launcher ---------------------------------------------------
extern "C" void kernel_launch(void* const* d_in, const int* in_sizes, int n_in,
                              void* d_out, int out_size) {
    const float* h0   = (const float*)d_in[0];
    const float* x    = (const float*)d_in[1];
    const int*   ei   = (const int*)d_in[2];
    const float* embW = (const float*)d_in[3];
    const float* embB = (const float*)d_in[4];
    const float* eW1  = (const float*)d_in[5];
    const float* eb1  = (const float*)d_in[6];
    const float* eW2  = (const float*)d_in[7];
    const float* eb2  = (const float*)d_in[8];
    const float* nW1  = (const float*)d_in[9];
    const float* nb1  = (const float*)d_in[10];
    const float* nW2  = (const float*)d_in[11];
    const float* nb2  = (const float*)d_in[12];
    const float* vW1  = (const float*)d_in[13];
    const float* vb1  = (const float*)d_in[14];
    const float* vW2  = (const float*)d_in[15];
    const float* vb2  = (const float*)d_in[16];
    const float* cW1  = (const float*)d_in[17];
    const float* cb1  = (const float*)d_in[18];
    const float* cW2  = (const float*)d_in[19];
    const float* cb2  = (const float*)d_in[20];

    float* out   = (float*)d_out;
    float* out_h = out;
    float* out_x = out + NN * HH;
    float* out_v = out + NN * HH + NN * 2;

    float *p_h, *p_macc, *p_t, *p_wme, *p_bme;
    int* p_cnt;
    cudaGetSymbolAddress((void**)&p_h,    g_h);
    cudaGetSymbolAddress((void**)&p_macc, g_macc);
    cudaGetSymbolAddress((void**)&p_t,    g_t);
    cudaGetSymbolAddress((void**)&p_cnt,  g_cnt);
    cudaGetSymbolAddress((void**)&p_wme,  g_Wme);
    cudaGetSymbolAddress((void**)&p_bme,  g_bme);

    cudaFuncSetAttribute(node_gemm, cudaFuncAttributeMaxDynamicSharedMemorySize, NG_SMEM);
    cudaFuncSetAttribute(node_gemm_m12, cudaFuncAttributeMaxDynamicSharedMemorySize, NG_SMEM);
    cudaFuncSetAttribute(edge2_kernel, cudaFuncAttributeMaxDynamicSharedMemorySize, EK2_SMEM);

    const int GB = (NN + 63) / 64;

    // sort pipeline (cnt + offsets + bucketed edge list)
    zero_cnt_scat_kernel<<<(NN * 2 + 255) / 256, 256>>>();
    count_kernel<<<(EE + 255) / 256, 256>>>(ei);
    scan1_kernel<<<SCAN_B, 256>>>();
    scan2_kernel<<<1, 32>>>();
    scan3_kernel<<<SCAN_B, 256>>>();
    scatter_kernel<<<(EE + 255) / 256, 256>>>(ei);

    prep_wc_kernel<<<128, 128>>>(eW2, cW1, eb2, cb1);
    prep_wme_kernel<<<128, 128>>>(eW2, nW1 + 128 * HH, eb2);
    embed_kernel<<<NN / 2, 256>>>(h0, embW, embB);

    for (int layer = 0; layer < 2; layer++) {
        // m1 = h @ eW1[0:128], m2 = h @ eW1[128:256]  (single pass over h)
        node_gemm_m12<<<GB, 256, NG_SMEM>>>(p_h, eW1);
        // macc[r] = sum over sorted edges of relu(m1[r]+m2[c]+rd*wd+eb1) — no atomics
        macc_gather_kernel<<<(NN * 32 + 255) / 256, 256>>>(x, eW1, eb1);
        if (layer == 1)
            edge2_kernel<<<EE / 128, 256, EK2_SMEM>>>(x, eW1, eb1, cW2, cb2);
        // t = relu(h @ nW1a + macc @ W_me + nb1 + cnt*b_me)
        node_gemm<<<GB, 256, NG_SMEM>>>(p_h, nW1, p_macc, p_wme, nb1, p_bme, p_cnt,
                                        nullptr, p_t, NN, 1);
        // h = h + t @ nW2 + nb2
        float* hdst = (layer == 1) ? out_h : p_h;
        node_gemm<<<GB, 256, NG_SMEM>>>(p_t, nW2, nullptr, nullptr, nb2, nullptr, nullptr,
                                        p_h, hdst, NN, 0);
    }

    // t = relu(h @ vW1 + vb1)
    node_gemm<<<GB, 256, NG_SMEM>>>(out_h, vW1, nullptr, nullptr, vb1, nullptr, nullptr,
                                    nullptr, p_t, NN, 1);
    v_final_kernel<<<NN, 128>>>(vW2, vb2, out_v);
    copy_x_kernel<<<(NN * 2 + 255) / 256, 256>>>(x, out_x);
}

// round 8
// speedup vs baseline: 3.5058x; 1.2826x over previous
#include <cuda_runtime.h>
#include <cuda_bf16.h>
#include <cstdint>

#define NN 50000
#define EE 800000
#define HH 128
#define PP 16
#define SCAN_B 196   // ceil(NN/256)

typedef __nv_bfloat16 bf16;

// ---------------- scratch (device globals; no allocation allowed) -----------
__device__ float g_h[NN * HH];
__device__ float g_m1[NN * HH];
__device__ float g_m2[NN * HH];
__device__ float g_macc[NN * HH];
__device__ float g_t[NN * HH];
__device__ float g_scat[NN * 2];
__device__ int   g_cnt[NN];
__device__ int   g_off[NN + 1];
__device__ int   g_cur[NN];
__device__ int   g_bsum[SCAN_B];
__device__ int   g_rows[EE];
__device__ int   g_cols[EE];
__device__ float g_bc[HH];
__device__ float g_bme[HH];
// transposed bf16 hi/lo weights: B[n][k] = W[k][n]
__device__ bf16 g_Bhi[HH * HH];      // Wc (coord)
__device__ bf16 g_Blo[HH * HH];
__device__ bf16 g_BeW1a_h[HH * HH], g_BeW1a_l[HH * HH];
__device__ bf16 g_BeW1b_h[HH * HH], g_BeW1b_l[HH * HH];
__device__ bf16 g_BnW1a_h[HH * HH], g_BnW1a_l[HH * HH];
__device__ bf16 g_BnW2_h[HH * HH],  g_BnW2_l[HH * HH];
__device__ bf16 g_BvW1_h[HH * HH],  g_BvW1_l[HH * HH];
__device__ bf16 g_BWme_h[HH * HH],  g_BWme_l[HH * HH];

// ---------------- PTX helpers ------------------------------------------------
__device__ __forceinline__ void red_add_v2(float* p, float a, float b) {
    asm volatile("red.global.add.v2.f32 [%0], {%1,%2};"
                 :: "l"(p), "f"(a), "f"(b) : "memory");
}
__device__ __forceinline__ uint32_t smem_u32(const void* p) {
    uint32_t a;
    asm("{ .reg .u64 t; cvta.to.shared.u64 t, %1; cvt.u32.u64 %0, t; }" : "=r"(a) : "l"(p));
    return a;
}
__device__ __forceinline__ void ldmx4(uint32_t* r, uint32_t a) {
    asm volatile("ldmatrix.sync.aligned.m8n8.x4.shared.b16 {%0,%1,%2,%3}, [%4];"
                 : "=r"(r[0]), "=r"(r[1]), "=r"(r[2]), "=r"(r[3]) : "r"(a));
}
__device__ __forceinline__ void ldmx2(uint32_t& r0, uint32_t& r1, uint32_t a) {
    asm volatile("ldmatrix.sync.aligned.m8n8.x2.shared.b16 {%0,%1}, [%2];"
                 : "=r"(r0), "=r"(r1) : "r"(a));
}
__device__ __forceinline__ void mma_bf16(float* c, const uint32_t* a, uint32_t b0, uint32_t b1) {
    asm volatile(
        "mma.sync.aligned.m16n8k16.row.col.f32.bf16.bf16.f32 "
        "{%0,%1,%2,%3}, {%4,%5,%6,%7}, {%8,%9}, {%0,%1,%2,%3};"
        : "+f"(c[0]), "+f"(c[1]), "+f"(c[2]), "+f"(c[3])
        : "r"(a[0]), "r"(a[1]), "r"(a[2]), "r"(a[3]), "r"(b0), "r"(b1));
}
__device__ __forceinline__ void hilo4(float v0, float v1, float v2, float v3,
                                      uint2& hv, uint2& lv) {
    bf16 h0 = __float2bfloat16(v0), h1 = __float2bfloat16(v1);
    bf16 h2 = __float2bfloat16(v2), h3 = __float2bfloat16(v3);
    bf16 l0 = __float2bfloat16(v0 - __bfloat162float(h0));
    bf16 l1 = __float2bfloat16(v1 - __bfloat162float(h1));
    bf16 l2 = __float2bfloat16(v2 - __bfloat162float(h2));
    bf16 l3 = __float2bfloat16(v3 - __bfloat162float(h3));
    hv.x = ((uint32_t)__bfloat16_as_ushort(h1) << 16) | __bfloat16_as_ushort(h0);
    hv.y = ((uint32_t)__bfloat16_as_ushort(h3) << 16) | __bfloat16_as_ushort(h2);
    lv.x = ((uint32_t)__bfloat16_as_ushort(l1) << 16) | __bfloat16_as_ushort(l0);
    lv.y = ((uint32_t)__bfloat16_as_ushort(l3) << 16) | __bfloat16_as_ushort(l2);
}

// ---------------- sort pipeline ----------------------------------------------
__global__ void zero_cnt_scat_kernel() {
    int i = blockIdx.x * blockDim.x + threadIdx.x;
    if (i < NN) g_cnt[i] = 0;
    if (i < NN * 2) g_scat[i] = 0.f;
}

__global__ void count_kernel(const int* __restrict__ ei) {
    int e = blockIdx.x * blockDim.x + threadIdx.x;
    if (e < EE) atomicAdd(&g_cnt[ei[e]], 1);
}

__global__ void scan1_kernel() {
    __shared__ int sm[256];
    int b = blockIdx.x, t = threadIdx.x, i = b * 256 + t;
    int v = (i < NN) ? g_cnt[i] : 0;
    sm[t] = v; __syncthreads();
    for (int o = 128; o; o >>= 1) {
        if (t < o) sm[t] += sm[t + o];
        __syncthreads();
    }
    if (t == 0) g_bsum[b] = sm[0];
}

__global__ void scan2_kernel() {   // parallel exclusive scan of 196 block sums
    __shared__ int sm[256];
    int t = threadIdx.x;
    int v = (t < SCAN_B) ? g_bsum[t] : 0;
    sm[t] = v; __syncthreads();
    for (int o = 1; o < 256; o <<= 1) {
        int add = (t >= o) ? sm[t - o] : 0;
        __syncthreads();
        sm[t] += add;
        __syncthreads();
    }
    if (t < SCAN_B) g_bsum[t] = sm[t] - v;
    if (t == 0) g_off[NN] = EE;
}

__global__ void scan3_kernel() {
    __shared__ int sm[256];
    int b = blockIdx.x, t = threadIdx.x, i = b * 256 + t;
    int v = (i < NN) ? g_cnt[i] : 0;
    sm[t] = v; __syncthreads();
    for (int o = 1; o < 256; o <<= 1) {
        int add = (t >= o) ? sm[t - o] : 0;
        __syncthreads();
        sm[t] += add;
        __syncthreads();
    }
    if (i < NN) {
        int off = g_bsum[b] + sm[t] - v;
        g_off[i] = off;
        g_cur[i] = off;
    }
}

__global__ void scatter_kernel(const int* __restrict__ ei) {
    int e = blockIdx.x * blockDim.x + threadIdx.x;
    if (e < EE) {
        int r = ei[e];
        int pos = atomicAdd(&g_cur[r], 1);
        g_rows[pos] = r;
        g_cols[pos] = ei[EE + e];
    }
}

// ---------------- prep kernels ------------------------------------------------
// split W[k][n] (row-major) into transposed bf16 hi/lo B[n][k]
__global__ void prep_bt_kernel(const float* __restrict__ W, bf16* __restrict__ oh,
                               bf16* __restrict__ ol) {
    int i = blockIdx.x, j = threadIdx.x;   // k=i, n=j
    float s = W[i * HH + j];
    bf16 hi = __float2bfloat16(s);
    bf16 lo = __float2bfloat16(s - __bfloat162float(hi));
    oh[j * HH + i] = hi;
    ol[j * HH + i] = lo;
}

// Wc = e_W2 @ c_W1 (transposed hi/lo into g_Bhi/g_Blo); bc = e_b2 @ c_W1 + c_b1
__global__ void prep_wc_kernel(const float* __restrict__ eW2, const float* __restrict__ cW1,
                               const float* __restrict__ eb2, const float* __restrict__ cb1) {
    int i = blockIdx.x, j = threadIdx.x;
    float s = 0.f;
    for (int k = 0; k < HH; k++) s += eW2[i * HH + k] * cW1[k * HH + j];
    bf16 hi = __float2bfloat16(s);
    bf16 lo = __float2bfloat16(s - __bfloat162float(hi));
    g_Bhi[j * HH + i] = hi;
    g_Blo[j * HH + i] = lo;
    if (i == 0) {
        float t = 0.f;
        for (int k = 0; k < HH; k++) t += eb2[k] * cW1[k * HH + j];
        g_bc[j] = t + cb1[j];
    }
}

// W_me = e_W2 @ nW1[128:256] (transposed hi/lo); b_me = e_b2 @ nW1b
__global__ void prep_wme_kernel(const float* __restrict__ eW2, const float* __restrict__ nW1b,
                                const float* __restrict__ eb2) {
    int i = blockIdx.x, j = threadIdx.x;
    float s = 0.f;
    for (int k = 0; k < HH; k++) s += eW2[i * HH + k] * nW1b[k * HH + j];
    bf16 hi = __float2bfloat16(s);
    bf16 lo = __float2bfloat16(s - __bfloat162float(hi));
    g_BWme_h[j * HH + i] = hi;
    g_BWme_l[j * HH + i] = lo;
    if (i == 0) {
        float t = 0.f;
        for (int k = 0; k < HH; k++) t += eb2[k] * nW1b[k * HH + j];
        g_bme[j] = t;
    }
}

// h = h0 @ emb_W + emb_b
__global__ void embed_kernel(const float* __restrict__ h0, const float* __restrict__ W,
                             const float* __restrict__ b) {
    int row = blockIdx.x * 2 + (threadIdx.x >> 7);
    int j = threadIdx.x & 127;
    if (row >= NN) return;
    float s = b[j];
#pragma unroll
    for (int k = 0; k < PP; k++) s += h0[row * PP + k] * W[k * HH + j];
    g_h[row * HH + j] = s;
}

// ---------------- tensor-core node GEMM --------------------------------------
// C[128-tile,128] = act( A1@W1 (+A2@W2) + bias + cnt*bias2 (+resid) )
// Weights pre-split to transposed bf16 hi/lo. A converted to hi/lo in SMEM.
// 8 warps; warp w owns output cols [w*16, w*16+16) (2 n-tiles), all 8 m-tiles.
#define NM_ST 272                 // bf16 row stride in bytes (136 elems)
#define NM_A_HI 0
#define NM_A_LO 34816
#define NM_B_HI 69632
#define NM_B_LO 104448
#define NM_MISC 139264
#define NM_SMEM (NM_MISC + 1024)

__global__ void __launch_bounds__(256)
node_mma(const float* __restrict__ A1, const bf16* __restrict__ B1h, const bf16* __restrict__ B1l,
         const float* __restrict__ A2, const bf16* __restrict__ B2h, const bf16* __restrict__ B2l,
         const float* __restrict__ bias, const float* __restrict__ bias2,
         const int* __restrict__ cnt, const float* __restrict__ resid,
         float* __restrict__ C, int do_relu) {
    extern __shared__ char smc[];
    char* A_hi = smc + NM_A_HI;
    char* A_lo = smc + NM_A_LO;
    char* B_hi = smc + NM_B_HI;
    char* B_lo = smc + NM_B_LO;
    float* bs  = (float*)(smc + NM_MISC);       // 128
    float* bs2 = bs + 128;                       // 128

    const int tid = threadIdx.x;
    const int wid = tid >> 5, lane = tid & 31;
    const int m0 = blockIdx.x * 128;

    if (tid < 128) {
        bs[tid]  = bias ? bias[tid] : 0.f;
        bs2[tid] = bias2 ? bias2[tid] : 0.f;
    }

    float acc[8][2][4];
#pragma unroll
    for (int m = 0; m < 8; m++)
#pragma unroll
        for (int nt = 0; nt < 2; nt++)
#pragma unroll
            for (int q = 0; q < 4; q++) acc[m][nt][q] = 0.f;

    uint32_t bh[2][8][2], bl[2][8][2];
    const uint32_t ah_base = smem_u32(A_hi);
    const uint32_t al_base = smem_u32(A_lo);
    const uint32_t bhs_base = smem_u32(B_hi);
    const uint32_t bls_base = smem_u32(B_lo);

    const int nsrc = A2 ? 2 : 1;
    for (int s = 0; s < nsrc; s++) {
        const float* A = s ? A2 : A1;
        const bf16* Bh = s ? B2h : B1h;
        const bf16* Bl = s ? B2l : B1l;
        // stage B (transposed weights) into SMEM rows n, stride NM_ST
        for (int idx = tid; idx < 8192; idx += 256) {
            int n = idx >> 6, kp = idx & 63;
            int off = n * NM_ST + kp * 4;
            *(uint32_t*)(B_hi + off) = ((const uint32_t*)Bh)[idx];
            *(uint32_t*)(B_lo + off) = ((const uint32_t*)Bl)[idx];
        }
        // convert A tile fp32 -> hi/lo bf16
        for (int idx = tid; idx < 128 * 32; idx += 256) {
            int r = idx >> 5, c4 = (idx & 31) << 2;
            int gr = m0 + r;
            float4 v = (gr < NN) ? *(const float4*)&A[gr * HH + c4]
                                 : make_float4(0.f, 0.f, 0.f, 0.f);
            uint2 hv, lv;
            hilo4(v.x, v.y, v.z, v.w, hv, lv);
            int off = r * NM_ST + c4 * 2;
            *(uint2*)(A_hi + off) = hv;
            *(uint2*)(A_lo + off) = lv;
        }
        __syncthreads();

        // preload B fragments for this warp's 16 cols
        {
            int roff = (lane & 7) * NM_ST + ((lane >> 3) & 1) * 16;
#pragma unroll
            for (int nt = 0; nt < 2; nt++)
#pragma unroll
                for (int k = 0; k < 8; k++) {
                    uint32_t a = (wid * 16 + nt * 8) * NM_ST + k * 32 + roff;
                    ldmx2(bh[nt][k][0], bh[nt][k][1], bhs_base + a);
                    ldmx2(bl[nt][k][0], bl[nt][k][1], bls_base + a);
                }
        }

        // mma over all m-tiles
        {
            int aroff = (lane & 15) * NM_ST + ((lane >> 4) & 1) * 16;
#pragma unroll
            for (int m = 0; m < 8; m++) {
#pragma unroll
                for (int k = 0; k < 8; k++) {
                    uint32_t a = (m * 16) * NM_ST + k * 32 + aroff;
                    uint32_t ahf[4], alf[4];
                    ldmx4(ahf, ah_base + a);
                    ldmx4(alf, al_base + a);
#pragma unroll
                    for (int nt = 0; nt < 2; nt++) {
                        mma_bf16(acc[m][nt], ahf, bh[nt][k][0], bh[nt][k][1]);
                        mma_bf16(acc[m][nt], ahf, bl[nt][k][0], bl[nt][k][1]);
                        mma_bf16(acc[m][nt], alf, bh[nt][k][0], bh[nt][k][1]);
                    }
                }
            }
        }
        __syncthreads();   // before next source overwrites SMEM
    }

    // epilogue
#pragma unroll
    for (int m = 0; m < 8; m++) {
        int r0 = m0 + m * 16 + (lane >> 2);
        int r1 = r0 + 8;
        float cm0 = (cnt && r0 < NN) ? (float)cnt[r0] : 0.f;
        float cm1 = (cnt && r1 < NN) ? (float)cnt[r1] : 0.f;
#pragma unroll
        for (int nt = 0; nt < 2; nt++) {
            int n = wid * 16 + nt * 8 + (lane & 3) * 2;
            float o0 = acc[m][nt][0] + bs[n] + cm0 * bs2[n];
            float o1 = acc[m][nt][1] + bs[n + 1] + cm0 * bs2[n + 1];
            float o2 = acc[m][nt][2] + bs[n] + cm1 * bs2[n];
            float o3 = acc[m][nt][3] + bs[n + 1] + cm1 * bs2[n + 1];
            if (resid) {
                if (r0 < NN) {
                    float2 rv = *(const float2*)&resid[r0 * HH + n];
                    o0 += rv.x; o1 += rv.y;
                }
                if (r1 < NN) {
                    float2 rv = *(const float2*)&resid[r1 * HH + n];
                    o2 += rv.x; o3 += rv.y;
                }
            }
            if (do_relu) {
                o0 = fmaxf(o0, 0.f); o1 = fmaxf(o1, 0.f);
                o2 = fmaxf(o2, 0.f); o3 = fmaxf(o3, 0.f);
            }
            if (r0 < NN) *(float2*)&C[r0 * HH + n] = make_float2(o0, o1);
            if (r1 < NN) *(float2*)&C[r1 * HH + n] = make_float2(o2, o3);
        }
    }
}

// ---------------- macc gather: one warp per node (no atomics) ----------------
__global__ void macc_gather_kernel(const float* __restrict__ x,
                                   const float* __restrict__ eW1,
                                   const float* __restrict__ eb1) {
    int warp = (blockIdx.x * blockDim.x + threadIdx.x) >> 5;
    int lane = threadIdx.x & 31;
    if (warp >= NN) return;
    int r = warp;
    int j = lane << 2;
    float4 m1v = *(const float4*)&g_m1[r * HH + j];
    float4 wd  = *(const float4*)&eW1[256 * HH + j];
    float4 b1  = *(const float4*)&eb1[j];
    float2 xr  = *(const float2*)&x[2 * r];
    float4 acc = make_float4(0.f, 0.f, 0.f, 0.f);
    int s = g_off[r], e = g_off[r + 1];
    for (int idx = s; idx < e; idx++) {
        int c = __ldg(&g_cols[idx]);
        float2 xc = *(const float2*)&x[2 * c];
        float dx = xr.x - xc.x, dy = xr.y - xc.y;
        float rd = dx * dx + dy * dy;
        float4 m2v = *(const float4*)&g_m2[c * HH + j];
        acc.x += fmaxf(m1v.x + m2v.x + rd * wd.x + b1.x, 0.f);
        acc.y += fmaxf(m1v.y + m2v.y + rd * wd.y + b1.y, 0.f);
        acc.z += fmaxf(m1v.z + m2v.z + rd * wd.z + b1.z, 0.f);
        acc.w += fmaxf(m1v.w + m2v.w + rd * wd.w + b1.w, 0.f);
    }
    *(float4*)&g_macc[r * HH + j] = acc;
}

// ---------------- coord kernel (layer 2 only, mma.sync) ----------------------
#define EK2_ASTRIDE 272
#define EK2_A_HI 0
#define EK2_A_LO 34816
#define EK2_MISC 69632
#define EK2_SMEM (EK2_MISC + 5120)

__global__ void __launch_bounds__(256)
edge2_kernel(const float* __restrict__ x,
             const float* __restrict__ eW1, const float* __restrict__ eb1,
             const float* __restrict__ cW2, const float* __restrict__ cb2) {
    extern __shared__ char smc[];
    char* A_hi = smc + EK2_A_HI;
    char* A_lo = smc + EK2_A_LO;
    float* misc   = (float*)(smc + EK2_MISC);
    float* wd_s   = misc;
    float* b1_s   = misc + 128;
    float* bc_s   = misc + 256;
    float* cw2_s  = misc + 384;
    float* p2a_s  = misc + 512;
    float* p2b_s  = misc + 640;
    float* rd_s   = misc + 768;
    float* coordp = misc + 896;
    int* row_s = (int*)(misc + 1024);
    int* col_s = (int*)(misc + 1152);

    const int tid = threadIdx.x;
    const int wid = tid >> 5, lane = tid & 31;

    if (tid < 128) {
        wd_s[tid]  = eW1[256 * HH + tid];
        b1_s[tid]  = eb1[tid];
        bc_s[tid]  = g_bc[tid];
        cw2_s[tid] = cW2[tid];
        coordp[tid] = 0.f;
        int eg = blockIdx.x * 128 + tid;
        int r = g_rows[eg], c = g_cols[eg];
        row_s[tid] = r; col_s[tid] = c;
        float2 xr = *(const float2*)&x[2 * r];
        float2 xc = *(const float2*)&x[2 * c];
        float dx = xr.x - xc.x, dy = xr.y - xc.y;
        rd_s[tid]  = dx * dx + dy * dy;
        p2a_s[tid] = dx * dx - dy * dy;
        p2b_s[tid] = 2.f * dx * dy;
    }
    for (int idx = tid; idx < 8192; idx += 256) {
        int n = idx >> 6, kp = idx & 63;
        uint32_t vh = ((const uint32_t*)g_Bhi)[idx];
        uint32_t vl = ((const uint32_t*)g_Blo)[idx];
        int off = n * EK2_ASTRIDE + kp * 4;
        *(uint32_t*)(A_hi + off) = vh;
        *(uint32_t*)(A_lo + off) = vl;
    }
    __syncthreads();

    uint32_t bh[2][8][2], bl[2][8][2];
    {
        uint32_t hbase = smem_u32(A_hi);
        uint32_t lbase = smem_u32(A_lo);
        int roff = (lane & 7) * EK2_ASTRIDE + ((lane >> 3) & 1) * 16;
#pragma unroll
        for (int nt = 0; nt < 2; nt++)
#pragma unroll
            for (int k = 0; k < 8; k++) {
                uint32_t a = (wid * 16 + nt * 8) * EK2_ASTRIDE + k * 32 + roff;
                ldmx2(bh[nt][k][0], bh[nt][k][1], hbase + a);
                ldmx2(bl[nt][k][0], bl[nt][k][1], lbase + a);
            }
    }
    __syncthreads();

    // phase 1: preact, write A tiles (macc handled by gather kernel)
#pragma unroll
    for (int s = 0; s < 16; s++) {
        int item = tid + s * 256;
        int e = item >> 5, j = (item & 31) << 2;
        int r = row_s[e], c = col_s[e];
        float rd = rd_s[e];
        float4 a  = *(const float4*)&g_m1[r * HH + j];
        float4 b  = *(const float4*)&g_m2[c * HH + j];
        float4 w  = *(const float4*)&wd_s[j];
        float4 bb = *(const float4*)&b1_s[j];
        float v0 = fmaxf(a.x + b.x + rd * w.x + bb.x, 0.f);
        float v1 = fmaxf(a.y + b.y + rd * w.y + bb.y, 0.f);
        float v2 = fmaxf(a.z + b.z + rd * w.z + bb.z, 0.f);
        float v3 = fmaxf(a.w + b.w + rd * w.w + bb.w, 0.f);
        uint2 hv, lv;
        hilo4(v0, v1, v2, v3, hv, lv);
        int off = e * EK2_ASTRIDE + j * 2;
        *(uint2*)(A_hi + off) = hv;
        *(uint2*)(A_lo + off) = lv;
    }
    __syncthreads();

    // phase 2: C = A @ Wc via mma, fused coord dot + scatter
    {
        uint32_t hbase = smem_u32(A_hi);
        uint32_t lbase = smem_u32(A_lo);
        int aroff = (lane & 15) * EK2_ASTRIDE + ((lane >> 4) & 1) * 16;
#pragma unroll
        for (int m = 0; m < 8; m++) {
            float acc[2][4];
#pragma unroll
            for (int nt = 0; nt < 2; nt++)
#pragma unroll
                for (int q = 0; q < 4; q++) acc[nt][q] = 0.f;
#pragma unroll
            for (int k = 0; k < 8; k++) {
                uint32_t a = (m * 16) * EK2_ASTRIDE + k * 32 + aroff;
                uint32_t ah[4], al[4];
                ldmx4(ah, hbase + a);
                ldmx4(al, lbase + a);
#pragma unroll
                for (int nt = 0; nt < 2; nt++) {
                    mma_bf16(acc[nt], ah, bh[nt][k][0], bh[nt][k][1]);
                    mma_bf16(acc[nt], ah, bl[nt][k][0], bl[nt][k][1]);
                    mma_bf16(acc[nt], al, bh[nt][k][0], bh[nt][k][1]);
                }
            }
            int r0 = m * 16 + (lane >> 2);
            float p0 = 0.f, p1 = 0.f;
#pragma unroll
            for (int nt = 0; nt < 2; nt++) {
                int n = wid * 16 + nt * 8 + (lane & 3) * 2;
                p0 += fmaxf(acc[nt][0] + bc_s[n], 0.f) * cw2_s[n]
                    + fmaxf(acc[nt][1] + bc_s[n + 1], 0.f) * cw2_s[n + 1];
                p1 += fmaxf(acc[nt][2] + bc_s[n], 0.f) * cw2_s[n]
                    + fmaxf(acc[nt][3] + bc_s[n + 1], 0.f) * cw2_s[n + 1];
            }
            p0 += __shfl_xor_sync(0xffffffffu, p0, 1);
            p0 += __shfl_xor_sync(0xffffffffu, p0, 2);
            p1 += __shfl_xor_sync(0xffffffffu, p1, 1);
            p1 += __shfl_xor_sync(0xffffffffu, p1, 2);
            if ((lane & 3) == 0) {
                atomicAdd(&coordp[r0], p0);
                atomicAdd(&coordp[r0 + 8], p1);
            }
        }
    }
    __syncthreads();
    if (tid < 128) {
        float csum = coordp[tid] + cb2[0];
        red_add_v2(&g_scat[2 * row_s[tid]], p2a_s[tid] * csum, p2b_s[tid] * csum);
    }
}

// ---------------- v epilogue -------------------------------------------------
__global__ void v_final_kernel(const float* __restrict__ vW2, const float* __restrict__ vb2,
                               float* __restrict__ outv) {
    int row = blockIdx.x;
    int k = threadIdx.x;
    float tv = g_t[row * HH + k];
    float p0 = tv * vW2[k * 2 + 0];
    float p1 = tv * vW2[k * 2 + 1];
#pragma unroll
    for (int o = 16; o; o >>= 1) {
        p0 += __shfl_down_sync(0xffffffffu, p0, o);
        p1 += __shfl_down_sync(0xffffffffu, p1, o);
    }
    __shared__ float s0[4], s1[4];
    if ((k & 31) == 0) { s0[k >> 5] = p0; s1[k >> 5] = p1; }
    __syncthreads();
    if (k == 0) {
        float v0 = vb2[0], v1 = vb2[1];
#pragma unroll
        for (int w = 0; w < 4; w++) { v0 += s0[w]; v1 += s1[w]; }
        float d = fmaxf((float)g_cnt[row], 1.f);
        v0 += g_scat[2 * row] / d;
        v1 += g_scat[2 * row + 1] / d;
        float n = fmaxf(sqrtf(v0 * v0 + v1 * v1), 1e-12f);
        outv[2 * row] = v0 / n;
        outv[2 * row + 1] = v1 / n;
    }
}

__global__ void copy_x_kernel(const float* __restrict__ x, float* __restrict__ outx) {
    int i = blockIdx.x * blockDim.x + threadIdx.x;
    if (i < NN * 2) outx[i] = x[i];
}

// ---------------- launcher ---------------------------------------------------
extern "C" void kernel_launch(void* const* d_in, const int* in_sizes, int n_in,
                              void* d_out, int out_size) {
    const float* h0   = (const float*)d_in[0];
    const float* x    = (const float*)d_in[1];
    const int*   ei   = (const int*)d_in[2];
    const float* embW = (const float*)d_in[3];
    const float* embB = (const float*)d_in[4];
    const float* eW1  = (const float*)d_in[5];
    const float* eb1  = (const float*)d_in[6];
    const float* eW2  = (const float*)d_in[7];
    const float* eb2  = (const float*)d_in[8];
    const float* nW1  = (const float*)d_in[9];
    const float* nb1  = (const float*)d_in[10];
    const float* nW2  = (const float*)d_in[11];
    const float* nb2  = (const float*)d_in[12];
    const float* vW1  = (const float*)d_in[13];
    const float* vb1  = (const float*)d_in[14];
    const float* vW2  = (const float*)d_in[15];
    const float* vb2  = (const float*)d_in[16];
    const float* cW1  = (const float*)d_in[17];
    const float* cb1  = (const float*)d_in[18];
    const float* cW2  = (const float*)d_in[19];
    const float* cb2  = (const float*)d_in[20];

    float* out   = (float*)d_out;
    float* out_h = out;
    float* out_x = out + NN * HH;
    float* out_v = out + NN * HH + NN * 2;

    float *p_h, *p_macc, *p_t, *p_m1, *p_m2, *p_bme;
    int* p_cnt;
    cudaGetSymbolAddress((void**)&p_h,    g_h);
    cudaGetSymbolAddress((void**)&p_macc, g_macc);
    cudaGetSymbolAddress((void**)&p_t,    g_t);
    cudaGetSymbolAddress((void**)&p_cnt,  g_cnt);
    cudaGetSymbolAddress((void**)&p_m1,   g_m1);
    cudaGetSymbolAddress((void**)&p_m2,   g_m2);
    cudaGetSymbolAddress((void**)&p_bme,  g_bme);

    bf16 *b_eW1a_h, *b_eW1a_l, *b_eW1b_h, *b_eW1b_l, *b_nW1a_h, *b_nW1a_l;
    bf16 *b_nW2_h, *b_nW2_l, *b_vW1_h, *b_vW1_l, *b_Wme_h, *b_Wme_l;
    cudaGetSymbolAddress((void**)&b_eW1a_h, g_BeW1a_h);
    cudaGetSymbolAddress((void**)&b_eW1a_l, g_BeW1a_l);
    cudaGetSymbolAddress((void**)&b_eW1b_h, g_BeW1b_h);
    cudaGetSymbolAddress((void**)&b_eW1b_l, g_BeW1b_l);
    cudaGetSymbolAddress((void**)&b_nW1a_h, g_BnW1a_h);
    cudaGetSymbolAddress((void**)&b_nW1a_l, g_BnW1a_l);
    cudaGetSymbolAddress((void**)&b_nW2_h,  g_BnW2_h);
    cudaGetSymbolAddress((void**)&b_nW2_l,  g_BnW2_l);
    cudaGetSymbolAddress((void**)&b_vW1_h,  g_BvW1_h);
    cudaGetSymbolAddress((void**)&b_vW1_l,  g_BvW1_l);
    cudaGetSymbolAddress((void**)&b_Wme_h,  g_BWme_h);
    cudaGetSymbolAddress((void**)&b_Wme_l,  g_BWme_l);

    cudaFuncSetAttribute(node_mma, cudaFuncAttributeMaxDynamicSharedMemorySize, NM_SMEM);
    cudaFuncSetAttribute(edge2_kernel, cudaFuncAttributeMaxDynamicSharedMemorySize, EK2_SMEM);

    const int GB = (NN + 127) / 128;

    // sort pipeline
    zero_cnt_scat_kernel<<<(NN * 2 + 255) / 256, 256>>>();
    count_kernel<<<(EE + 255) / 256, 256>>>(ei);
    scan1_kernel<<<SCAN_B, 256>>>();
    scan2_kernel<<<1, 256>>>();
    scan3_kernel<<<SCAN_B, 256>>>();
    scatter_kernel<<<(EE + 255) / 256, 256>>>(ei);

    // weight prep
    prep_wc_kernel<<<128, 128>>>(eW2, cW1, eb2, cb1);
    prep_wme_kernel<<<128, 128>>>(eW2, nW1 + 128 * HH, eb2);
    prep_bt_kernel<<<128, 128>>>(eW1, b_eW1a_h, b_eW1a_l);
    prep_bt_kernel<<<128, 128>>>(eW1 + 128 * HH, b_eW1b_h, b_eW1b_l);
    prep_bt_kernel<<<128, 128>>>(nW1, b_nW1a_h, b_nW1a_l);
    prep_bt_kernel<<<128, 128>>>(nW2, b_nW2_h, b_nW2_l);
    prep_bt_kernel<<<128, 128>>>(vW1, b_vW1_h, b_vW1_l);
    embed_kernel<<<NN / 2, 256>>>(h0, embW, embB);

    for (int layer = 0; layer < 2; layer++) {
        // m1 = h @ eW1a ; m2 = h @ eW1b
        node_mma<<<GB, 256, NM_SMEM>>>(p_h, b_eW1a_h, b_eW1a_l, nullptr, nullptr, nullptr,
                                       nullptr, nullptr, nullptr, nullptr, p_m1, 0);
        node_mma<<<GB, 256, NM_SMEM>>>(p_h, b_eW1b_h, b_eW1b_l, nullptr, nullptr, nullptr,
                                       nullptr, nullptr, nullptr, nullptr, p_m2, 0);
        macc_gather_kernel<<<(NN * 32 + 255) / 256, 256>>>(x, eW1, eb1);
        if (layer == 1)
            edge2_kernel<<<EE / 128, 256, EK2_SMEM>>>(x, eW1, eb1, cW2, cb2);
        // t = relu(h @ nW1a + macc @ Wme + nb1 + cnt*bme)
        node_mma<<<GB, 256, NM_SMEM>>>(p_h, b_nW1a_h, b_nW1a_l, p_macc, b_Wme_h, b_Wme_l,
                                       nb1, p_bme, p_cnt, nullptr, p_t, 1);
        // h = h + t @ nW2 + nb2
        float* hdst = (layer == 1) ? out_h : p_h;
        node_mma<<<GB, 256, NM_SMEM>>>(p_t, b_nW2_h, b_nW2_l, nullptr, nullptr, nullptr,
                                       nb2, nullptr, nullptr, p_h, hdst, 0);
    }

    // t = relu(h_final @ vW1 + vb1)
    node_mma<<<GB, 256, NM_SMEM>>>(out_h, b_vW1_h, b_vW1_l, nullptr, nullptr, nullptr,
                                   vb1, nullptr, nullptr, nullptr, p_t, 1);
    v_final_kernel<<<NN, 128>>>(vW2, vb2, out_v);
    copy_x_kernel<<<(NN * 2 + 255) / 256, 256>>>(x, out_x);
}

// round 9
// speedup vs baseline: 3.9613x; 1.1300x over previous
#include <cuda_runtime.h>
#include <cuda_bf16.h>
#include <cstdint>

#define NN 50000
#define EE 800000
#define HH 128
#define PP 16
#define SCAN_B 196   // ceil(NN/256)

typedef __nv_bfloat16 bf16;

// ---------------- scratch (device globals; no allocation allowed) -----------
__device__ float g_h[NN * HH];
__device__ float g_m1[NN * HH];
__device__ float g_m2[NN * HH];
__device__ float g_macc[NN * HH];
__device__ float g_scat[NN * 2];
__device__ int   g_cnt[NN];
__device__ int   g_off[NN + 1];
__device__ int   g_cur[NN];
__device__ int   g_bsum[SCAN_B];
__device__ int   g_rows[EE];
__device__ int   g_cols[EE];
__device__ float g_bc[HH];
__device__ float g_bme[HH];
// transposed bf16 hi/lo weights: B[n][k] = W[k][n]
__device__ bf16 g_Bhi[HH * HH];      // Wc (coord)
__device__ bf16 g_Blo[HH * HH];
__device__ bf16 g_BeW1a_h[HH * HH], g_BeW1a_l[HH * HH];
__device__ bf16 g_BeW1b_h[HH * HH], g_BeW1b_l[HH * HH];
__device__ bf16 g_BnW1a_h[HH * HH], g_BnW1a_l[HH * HH];
__device__ bf16 g_BnW2_h[HH * HH],  g_BnW2_l[HH * HH];
__device__ bf16 g_BvW1_h[HH * HH],  g_BvW1_l[HH * HH];
__device__ bf16 g_BWme_h[HH * HH],  g_BWme_l[HH * HH];

// ---------------- PTX helpers ------------------------------------------------
__device__ __forceinline__ void red_add_v2(float* p, float a, float b) {
    asm volatile("red.global.add.v2.f32 [%0], {%1,%2};"
                 :: "l"(p), "f"(a), "f"(b) : "memory");
}
__device__ __forceinline__ uint32_t smem_u32(const void* p) {
    uint32_t a;
    asm("{ .reg .u64 t; cvta.to.shared.u64 t, %1; cvt.u32.u64 %0, t; }" : "=r"(a) : "l"(p));
    return a;
}
__device__ __forceinline__ void ldmx4(uint32_t* r, uint32_t a) {
    asm volatile("ldmatrix.sync.aligned.m8n8.x4.shared.b16 {%0,%1,%2,%3}, [%4];"
                 : "=r"(r[0]), "=r"(r[1]), "=r"(r[2]), "=r"(r[3]) : "r"(a));
}
__device__ __forceinline__ void ldmx2(uint32_t& r0, uint32_t& r1, uint32_t a) {
    asm volatile("ldmatrix.sync.aligned.m8n8.x2.shared.b16 {%0,%1}, [%2];"
                 : "=r"(r0), "=r"(r1) : "r"(a));
}
__device__ __forceinline__ void mma_bf16(float* c, const uint32_t* a, uint32_t b0, uint32_t b1) {
    asm volatile(
        "mma.sync.aligned.m16n8k16.row.col.f32.bf16.bf16.f32 "
        "{%0,%1,%2,%3}, {%4,%5,%6,%7}, {%8,%9}, {%0,%1,%2,%3};"
        : "+f"(c[0]), "+f"(c[1]), "+f"(c[2]), "+f"(c[3])
        : "r"(a[0]), "r"(a[1]), "r"(a[2]), "r"(a[3]), "r"(b0), "r"(b1));
}
__device__ __forceinline__ void hilo4(float v0, float v1, float v2, float v3,
                                      uint2& hv, uint2& lv) {
    bf16 h0 = __float2bfloat16(v0), h1 = __float2bfloat16(v1);
    bf16 h2 = __float2bfloat16(v2), h3 = __float2bfloat16(v3);
    bf16 l0 = __float2bfloat16(v0 - __bfloat162float(h0));
    bf16 l1 = __float2bfloat16(v1 - __bfloat162float(h1));
    bf16 l2 = __float2bfloat16(v2 - __bfloat162float(h2));
    bf16 l3 = __float2bfloat16(v3 - __bfloat162float(h3));
    hv.x = ((uint32_t)__bfloat16_as_ushort(h1) << 16) | __bfloat16_as_ushort(h0);
    hv.y = ((uint32_t)__bfloat16_as_ushort(h3) << 16) | __bfloat16_as_ushort(h2);
    lv.x = ((uint32_t)__bfloat16_as_ushort(l1) << 16) | __bfloat16_as_ushort(l0);
    lv.y = ((uint32_t)__bfloat16_as_ushort(l3) << 16) | __bfloat16_as_ushort(l2);
}
__device__ __forceinline__ void hilo2(float a, float b, uint32_t& h, uint32_t& l) {
    bf16 ha = __float2bfloat16(a), hb = __float2bfloat16(b);
    bf16 la = __float2bfloat16(a - __bfloat162float(ha));
    bf16 lb = __float2bfloat16(b - __bfloat162float(hb));
    h = ((uint32_t)__bfloat16_as_ushort(hb) << 16) | __bfloat16_as_ushort(ha);
    l = ((uint32_t)__bfloat16_as_ushort(lb) << 16) | __bfloat16_as_ushort(la);
}

// ---------------- sort pipeline ----------------------------------------------
__global__ void zero_cnt_scat_kernel() {
    int i = blockIdx.x * blockDim.x + threadIdx.x;
    if (i < NN) g_cnt[i] = 0;
    if (i < NN * 2) g_scat[i] = 0.f;
}

__global__ void count_kernel(const int* __restrict__ ei) {
    int e = blockIdx.x * blockDim.x + threadIdx.x;
    if (e < EE) atomicAdd(&g_cnt[ei[e]], 1);
}

__global__ void scan1_kernel() {
    __shared__ int sm[256];
    int b = blockIdx.x, t = threadIdx.x, i = b * 256 + t;
    int v = (i < NN) ? g_cnt[i] : 0;
    sm[t] = v; __syncthreads();
    for (int o = 128; o; o >>= 1) {
        if (t < o) sm[t] += sm[t + o];
        __syncthreads();
    }
    if (t == 0) g_bsum[b] = sm[0];
}

__global__ void scan2_kernel() {
    __shared__ int sm[256];
    int t = threadIdx.x;
    int v = (t < SCAN_B) ? g_bsum[t] : 0;
    sm[t] = v; __syncthreads();
    for (int o = 1; o < 256; o <<= 1) {
        int add = (t >= o) ? sm[t - o] : 0;
        __syncthreads();
        sm[t] += add;
        __syncthreads();
    }
    if (t < SCAN_B) g_bsum[t] = sm[t] - v;
    if (t == 0) g_off[NN] = EE;
}

__global__ void scan3_kernel() {
    __shared__ int sm[256];
    int b = blockIdx.x, t = threadIdx.x, i = b * 256 + t;
    int v = (i < NN) ? g_cnt[i] : 0;
    sm[t] = v; __syncthreads();
    for (int o = 1; o < 256; o <<= 1) {
        int add = (t >= o) ? sm[t - o] : 0;
        __syncthreads();
        sm[t] += add;
        __syncthreads();
    }
    if (i < NN) {
        int off = g_bsum[b] + sm[t] - v;
        g_off[i] = off;
        g_cur[i] = off;
    }
}

__global__ void scatter_kernel(const int* __restrict__ ei) {
    int e = blockIdx.x * blockDim.x + threadIdx.x;
    if (e < EE) {
        int r = ei[e];
        int pos = atomicAdd(&g_cur[r], 1);
        g_rows[pos] = r;
        g_cols[pos] = ei[EE + e];
    }
}

// ---------------- prep kernels ------------------------------------------------
__global__ void prep_bt_kernel(const float* __restrict__ W, bf16* __restrict__ oh,
                               bf16* __restrict__ ol) {
    int i = blockIdx.x, j = threadIdx.x;   // k=i, n=j
    float s = W[i * HH + j];
    bf16 hi = __float2bfloat16(s);
    bf16 lo = __float2bfloat16(s - __bfloat162float(hi));
    oh[j * HH + i] = hi;
    ol[j * HH + i] = lo;
}

__global__ void prep_wc_kernel(const float* __restrict__ eW2, const float* __restrict__ cW1,
                               const float* __restrict__ eb2, const float* __restrict__ cb1) {
    int i = blockIdx.x, j = threadIdx.x;
    float s = 0.f;
    for (int k = 0; k < HH; k++) s += eW2[i * HH + k] * cW1[k * HH + j];
    bf16 hi = __float2bfloat16(s);
    bf16 lo = __float2bfloat16(s - __bfloat162float(hi));
    g_Bhi[j * HH + i] = hi;
    g_Blo[j * HH + i] = lo;
    if (i == 0) {
        float t = 0.f;
        for (int k = 0; k < HH; k++) t += eb2[k] * cW1[k * HH + j];
        g_bc[j] = t + cb1[j];
    }
}

__global__ void prep_wme_kernel(const float* __restrict__ eW2, const float* __restrict__ nW1b,
                                const float* __restrict__ eb2) {
    int i = blockIdx.x, j = threadIdx.x;
    float s = 0.f;
    for (int k = 0; k < HH; k++) s += eW2[i * HH + k] * nW1b[k * HH + j];
    bf16 hi = __float2bfloat16(s);
    bf16 lo = __float2bfloat16(s - __bfloat162float(hi));
    g_BWme_h[j * HH + i] = hi;
    g_BWme_l[j * HH + i] = lo;
    if (i == 0) {
        float t = 0.f;
        for (int k = 0; k < HH; k++) t += eb2[k] * nW1b[k * HH + j];
        g_bme[j] = t;
    }
}

__global__ void embed_kernel(const float* __restrict__ h0, const float* __restrict__ W,
                             const float* __restrict__ b) {
    int row = blockIdx.x * 2 + (threadIdx.x >> 7);
    int j = threadIdx.x & 127;
    if (row >= NN) return;
    float s = b[j];
#pragma unroll
    for (int k = 0; k < PP; k++) s += h0[row * PP + k] * W[k * HH + j];
    g_h[row * HH + j] = s;
}

// ---------------- shared MMA machinery ---------------------------------------
#define NM_ST 272                 // bf16 row stride in bytes (136 elems)
#define NM_A_HI 0
#define NM_A_LO 34816
#define NM_B_HI 69632
#define NM_B_LO 104448
#define NM_MISC 139264
#define NM_SMEM (NM_MISC + 4096)

// stage transposed-weight matrix (hi/lo) into B smem
__device__ __forceinline__ void stage_B(char* B_hi, char* B_lo, const bf16* Bh,
                                        const bf16* Bl, int tid) {
    for (int idx = tid; idx < 8192; idx += 256) {
        int n = idx >> 6, kp = idx & 63;
        int off = n * NM_ST + kp * 4;
        *(uint32_t*)(B_hi + off) = ((const uint32_t*)Bh)[idx];
        *(uint32_t*)(B_lo + off) = ((const uint32_t*)Bl)[idx];
    }
}
// stage fp32 A tile -> hi/lo bf16 smem
__device__ __forceinline__ void stage_A(char* A_hi, char* A_lo, const float* A,
                                        int m0, int tid) {
    for (int idx = tid; idx < 128 * 32; idx += 256) {
        int r = idx >> 5, c4 = (idx & 31) << 2;
        int gr = m0 + r;
        float4 v = (gr < NN) ? *(const float4*)&A[gr * HH + c4]
                             : make_float4(0.f, 0.f, 0.f, 0.f);
        uint2 hv, lv;
        hilo4(v.x, v.y, v.z, v.w, hv, lv);
        int off = r * NM_ST + c4 * 2;
        *(uint2*)(A_hi + off) = hv;
        *(uint2*)(A_lo + off) = lv;
    }
}
// preload this warp's B fragments (16 cols)
__device__ __forceinline__ void preload_B(uint32_t bh[2][8][2], uint32_t bl[2][8][2],
                                          uint32_t bhs, uint32_t bls, int wid, int lane) {
    int roff = (lane & 7) * NM_ST + ((lane >> 3) & 1) * 16;
#pragma unroll
    for (int nt = 0; nt < 2; nt++)
#pragma unroll
        for (int k = 0; k < 8; k++) {
            uint32_t a = (wid * 16 + nt * 8) * NM_ST + k * 32 + roff;
            ldmx2(bh[nt][k][0], bh[nt][k][1], bhs + a);
            ldmx2(bl[nt][k][0], bl[nt][k][1], bls + a);
        }
}
// run mma over all 8 m-tiles, accumulating into acc
__device__ __forceinline__ void mma_all(float acc[8][2][4], uint32_t ah_base, uint32_t al_base,
                                        uint32_t bh[2][8][2], uint32_t bl[2][8][2], int lane) {
    int aroff = (lane & 15) * NM_ST + ((lane >> 4) & 1) * 16;
#pragma unroll
    for (int m = 0; m < 8; m++) {
#pragma unroll
        for (int k = 0; k < 8; k++) {
            uint32_t a = (m * 16) * NM_ST + k * 32 + aroff;
            uint32_t ahf[4], alf[4];
            ldmx4(ahf, ah_base + a);
            ldmx4(alf, al_base + a);
#pragma unroll
            for (int nt = 0; nt < 2; nt++) {
                mma_bf16(acc[m][nt], ahf, bh[nt][k][0], bh[nt][k][1]);
                mma_bf16(acc[m][nt], ahf, bl[nt][k][0], bl[nt][k][1]);
                mma_bf16(acc[m][nt], alf, bh[nt][k][0], bh[nt][k][1]);
            }
        }
    }
}
#define ZERO_ACC(acc) \
    _Pragma("unroll") for (int m = 0; m < 8; m++) \
    _Pragma("unroll") for (int nt = 0; nt < 2; nt++) \
    _Pragma("unroll") for (int q = 0; q < 4; q++) acc[m][nt][q] = 0.f;

// ---------------- m1/m2 dual-output GEMM -------------------------------------
__global__ void __launch_bounds__(256)
node_mma_m12(const float* __restrict__ A) {
    extern __shared__ char smc[];
    char* A_hi = smc + NM_A_HI;
    char* A_lo = smc + NM_A_LO;
    char* B_hi = smc + NM_B_HI;
    char* B_lo = smc + NM_B_LO;
    const int tid = threadIdx.x;
    const int wid = tid >> 5, lane = tid & 31;
    const int m0 = blockIdx.x * 128;

    const uint32_t ah_base = smem_u32(A_hi), al_base = smem_u32(A_lo);
    const uint32_t bhs = smem_u32(B_hi), bls = smem_u32(B_lo);

    stage_A(A_hi, A_lo, A, m0, tid);
    stage_B(B_hi, B_lo, g_BeW1a_h, g_BeW1a_l, tid);
    __syncthreads();

    uint32_t bh[2][8][2], bl[2][8][2];
    float acc[8][2][4];
    for (int s = 0; s < 2; s++) {
        preload_B(bh, bl, bhs, bls, wid, lane);
        ZERO_ACC(acc);
        mma_all(acc, ah_base, al_base, bh, bl, lane);
        float* C = s ? g_m2 : g_m1;
#pragma unroll
        for (int m = 0; m < 8; m++) {
            int r0 = m0 + m * 16 + (lane >> 2);
            int r1 = r0 + 8;
#pragma unroll
            for (int nt = 0; nt < 2; nt++) {
                int n = wid * 16 + nt * 8 + (lane & 3) * 2;
                if (r0 < NN) *(float2*)&C[r0 * HH + n] = make_float2(acc[m][nt][0], acc[m][nt][1]);
                if (r1 < NN) *(float2*)&C[r1 * HH + n] = make_float2(acc[m][nt][2], acc[m][nt][3]);
            }
        }
        if (s == 0) {
            __syncthreads();   // all warps past preload_B of source 0
            stage_B(B_hi, B_lo, g_BeW1b_h, g_BeW1b_l, tid);
            __syncthreads();
        }
    }
}

// ---------------- fused t-GEMM + h-GEMM --------------------------------------
// t = relu(h@nW1a + macc@Wme + nb1 + cnt*bme)   (t kept in SMEM as hi/lo bf16)
// hdst = h + t@nW2 + nb2
__global__ void __launch_bounds__(256)
node_mma_th(const float* __restrict__ Ah, const float* __restrict__ Amacc,
            const float* __restrict__ nb1, const float* __restrict__ nb2,
            float* __restrict__ hdst) {
    extern __shared__ char smc[];
    char* A_hi = smc + NM_A_HI;
    char* A_lo = smc + NM_A_LO;
    char* B_hi = smc + NM_B_HI;
    char* B_lo = smc + NM_B_LO;
    float* bs  = (float*)(smc + NM_MISC);   // 128: nb1
    float* bs2 = bs + 128;                  // 128: bme
    const int tid = threadIdx.x;
    const int wid = tid >> 5, lane = tid & 31;
    const int m0 = blockIdx.x * 128;

    const uint32_t ah_base = smem_u32(A_hi), al_base = smem_u32(A_lo);
    const uint32_t bhs = smem_u32(B_hi), bls = smem_u32(B_lo);

    if (tid < 128) { bs[tid] = nb1[tid]; bs2[tid] = g_bme[tid]; }

    uint32_t bh[2][8][2], bl[2][8][2];
    float acc[8][2][4];
    ZERO_ACC(acc);

    // phase A source 0: h @ nW1a
    stage_A(A_hi, A_lo, Ah, m0, tid);
    stage_B(B_hi, B_lo, g_BnW1a_h, g_BnW1a_l, tid);
    __syncthreads();
    preload_B(bh, bl, bhs, bls, wid, lane);
    mma_all(acc, ah_base, al_base, bh, bl, lane);
    __syncthreads();
    // phase A source 1: macc @ Wme
    stage_A(A_hi, A_lo, Amacc, m0, tid);
    stage_B(B_hi, B_lo, g_BWme_h, g_BWme_l, tid);
    __syncthreads();
    preload_B(bh, bl, bhs, bls, wid, lane);
    mma_all(acc, ah_base, al_base, bh, bl, lane);
    __syncthreads();

    // write T = relu(acc + nb1 + cnt*bme) into A smem as hi/lo
#pragma unroll
    for (int m = 0; m < 8; m++) {
        int r0l = m * 16 + (lane >> 2);
        int r1l = r0l + 8;
        int r0 = m0 + r0l, r1 = m0 + r1l;
        float cm0 = (r0 < NN) ? (float)g_cnt[r0] : 0.f;
        float cm1 = (r1 < NN) ? (float)g_cnt[r1] : 0.f;
#pragma unroll
        for (int nt = 0; nt < 2; nt++) {
            int n = wid * 16 + nt * 8 + (lane & 3) * 2;
            float o0 = fmaxf(acc[m][nt][0] + bs[n] + cm0 * bs2[n], 0.f);
            float o1 = fmaxf(acc[m][nt][1] + bs[n + 1] + cm0 * bs2[n + 1], 0.f);
            float o2 = fmaxf(acc[m][nt][2] + bs[n] + cm1 * bs2[n], 0.f);
            float o3 = fmaxf(acc[m][nt][3] + bs[n + 1] + cm1 * bs2[n + 1], 0.f);
            uint32_t hv, lv;
            hilo2(o0, o1, hv, lv);
            *(uint32_t*)(A_hi + r0l * NM_ST + n * 2) = hv;
            *(uint32_t*)(A_lo + r0l * NM_ST + n * 2) = lv;
            hilo2(o2, o3, hv, lv);
            *(uint32_t*)(A_hi + r1l * NM_ST + n * 2) = hv;
            *(uint32_t*)(A_lo + r1l * NM_ST + n * 2) = lv;
        }
    }
    stage_B(B_hi, B_lo, g_BnW2_h, g_BnW2_l, tid);
    __syncthreads();

    // phase B: hdst = h + T @ nW2 + nb2
    preload_B(bh, bl, bhs, bls, wid, lane);
    ZERO_ACC(acc);
    mma_all(acc, ah_base, al_base, bh, bl, lane);

#pragma unroll
    for (int m = 0; m < 8; m++) {
        int r0 = m0 + m * 16 + (lane >> 2);
        int r1 = r0 + 8;
#pragma unroll
        for (int nt = 0; nt < 2; nt++) {
            int n = wid * 16 + nt * 8 + (lane & 3) * 2;
            float b0 = __ldg(&nb2[n]), b1 = __ldg(&nb2[n + 1]);
            if (r0 < NN) {
                float2 rv = *(const float2*)&Ah[r0 * HH + n];
                *(float2*)&hdst[r0 * HH + n] =
                    make_float2(acc[m][nt][0] + b0 + rv.x, acc[m][nt][1] + b1 + rv.y);
            }
            if (r1 < NN) {
                float2 rv = *(const float2*)&Ah[r1 * HH + n];
                *(float2*)&hdst[r1 * HH + n] =
                    make_float2(acc[m][nt][2] + b0 + rv.x, acc[m][nt][3] + b1 + rv.y);
            }
        }
    }
}

// ---------------- fused vW1-GEMM + v epilogue --------------------------------
// t2 = relu(h@vW1+vb1); v = t2@vW2 + vb2 + scat/denom; normalize; write outv
__global__ void __launch_bounds__(256)
node_mma_v(const float* __restrict__ A, const float* __restrict__ vb1,
           const float* __restrict__ vW2, const float* __restrict__ vb2,
           float* __restrict__ outv) {
    extern __shared__ char smc[];
    char* A_hi = smc + NM_A_HI;
    char* A_lo = smc + NM_A_LO;
    char* B_hi = smc + NM_B_HI;
    char* B_lo = smc + NM_B_LO;
    float* bs = (float*)(smc + NM_MISC);   // 128: vb1
    float* w2 = bs + 128;                  // 256: vW2
    float* vp = w2 + 256;                  // 256: per-row v partials
    const int tid = threadIdx.x;
    const int wid = tid >> 5, lane = tid & 31;
    const int m0 = blockIdx.x * 128;

    const uint32_t ah_base = smem_u32(A_hi), al_base = smem_u32(A_lo);
    const uint32_t bhs = smem_u32(B_hi), bls = smem_u32(B_lo);

    if (tid < 128) bs[tid] = vb1[tid];
    if (tid < 256) { w2[tid] = vW2[tid]; vp[tid] = 0.f; }

    stage_A(A_hi, A_lo, A, m0, tid);
    stage_B(B_hi, B_lo, g_BvW1_h, g_BvW1_l, tid);
    __syncthreads();

    uint32_t bh[2][8][2], bl[2][8][2];
    preload_B(bh, bl, bhs, bls, wid, lane);
    float acc[8][2][4];
    ZERO_ACC(acc);
    mma_all(acc, ah_base, al_base, bh, bl, lane);

#pragma unroll
    for (int m = 0; m < 8; m++) {
        int r0l = m * 16 + (lane >> 2);
        int r1l = r0l + 8;
        float c00 = 0.f, c01 = 0.f, c10 = 0.f, c11 = 0.f;
#pragma unroll
        for (int nt = 0; nt < 2; nt++) {
            int n = wid * 16 + nt * 8 + (lane & 3) * 2;
            float o0 = fmaxf(acc[m][nt][0] + bs[n], 0.f);
            float o1 = fmaxf(acc[m][nt][1] + bs[n + 1], 0.f);
            float o2 = fmaxf(acc[m][nt][2] + bs[n], 0.f);
            float o3 = fmaxf(acc[m][nt][3] + bs[n + 1], 0.f);
            c00 += o0 * w2[n * 2 + 0] + o1 * w2[(n + 1) * 2 + 0];
            c01 += o0 * w2[n * 2 + 1] + o1 * w2[(n + 1) * 2 + 1];
            c10 += o2 * w2[n * 2 + 0] + o3 * w2[(n + 1) * 2 + 0];
            c11 += o2 * w2[n * 2 + 1] + o3 * w2[(n + 1) * 2 + 1];
        }
        // reduce over lane&3 (same row, different n groups)
        c00 += __shfl_xor_sync(0xffffffffu, c00, 1);
        c00 += __shfl_xor_sync(0xffffffffu, c00, 2);
        c01 += __shfl_xor_sync(0xffffffffu, c01, 1);
        c01 += __shfl_xor_sync(0xffffffffu, c01, 2);
        c10 += __shfl_xor_sync(0xffffffffu, c10, 1);
        c10 += __shfl_xor_sync(0xffffffffu, c10, 2);
        c11 += __shfl_xor_sync(0xffffffffu, c11, 1);
        c11 += __shfl_xor_sync(0xffffffffu, c11, 2);
        if ((lane & 3) == 0) {
            atomicAdd(&vp[2 * r0l + 0], c00);
            atomicAdd(&vp[2 * r0l + 1], c01);
            atomicAdd(&vp[2 * r1l + 0], c10);
            atomicAdd(&vp[2 * r1l + 1], c11);
        }
    }
    __syncthreads();
    if (tid < 128) {
        int row = m0 + tid;
        if (row < NN) {
            float d = fmaxf((float)g_cnt[row], 1.f);
            float v0 = vp[2 * tid] + vb2[0] + g_scat[2 * row] / d;
            float v1 = vp[2 * tid + 1] + vb2[1] + g_scat[2 * row + 1] / d;
            float n = fmaxf(sqrtf(v0 * v0 + v1 * v1), 1e-12f);
            outv[2 * row] = v0 / n;
            outv[2 * row + 1] = v1 / n;
        }
    }
}

// ---------------- macc gather: one warp per node (no atomics) ----------------
__global__ void macc_gather_kernel(const float* __restrict__ x,
                                   const float* __restrict__ eW1,
                                   const float* __restrict__ eb1) {
    int warp = (blockIdx.x * blockDim.x + threadIdx.x) >> 5;
    int lane = threadIdx.x & 31;
    if (warp >= NN) return;
    int r = warp;
    int j = lane << 2;
    float4 m1v = *(const float4*)&g_m1[r * HH + j];
    float4 wd  = *(const float4*)&eW1[256 * HH + j];
    float4 b1  = *(const float4*)&eb1[j];
    float2 xr  = *(const float2*)&x[2 * r];
    float4 acc = make_float4(0.f, 0.f, 0.f, 0.f);
    int s = g_off[r], e = g_off[r + 1];
    for (int idx = s; idx < e; idx++) {
        int c = __ldg(&g_cols[idx]);
        float2 xc = *(const float2*)&x[2 * c];
        float dx = xr.x - xc.x, dy = xr.y - xc.y;
        float rd = dx * dx + dy * dy;
        float4 m2v = *(const float4*)&g_m2[c * HH + j];
        acc.x += fmaxf(m1v.x + m2v.x + rd * wd.x + b1.x, 0.f);
        acc.y += fmaxf(m1v.y + m2v.y + rd * wd.y + b1.y, 0.f);
        acc.z += fmaxf(m1v.z + m2v.z + rd * wd.z + b1.z, 0.f);
        acc.w += fmaxf(m1v.w + m2v.w + rd * wd.w + b1.w, 0.f);
    }
    *(float4*)&g_macc[r * HH + j] = acc;
}

// ---------------- coord kernel (layer 2 only, mma.sync) ----------------------
#define EK2_ASTRIDE 272
#define EK2_A_HI 0
#define EK2_A_LO 34816
#define EK2_MISC 69632
#define EK2_SMEM (EK2_MISC + 5120)

__global__ void __launch_bounds__(256)
edge2_kernel(const float* __restrict__ x,
             const float* __restrict__ eW1, const float* __restrict__ eb1,
             const float* __restrict__ cW2, const float* __restrict__ cb2) {
    extern __shared__ char smc[];
    char* A_hi = smc + EK2_A_HI;
    char* A_lo = smc + EK2_A_LO;
    float* misc   = (float*)(smc + EK2_MISC);
    float* wd_s   = misc;
    float* b1_s   = misc + 128;
    float* bc_s   = misc + 256;
    float* cw2_s  = misc + 384;
    float* p2a_s  = misc + 512;
    float* p2b_s  = misc + 640;
    float* rd_s   = misc + 768;
    float* coordp = misc + 896;
    int* row_s = (int*)(misc + 1024);
    int* col_s = (int*)(misc + 1152);

    const int tid = threadIdx.x;
    const int wid = tid >> 5, lane = tid & 31;

    if (tid < 128) {
        wd_s[tid]  = eW1[256 * HH + tid];
        b1_s[tid]  = eb1[tid];
        bc_s[tid]  = g_bc[tid];
        cw2_s[tid] = cW2[tid];
        coordp[tid] = 0.f;
        int eg = blockIdx.x * 128 + tid;
        int r = g_rows[eg], c = g_cols[eg];
        row_s[tid] = r; col_s[tid] = c;
        float2 xr = *(const float2*)&x[2 * r];
        float2 xc = *(const float2*)&x[2 * c];
        float dx = xr.x - xc.x, dy = xr.y - xc.y;
        rd_s[tid]  = dx * dx + dy * dy;
        p2a_s[tid] = dx * dx - dy * dy;
        p2b_s[tid] = 2.f * dx * dy;
    }
    for (int idx = tid; idx < 8192; idx += 256) {
        int n = idx >> 6, kp = idx & 63;
        uint32_t vh = ((const uint32_t*)g_Bhi)[idx];
        uint32_t vl = ((const uint32_t*)g_Blo)[idx];
        int off = n * EK2_ASTRIDE + kp * 4;
        *(uint32_t*)(A_hi + off) = vh;
        *(uint32_t*)(A_lo + off) = vl;
    }
    __syncthreads();

    uint32_t bh[2][8][2], bl[2][8][2];
    {
        uint32_t hbase = smem_u32(A_hi);
        uint32_t lbase = smem_u32(A_lo);
        int roff = (lane & 7) * EK2_ASTRIDE + ((lane >> 3) & 1) * 16;
#pragma unroll
        for (int nt = 0; nt < 2; nt++)
#pragma unroll
            for (int k = 0; k < 8; k++) {
                uint32_t a = (wid * 16 + nt * 8) * EK2_ASTRIDE + k * 32 + roff;
                ldmx2(bh[nt][k][0], bh[nt][k][1], hbase + a);
                ldmx2(bl[nt][k][0], bl[nt][k][1], lbase + a);
            }
    }
    __syncthreads();

    // phase 1: preact, write A tiles
#pragma unroll
    for (int s = 0; s < 16; s++) {
        int item = tid + s * 256;
        int e = item >> 5, j = (item & 31) << 2;
        int r = row_s[e], c = col_s[e];
        float rd = rd_s[e];
        float4 a  = *(const float4*)&g_m1[r * HH + j];
        float4 b  = *(const float4*)&g_m2[c * HH + j];
        float4 w  = *(const float4*)&wd_s[j];
        float4 bb = *(const float4*)&b1_s[j];
        float v0 = fmaxf(a.x + b.x + rd * w.x + bb.x, 0.f);
        float v1 = fmaxf(a.y + b.y + rd * w.y + bb.y, 0.f);
        float v2 = fmaxf(a.z + b.z + rd * w.z + bb.z, 0.f);
        float v3 = fmaxf(a.w + b.w + rd * w.w + bb.w, 0.f);
        uint2 hv, lv;
        hilo4(v0, v1, v2, v3, hv, lv);
        int off = e * EK2_ASTRIDE + j * 2;
        *(uint2*)(A_hi + off) = hv;
        *(uint2*)(A_lo + off) = lv;
    }
    __syncthreads();

    // phase 2: C = A @ Wc via mma, fused coord dot + scatter
    {
        uint32_t hbase = smem_u32(A_hi);
        uint32_t lbase = smem_u32(A_lo);
        int aroff = (lane & 15) * EK2_ASTRIDE + ((lane >> 4) & 1) * 16;
#pragma unroll
        for (int m = 0; m < 8; m++) {
            float acc[2][4];
#pragma unroll
            for (int nt = 0; nt < 2; nt++)
#pragma unroll
                for (int q = 0; q < 4; q++) acc[nt][q] = 0.f;
#pragma unroll
            for (int k = 0; k < 8; k++) {
                uint32_t a = (m * 16) * EK2_ASTRIDE + k * 32 + aroff;
                uint32_t ah[4], al[4];
                ldmx4(ah, hbase + a);
                ldmx4(al, lbase + a);
#pragma unroll
                for (int nt = 0; nt < 2; nt++) {
                    mma_bf16(acc[nt], ah, bh[nt][k][0], bh[nt][k][1]);
                    mma_bf16(acc[nt], ah, bl[nt][k][0], bl[nt][k][1]);
                    mma_bf16(acc[nt], al, bh[nt][k][0], bh[nt][k][1]);
                }
            }
            int r0 = m * 16 + (lane >> 2);
            float p0 = 0.f, p1 = 0.f;
#pragma unroll
            for (int nt = 0; nt < 2; nt++) {
                int n = wid * 16 + nt * 8 + (lane & 3) * 2;
                p0 += fmaxf(acc[nt][0] + bc_s[n], 0.f) * cw2_s[n]
                    + fmaxf(acc[nt][1] + bc_s[n + 1], 0.f) * cw2_s[n + 1];
                p1 += fmaxf(acc[nt][2] + bc_s[n], 0.f) * cw2_s[n]
                    + fmaxf(acc[nt][3] + bc_s[n + 1], 0.f) * cw2_s[n + 1];
            }
            p0 += __shfl_xor_sync(0xffffffffu, p0, 1);
            p0 += __shfl_xor_sync(0xffffffffu, p0, 2);
            p1 += __shfl_xor_sync(0xffffffffu, p1, 1);
            p1 += __shfl_xor_sync(0xffffffffu, p1, 2);
            if ((lane & 3) == 0) {
                atomicAdd(&coordp[r0], p0);
                atomicAdd(&coordp[r0 + 8], p1);
            }
        }
    }
    __syncthreads();
    if (tid < 128) {
        float csum = coordp[tid] + cb2[0];
        red_add_v2(&g_scat[2 * row_s[tid]], p2a_s[tid] * csum, p2b_s[tid] * csum);
    }
}

__global__ void copy_x_kernel(const float* __restrict__ x, float* __restrict__ outx) {
    int i = blockIdx.x * blockDim.x + threadIdx.x;
    if (i < NN * 2) outx[i] = x[i];
}

// ---------------- launcher ---------------------------------------------------
extern "C" void kernel_launch(void* const* d_in, const int* in_sizes, int n_in,
                              void* d_out, int out_size) {
    const float* h0   = (const float*)d_in[0];
    const float* x    = (const float*)d_in[1];
    const int*   ei   = (const int*)d_in[2];
    const float* embW = (const float*)d_in[3];
    const float* embB = (const float*)d_in[4];
    const float* eW1  = (const float*)d_in[5];
    const float* eb1  = (const float*)d_in[6];
    const float* eW2  = (const float*)d_in[7];
    const float* eb2  = (const float*)d_in[8];
    const float* nW1  = (const float*)d_in[9];
    const float* nb1  = (const float*)d_in[10];
    const float* nW2  = (const float*)d_in[11];
    const float* nb2  = (const float*)d_in[12];
    const float* vW1  = (const float*)d_in[13];
    const float* vb1  = (const float*)d_in[14];
    const float* vW2  = (const float*)d_in[15];
    const float* vb2  = (const float*)d_in[16];
    const float* cW1  = (const float*)d_in[17];
    const float* cb1  = (const float*)d_in[18];
    const float* cW2  = (const float*)d_in[19];
    const float* cb2  = (const float*)d_in[20];

    float* out   = (float*)d_out;
    float* out_h = out;
    float* out_x = out + NN * HH;
    float* out_v = out + NN * HH + NN * 2;

    float *p_h, *p_macc;
    cudaGetSymbolAddress((void**)&p_h,    g_h);
    cudaGetSymbolAddress((void**)&p_macc, g_macc);

    bf16 *b_eW1a_h, *b_eW1a_l, *b_eW1b_h, *b_eW1b_l, *b_nW1a_h, *b_nW1a_l;
    bf16 *b_nW2_h, *b_nW2_l, *b_vW1_h, *b_vW1_l;
    cudaGetSymbolAddress((void**)&b_eW1a_h, g_BeW1a_h);
    cudaGetSymbolAddress((void**)&b_eW1a_l, g_BeW1a_l);
    cudaGetSymbolAddress((void**)&b_eW1b_h, g_BeW1b_h);
    cudaGetSymbolAddress((void**)&b_eW1b_l, g_BeW1b_l);
    cudaGetSymbolAddress((void**)&b_nW1a_h, g_BnW1a_h);
    cudaGetSymbolAddress((void**)&b_nW1a_l, g_BnW1a_l);
    cudaGetSymbolAddress((void**)&b_nW2_h,  g_BnW2_h);
    cudaGetSymbolAddress((void**)&b_nW2_l,  g_BnW2_l);
    cudaGetSymbolAddress((void**)&b_vW1_h,  g_BvW1_h);
    cudaGetSymbolAddress((void**)&b_vW1_l,  g_BvW1_l);

    cudaFuncSetAttribute(node_mma_m12, cudaFuncAttributeMaxDynamicSharedMemorySize, NM_SMEM);
    cudaFuncSetAttribute(node_mma_th, cudaFuncAttributeMaxDynamicSharedMemorySize, NM_SMEM);
    cudaFuncSetAttribute(node_mma_v, cudaFuncAttributeMaxDynamicSharedMemorySize, NM_SMEM);
    cudaFuncSetAttribute(edge2_kernel, cudaFuncAttributeMaxDynamicSharedMemorySize, EK2_SMEM);

    const int GB = (NN + 127) / 128;

    // sort pipeline
    zero_cnt_scat_kernel<<<(NN * 2 + 255) / 256, 256>>>();
    count_kernel<<<(EE + 255) / 256, 256>>>(ei);
    scan1_kernel<<<SCAN_B, 256>>>();
    scan2_kernel<<<1, 256>>>();
    scan3_kernel<<<SCAN_B, 256>>>();
    scatter_kernel<<<(EE + 255) / 256, 256>>>(ei);

    // weight prep
    prep_wc_kernel<<<128, 128>>>(eW2, cW1, eb2, cb1);
    prep_wme_kernel<<<128, 128>>>(eW2, nW1 + 128 * HH, eb2);
    prep_bt_kernel<<<128, 128>>>(eW1, b_eW1a_h, b_eW1a_l);
    prep_bt_kernel<<<128, 128>>>(eW1 + 128 * HH, b_eW1b_h, b_eW1b_l);
    prep_bt_kernel<<<128, 128>>>(nW1, b_nW1a_h, b_nW1a_l);
    prep_bt_kernel<<<128, 128>>>(nW2, b_nW2_h, b_nW2_l);
    prep_bt_kernel<<<128, 128>>>(vW1, b_vW1_h, b_vW1_l);
    embed_kernel<<<NN / 2, 256>>>(h0, embW, embB);

    for (int layer = 0; layer < 2; layer++) {
        node_mma_m12<<<GB, 256, NM_SMEM>>>(p_h);
        macc_gather_kernel<<<(NN * 32 + 255) / 256, 256>>>(x, eW1, eb1);
        if (layer == 1)
            edge2_kernel<<<EE / 128, 256, EK2_SMEM>>>(x, eW1, eb1, cW2, cb2);
        float* hdst = (layer == 1) ? out_h : p_h;
        node_mma_th<<<GB, 256, NM_SMEM>>>(p_h, p_macc, nb1, nb2, hdst);
    }

    node_mma_v<<<GB, 256, NM_SMEM>>>(out_h, vb1, vW2, vb2, out_v);
    copy_x_kernel<<<(NN * 2 + 255) / 256, 256>>>(x, out_x);
}

// round 12
// speedup vs baseline: 4.1447x; 1.0463x over previous
#include <cuda_runtime.h>
#include <cuda_bf16.h>
#include <cstdint>

#define NN 50000
#define EE 800000
#define HH 128
#define PP 16
#define SCAN_B 196   // ceil(NN/256)

typedef __nv_bfloat16 bf16;

// ---------------- scratch (device globals; no allocation allowed) -----------
__device__ float g_h[NN * HH];
__device__ float g_m1[NN * HH];
__device__ float g_m2[NN * HH];
__device__ float g_macc[NN * HH];
__device__ float g_scat[NN * 2];
__device__ int   g_cnt[NN];
__device__ int   g_off[NN + 1];
__device__ int   g_cur[NN];
__device__ int   g_bsum[SCAN_B];
__device__ int   g_rows[EE];
__device__ int   g_cols[EE];
__device__ float g_bc[HH];
__device__ float g_bme[HH];
// transposed bf16 hi/lo weights: B[n][k] = W[k][n]
__device__ bf16 g_Bhi[HH * HH];      // Wc (coord)
__device__ bf16 g_Blo[HH * HH];
__device__ bf16 g_BeW1a_h[HH * HH], g_BeW1a_l[HH * HH];
__device__ bf16 g_BeW1b_h[HH * HH], g_BeW1b_l[HH * HH];
__device__ bf16 g_BnW1a_h[HH * HH], g_BnW1a_l[HH * HH];
__device__ bf16 g_BnW2_h[HH * HH],  g_BnW2_l[HH * HH];
__device__ bf16 g_BvW1_h[HH * HH],  g_BvW1_l[HH * HH];
__device__ bf16 g_BWme_h[HH * HH],  g_BWme_l[HH * HH];

// ---------------- PTX helpers ------------------------------------------------
__device__ __forceinline__ void red_add_v2(float* p, float a, float b) {
    asm volatile("red.global.add.v2.f32 [%0], {%1,%2};"
                 :: "l"(p), "f"(a), "f"(b) : "memory");
}
__device__ __forceinline__ uint32_t smem_u32(const void* p) {
    uint32_t a;
    asm("{ .reg .u64 t; cvta.to.shared.u64 t, %1; cvt.u32.u64 %0, t; }" : "=r"(a) : "l"(p));
    return a;
}
__device__ __forceinline__ void ldmx4(uint32_t* r, uint32_t a) {
    asm volatile("ldmatrix.sync.aligned.m8n8.x4.shared.b16 {%0,%1,%2,%3}, [%4];"
                 : "=r"(r[0]), "=r"(r[1]), "=r"(r[2]), "=r"(r[3]) : "r"(a));
}
__device__ __forceinline__ void ldmx2(uint32_t& r0, uint32_t& r1, uint32_t a) {
    asm volatile("ldmatrix.sync.aligned.m8n8.x2.shared.b16 {%0,%1}, [%2];"
                 : "=r"(r0), "=r"(r1) : "r"(a));
}
__device__ __forceinline__ void mma_bf16(float* c, const uint32_t* a, uint32_t b0, uint32_t b1) {
    asm volatile(
        "mma.sync.aligned.m16n8k16.row.col.f32.bf16.bf16.f32 "
        "{%0,%1,%2,%3}, {%4,%5,%6,%7}, {%8,%9}, {%0,%1,%2,%3};"
        : "+f"(c[0]), "+f"(c[1]), "+f"(c[2]), "+f"(c[3])
        : "r"(a[0]), "r"(a[1]), "r"(a[2]), "r"(a[3]), "r"(b0), "r"(b1));
}
__device__ __forceinline__ void hilo4(float v0, float v1, float v2, float v3,
                                      uint2& hv, uint2& lv) {
    bf16 h0 = __float2bfloat16(v0), h1 = __float2bfloat16(v1);
    bf16 h2 = __float2bfloat16(v2), h3 = __float2bfloat16(v3);
    bf16 l0 = __float2bfloat16(v0 - __bfloat162float(h0));
    bf16 l1 = __float2bfloat16(v1 - __bfloat162float(h1));
    bf16 l2 = __float2bfloat16(v2 - __bfloat162float(h2));
    bf16 l3 = __float2bfloat16(v3 - __bfloat162float(h3));
    hv.x = ((uint32_t)__bfloat16_as_ushort(h1) << 16) | __bfloat16_as_ushort(h0);
    hv.y = ((uint32_t)__bfloat16_as_ushort(h3) << 16) | __bfloat16_as_ushort(h2);
    lv.x = ((uint32_t)__bfloat16_as_ushort(l1) << 16) | __bfloat16_as_ushort(l0);
    lv.y = ((uint32_t)__bfloat16_as_ushort(l3) << 16) | __bfloat16_as_ushort(l2);
}
__device__ __forceinline__ void hilo2(float a, float b, uint32_t& h, uint32_t& l) {
    bf16 ha = __float2bfloat16(a), hb = __float2bfloat16(b);
    bf16 la = __float2bfloat16(a - __bfloat162float(ha));
    bf16 lb = __float2bfloat16(b - __bfloat162float(hb));
    h = ((uint32_t)__bfloat16_as_ushort(hb) << 16) | __bfloat16_as_ushort(ha);
    l = ((uint32_t)__bfloat16_as_ushort(lb) << 16) | __bfloat16_as_ushort(la);
}

// ---------------- sort pipeline ----------------------------------------------
__global__ void zero_cnt_scat_kernel() {
    int i = blockIdx.x * blockDim.x + threadIdx.x;
    if (i < NN) g_cnt[i] = 0;
    if (i < NN * 2) g_scat[i] = 0.f;
}

__global__ void count_kernel(const int* __restrict__ ei) {
    int e = blockIdx.x * blockDim.x + threadIdx.x;
    if (e < EE) atomicAdd(&g_cnt[ei[e]], 1);
}

__global__ void scan1_kernel() {
    __shared__ int sm[256];
    int b = blockIdx.x, t = threadIdx.x, i = b * 256 + t;
    int v = (i < NN) ? g_cnt[i] : 0;
    sm[t] = v; __syncthreads();
    for (int o = 128; o; o >>= 1) {
        if (t < o) sm[t] += sm[t + o];
        __syncthreads();
    }
    if (t == 0) g_bsum[b] = sm[0];
}

__global__ void scan2_kernel() {
    __shared__ int sm[256];
    int t = threadIdx.x;
    int v = (t < SCAN_B) ? g_bsum[t] : 0;
    sm[t] = v; __syncthreads();
    for (int o = 1; o < 256; o <<= 1) {
        int add = (t >= o) ? sm[t - o] : 0;
        __syncthreads();
        sm[t] += add;
        __syncthreads();
    }
    if (t < SCAN_B) g_bsum[t] = sm[t] - v;
    if (t == 0) g_off[NN] = EE;
}

__global__ void scan3_kernel() {
    __shared__ int sm[256];
    int b = blockIdx.x, t = threadIdx.x, i = b * 256 + t;
    int v = (i < NN) ? g_cnt[i] : 0;
    sm[t] = v; __syncthreads();
    for (int o = 1; o < 256; o <<= 1) {
        int add = (t >= o) ? sm[t - o] : 0;
        __syncthreads();
        sm[t] += add;
        __syncthreads();
    }
    if (i < NN) {
        int off = g_bsum[b] + sm[t] - v;
        g_off[i] = off;
        g_cur[i] = off;
    }
}

__global__ void scatter_kernel(const int* __restrict__ ei) {
    int e = blockIdx.x * blockDim.x + threadIdx.x;
    if (e < EE) {
        int r = ei[e];
        int pos = atomicAdd(&g_cur[r], 1);
        g_rows[pos] = r;
        g_cols[pos] = ei[EE + e];
    }
}

// ---------------- merged weight-prep kernel -----------------------------------
// grid (128, 7), block 128
__global__ void prep_all_kernel(const float* __restrict__ eW1, const float* __restrict__ nW1,
                                const float* __restrict__ nW2, const float* __restrict__ vW1,
                                const float* __restrict__ eW2, const float* __restrict__ cW1,
                                const float* __restrict__ eb2, const float* __restrict__ cb1) {
    int i = blockIdx.x, j = threadIdx.x;
    int task = blockIdx.y;
    if (task < 5) {
        const float* W;
        bf16 *oh, *ol;
        switch (task) {
            case 0: W = eW1;            oh = g_BeW1a_h; ol = g_BeW1a_l; break;
            case 1: W = eW1 + 128 * HH; oh = g_BeW1b_h; ol = g_BeW1b_l; break;
            case 2: W = nW1;            oh = g_BnW1a_h; ol = g_BnW1a_l; break;
            case 3: W = nW2;            oh = g_BnW2_h;  ol = g_BnW2_l;  break;
            default: W = vW1;           oh = g_BvW1_h;  ol = g_BvW1_l;  break;
        }
        float s = W[i * HH + j];
        bf16 hi = __float2bfloat16(s);
        bf16 lo = __float2bfloat16(s - __bfloat162float(hi));
        oh[j * HH + i] = hi;
        ol[j * HH + i] = lo;
    } else if (task == 5) {
        // Wc = eW2 @ cW1; bc = eb2 @ cW1 + cb1
        float s = 0.f;
        for (int k = 0; k < HH; k++) s += eW2[i * HH + k] * cW1[k * HH + j];
        bf16 hi = __float2bfloat16(s);
        bf16 lo = __float2bfloat16(s - __bfloat162float(hi));
        g_Bhi[j * HH + i] = hi;
        g_Blo[j * HH + i] = lo;
        if (i == 0) {
            float t = 0.f;
            for (int k = 0; k < HH; k++) t += eb2[k] * cW1[k * HH + j];
            g_bc[j] = t + cb1[j];
        }
    } else {
        // Wme = eW2 @ nW1b; bme = eb2 @ nW1b
        const float* nW1b = nW1 + 128 * HH;
        float s = 0.f;
        for (int k = 0; k < HH; k++) s += eW2[i * HH + k] * nW1b[k * HH + j];
        bf16 hi = __float2bfloat16(s);
        bf16 lo = __float2bfloat16(s - __bfloat162float(hi));
        g_BWme_h[j * HH + i] = hi;
        g_BWme_l[j * HH + i] = lo;
        if (i == 0) {
            float t = 0.f;
            for (int k = 0; k < HH; k++) t += eb2[k] * nW1b[k * HH + j];
            g_bme[j] = t;
        }
    }
}

__global__ void embed_kernel(const float* __restrict__ h0, const float* __restrict__ W,
                             const float* __restrict__ b) {
    int row = blockIdx.x * 2 + (threadIdx.x >> 7);
    int j = threadIdx.x & 127;
    if (row >= NN) return;
    float s = b[j];
#pragma unroll
    for (int k = 0; k < PP; k++) s += h0[row * PP + k] * W[k * HH + j];
    g_h[row * HH + j] = s;
}

// ---------------- shared MMA machinery ---------------------------------------
#define NM_ST 272
#define NM_A_HI 0
#define NM_A_LO 34816
#define NM_B_HI 69632
#define NM_B_LO 104448
#define NM_MISC 139264
#define NM_SMEM (NM_MISC + 4096)

__device__ __forceinline__ void stage_B(char* B_hi, char* B_lo, const bf16* Bh,
                                        const bf16* Bl, int tid) {
    for (int idx = tid; idx < 8192; idx += 256) {
        int n = idx >> 6, kp = idx & 63;
        int off = n * NM_ST + kp * 4;
        *(uint32_t*)(B_hi + off) = ((const uint32_t*)Bh)[idx];
        *(uint32_t*)(B_lo + off) = ((const uint32_t*)Bl)[idx];
    }
}
__device__ __forceinline__ void stage_A(char* A_hi, char* A_lo, const float* A,
                                        int m0, int tid) {
    for (int idx = tid; idx < 128 * 32; idx += 256) {
        int r = idx >> 5, c4 = (idx & 31) << 2;
        int gr = m0 + r;
        float4 v = (gr < NN) ? *(const float4*)&A[gr * HH + c4]
                             : make_float4(0.f, 0.f, 0.f, 0.f);
        uint2 hv, lv;
        hilo4(v.x, v.y, v.z, v.w, hv, lv);
        int off = r * NM_ST + c4 * 2;
        *(uint2*)(A_hi + off) = hv;
        *(uint2*)(A_lo + off) = lv;
    }
}
__device__ __forceinline__ void preload_B(uint32_t bh[2][8][2], uint32_t bl[2][8][2],
                                          uint32_t bhs, uint32_t bls, int wid, int lane) {
    int roff = (lane & 7) * NM_ST + ((lane >> 3) & 1) * 16;
#pragma unroll
    for (int nt = 0; nt < 2; nt++)
#pragma unroll
        for (int k = 0; k < 8; k++) {
            uint32_t a = (wid * 16 + nt * 8) * NM_ST + k * 32 + roff;
            ldmx2(bh[nt][k][0], bh[nt][k][1], bhs + a);
            ldmx2(bl[nt][k][0], bl[nt][k][1], bls + a);
        }
}
__device__ __forceinline__ void mma_all(float acc[8][2][4], uint32_t ah_base, uint32_t al_base,
                                        uint32_t bh[2][8][2], uint32_t bl[2][8][2], int lane) {
    int aroff = (lane & 15) * NM_ST + ((lane >> 4) & 1) * 16;
#pragma unroll
    for (int m = 0; m < 8; m++) {
#pragma unroll
        for (int k = 0; k < 8; k++) {
            uint32_t a = (m * 16) * NM_ST + k * 32 + aroff;
            uint32_t ahf[4], alf[4];
            ldmx4(ahf, ah_base + a);
            ldmx4(alf, al_base + a);
#pragma unroll
            for (int nt = 0; nt < 2; nt++) {
                mma_bf16(acc[m][nt], ahf, bh[nt][k][0], bh[nt][k][1]);
                mma_bf16(acc[m][nt], ahf, bl[nt][k][0], bl[nt][k][1]);
                mma_bf16(acc[m][nt], alf, bh[nt][k][0], bh[nt][k][1]);
            }
        }
    }
}
#define ZERO_ACC(acc) \
    _Pragma("unroll") for (int m = 0; m < 8; m++) \
    _Pragma("unroll") for (int nt = 0; nt < 2; nt++) \
    _Pragma("unroll") for (int q = 0; q < 4; q++) acc[m][nt][q] = 0.f;

// ---------------- m1/m2 dual-output GEMM -------------------------------------
__global__ void __launch_bounds__(256)
node_mma_m12(const float* __restrict__ A) {
    extern __shared__ char smc[];
    char* A_hi = smc + NM_A_HI;
    char* A_lo = smc + NM_A_LO;
    char* B_hi = smc + NM_B_HI;
    char* B_lo = smc + NM_B_LO;
    const int tid = threadIdx.x;
    const int wid = tid >> 5, lane = tid & 31;
    const int m0 = blockIdx.x * 128;

    const uint32_t ah_base = smem_u32(A_hi), al_base = smem_u32(A_lo);
    const uint32_t bhs = smem_u32(B_hi), bls = smem_u32(B_lo);

    stage_A(A_hi, A_lo, A, m0, tid);
    stage_B(B_hi, B_lo, g_BeW1a_h, g_BeW1a_l, tid);
    __syncthreads();

    uint32_t bh[2][8][2], bl[2][8][2];
    float acc[8][2][4];
    for (int s = 0; s < 2; s++) {
        preload_B(bh, bl, bhs, bls, wid, lane);
        ZERO_ACC(acc);
        mma_all(acc, ah_base, al_base, bh, bl, lane);
        float* C = s ? g_m2 : g_m1;
#pragma unroll
        for (int m = 0; m < 8; m++) {
            int r0 = m0 + m * 16 + (lane >> 2);
            int r1 = r0 + 8;
#pragma unroll
            for (int nt = 0; nt < 2; nt++) {
                int n = wid * 16 + nt * 8 + (lane & 3) * 2;
                if (r0 < NN) *(float2*)&C[r0 * HH + n] = make_float2(acc[m][nt][0], acc[m][nt][1]);
                if (r1 < NN) *(float2*)&C[r1 * HH + n] = make_float2(acc[m][nt][2], acc[m][nt][3]);
            }
        }
        if (s == 0) {
            __syncthreads();
            stage_B(B_hi, B_lo, g_BeW1b_h, g_BeW1b_l, tid);
            __syncthreads();
        }
    }
}

// ---------------- fused t-GEMM + h-GEMM --------------------------------------
__global__ void __launch_bounds__(256)
node_mma_th(const float* __restrict__ Ah, const float* __restrict__ Amacc,
            const float* __restrict__ nb1, const float* __restrict__ nb2,
            float* __restrict__ hdst) {
    extern __shared__ char smc[];
    char* A_hi = smc + NM_A_HI;
    char* A_lo = smc + NM_A_LO;
    char* B_hi = smc + NM_B_HI;
    char* B_lo = smc + NM_B_LO;
    float* bs  = (float*)(smc + NM_MISC);
    float* bs2 = bs + 128;
    const int tid = threadIdx.x;
    const int wid = tid >> 5, lane = tid & 31;
    const int m0 = blockIdx.x * 128;

    const uint32_t ah_base = smem_u32(A_hi), al_base = smem_u32(A_lo);
    const uint32_t bhs = smem_u32(B_hi), bls = smem_u32(B_lo);

    if (tid < 128) { bs[tid] = nb1[tid]; bs2[tid] = g_bme[tid]; }

    uint32_t bh[2][8][2], bl[2][8][2];
    float acc[8][2][4];
    ZERO_ACC(acc);

    stage_A(A_hi, A_lo, Ah, m0, tid);
    stage_B(B_hi, B_lo, g_BnW1a_h, g_BnW1a_l, tid);
    __syncthreads();
    preload_B(bh, bl, bhs, bls, wid, lane);
    mma_all(acc, ah_base, al_base, bh, bl, lane);
    __syncthreads();
    stage_A(A_hi, A_lo, Amacc, m0, tid);
    stage_B(B_hi, B_lo, g_BWme_h, g_BWme_l, tid);
    __syncthreads();
    preload_B(bh, bl, bhs, bls, wid, lane);
    mma_all(acc, ah_base, al_base, bh, bl, lane);
    __syncthreads();

#pragma unroll
    for (int m = 0; m < 8; m++) {
        int r0l = m * 16 + (lane >> 2);
        int r1l = r0l + 8;
        int r0 = m0 + r0l, r1 = m0 + r1l;
        float cm0 = (r0 < NN) ? (float)g_cnt[r0] : 0.f;
        float cm1 = (r1 < NN) ? (float)g_cnt[r1] : 0.f;
#pragma unroll
        for (int nt = 0; nt < 2; nt++) {
            int n = wid * 16 + nt * 8 + (lane & 3) * 2;
            float o0 = fmaxf(acc[m][nt][0] + bs[n] + cm0 * bs2[n], 0.f);
            float o1 = fmaxf(acc[m][nt][1] + bs[n + 1] + cm0 * bs2[n + 1], 0.f);
            float o2 = fmaxf(acc[m][nt][2] + bs[n] + cm1 * bs2[n], 0.f);
            float o3 = fmaxf(acc[m][nt][3] + bs[n + 1] + cm1 * bs2[n + 1], 0.f);
            uint32_t hv, lv;
            hilo2(o0, o1, hv, lv);
            *(uint32_t*)(A_hi + r0l * NM_ST + n * 2) = hv;
            *(uint32_t*)(A_lo + r0l * NM_ST + n * 2) = lv;
            hilo2(o2, o3, hv, lv);
            *(uint32_t*)(A_hi + r1l * NM_ST + n * 2) = hv;
            *(uint32_t*)(A_lo + r1l * NM_ST + n * 2) = lv;
        }
    }
    stage_B(B_hi, B_lo, g_BnW2_h, g_BnW2_l, tid);
    __syncthreads();

    preload_B(bh, bl, bhs, bls, wid, lane);
    ZERO_ACC(acc);
    mma_all(acc, ah_base, al_base, bh, bl, lane);

#pragma unroll
    for (int m = 0; m < 8; m++) {
        int r0 = m0 + m * 16 + (lane >> 2);
        int r1 = r0 + 8;
#pragma unroll
        for (int nt = 0; nt < 2; nt++) {
            int n = wid * 16 + nt * 8 + (lane & 3) * 2;
            float b0 = __ldg(&nb2[n]), b1 = __ldg(&nb2[n + 1]);
            if (r0 < NN) {
                float2 rv = *(const float2*)&Ah[r0 * HH + n];
                *(float2*)&hdst[r0 * HH + n] =
                    make_float2(acc[m][nt][0] + b0 + rv.x, acc[m][nt][1] + b1 + rv.y);
            }
            if (r1 < NN) {
                float2 rv = *(const float2*)&Ah[r1 * HH + n];
                *(float2*)&hdst[r1 * HH + n] =
                    make_float2(acc[m][nt][2] + b0 + rv.x, acc[m][nt][3] + b1 + rv.y);
            }
        }
    }
}

// ---------------- fused vW1-GEMM + v epilogue --------------------------------
__global__ void __launch_bounds__(256)
node_mma_v(const float* __restrict__ A, const float* __restrict__ vb1,
           const float* __restrict__ vW2, const float* __restrict__ vb2,
           float* __restrict__ outv) {
    extern __shared__ char smc[];
    char* A_hi = smc + NM_A_HI;
    char* A_lo = smc + NM_A_LO;
    char* B_hi = smc + NM_B_HI;
    char* B_lo = smc + NM_B_LO;
    float* bs = (float*)(smc + NM_MISC);
    float* w2 = bs + 128;
    float* vp = w2 + 256;
    const int tid = threadIdx.x;
    const int wid = tid >> 5, lane = tid & 31;
    const int m0 = blockIdx.x * 128;

    const uint32_t ah_base = smem_u32(A_hi), al_base = smem_u32(A_lo);
    const uint32_t bhs = smem_u32(B_hi), bls = smem_u32(B_lo);

    if (tid < 128) bs[tid] = vb1[tid];
    if (tid < 256) { w2[tid] = vW2[tid]; vp[tid] = 0.f; }

    stage_A(A_hi, A_lo, A, m0, tid);
    stage_B(B_hi, B_lo, g_BvW1_h, g_BvW1_l, tid);
    __syncthreads();

    uint32_t bh[2][8][2], bl[2][8][2];
    preload_B(bh, bl, bhs, bls, wid, lane);
    float acc[8][2][4];
    ZERO_ACC(acc);
    mma_all(acc, ah_base, al_base, bh, bl, lane);

#pragma unroll
    for (int m = 0; m < 8; m++) {
        int r0l = m * 16 + (lane >> 2);
        int r1l = r0l + 8;
        float c00 = 0.f, c01 = 0.f, c10 = 0.f, c11 = 0.f;
#pragma unroll
        for (int nt = 0; nt < 2; nt++) {
            int n = wid * 16 + nt * 8 + (lane & 3) * 2;
            float o0 = fmaxf(acc[m][nt][0] + bs[n], 0.f);
            float o1 = fmaxf(acc[m][nt][1] + bs[n + 1], 0.f);
            float o2 = fmaxf(acc[m][nt][2] + bs[n], 0.f);
            float o3 = fmaxf(acc[m][nt][3] + bs[n + 1], 0.f);
            c00 += o0 * w2[n * 2 + 0] + o1 * w2[(n + 1) * 2 + 0];
            c01 += o0 * w2[n * 2 + 1] + o1 * w2[(n + 1) * 2 + 1];
            c10 += o2 * w2[n * 2 + 0] + o3 * w2[(n + 1) * 2 + 0];
            c11 += o2 * w2[n * 2 + 1] + o3 * w2[(n + 1) * 2 + 1];
        }
        c00 += __shfl_xor_sync(0xffffffffu, c00, 1);
        c00 += __shfl_xor_sync(0xffffffffu, c00, 2);
        c01 += __shfl_xor_sync(0xffffffffu, c01, 1);
        c01 += __shfl_xor_sync(0xffffffffu, c01, 2);
        c10 += __shfl_xor_sync(0xffffffffu, c10, 1);
        c10 += __shfl_xor_sync(0xffffffffu, c10, 2);
        c11 += __shfl_xor_sync(0xffffffffu, c11, 1);
        c11 += __shfl_xor_sync(0xffffffffu, c11, 2);
        if ((lane & 3) == 0) {
            atomicAdd(&vp[2 * r0l + 0], c00);
            atomicAdd(&vp[2 * r0l + 1], c01);
            atomicAdd(&vp[2 * r1l + 0], c10);
            atomicAdd(&vp[2 * r1l + 1], c11);
        }
    }
    __syncthreads();
    if (tid < 128) {
        int row = m0 + tid;
        if (row < NN) {
            float d = fmaxf((float)g_cnt[row], 1.f);
            float v0 = vp[2 * tid] + vb2[0] + g_scat[2 * row] / d;
            float v1 = vp[2 * tid + 1] + vb2[1] + g_scat[2 * row + 1] / d;
            float n = fmaxf(sqrtf(v0 * v0 + v1 * v1), 1e-12f);
            outv[2 * row] = v0 / n;
            outv[2 * row + 1] = v1 / n;
        }
    }
}

// ---------------- macc gather: one warp per node (no atomics) ----------------
__global__ void macc_gather_kernel(const float* __restrict__ x,
                                   const float* __restrict__ eW1,
                                   const float* __restrict__ eb1) {
    int warp = (blockIdx.x * blockDim.x + threadIdx.x) >> 5;
    int lane = threadIdx.x & 31;
    if (warp >= NN) return;
    int r = warp;
    int j = lane << 2;
    float4 m1v = *(const float4*)&g_m1[r * HH + j];
    float4 wd  = *(const float4*)&eW1[256 * HH + j];
    float4 b1  = *(const float4*)&eb1[j];
    float2 xr  = *(const float2*)&x[2 * r];
    float4 acc = make_float4(0.f, 0.f, 0.f, 0.f);
    int s = g_off[r], e = g_off[r + 1];
    for (int idx = s; idx < e; idx++) {
        int c = __ldg(&g_cols[idx]);
        float2 xc = *(const float2*)&x[2 * c];
        float dx = xr.x - xc.x, dy = xr.y - xc.y;
        float rd = dx * dx + dy * dy;
        float4 m2v = *(const float4*)&g_m2[c * HH + j];
        acc.x += fmaxf(m1v.x + m2v.x + rd * wd.x + b1.x, 0.f);
        acc.y += fmaxf(m1v.y + m2v.y + rd * wd.y + b1.y, 0.f);
        acc.z += fmaxf(m1v.z + m2v.z + rd * wd.z + b1.z, 0.f);
        acc.w += fmaxf(m1v.w + m2v.w + rd * wd.w + b1.w, 0.f);
    }
    *(float4*)&g_macc[r * HH + j] = acc;
}

// ---------------- coord kernel (layer 2 only, mma.sync) ----------------------
#define EK2_ASTRIDE 272
#define EK2_A_HI 0
#define EK2_A_LO 34816
#define EK2_MISC 69632
#define EK2_SMEM (EK2_MISC + 5120)

__global__ void __launch_bounds__(256)
edge2_kernel(const float* __restrict__ x,
             const float* __restrict__ eW1, const float* __restrict__ eb1,
             const float* __restrict__ cW2, const float* __restrict__ cb2) {
    extern __shared__ char smc[];
    char* A_hi = smc + EK2_A_HI;
    char* A_lo = smc + EK2_A_LO;
    float* misc   = (float*)(smc + EK2_MISC);
    float* wd_s   = misc;
    float* b1_s   = misc + 128;
    float* bc_s   = misc + 256;
    float* cw2_s  = misc + 384;
    float* p2a_s  = misc + 512;
    float* p2b_s  = misc + 640;
    float* rd_s   = misc + 768;
    float* coordp = misc + 896;
    int* row_s = (int*)(misc + 1024);
    int* col_s = (int*)(misc + 1152);

    const int tid = threadIdx.x;
    const int wid = tid >> 5, lane = tid & 31;

    if (tid < 128) {
        wd_s[tid]  = eW1[256 * HH + tid];
        b1_s[tid]  = eb1[tid];
        bc_s[tid]  = g_bc[tid];
        cw2_s[tid] = cW2[tid];
        coordp[tid] = 0.f;
        int eg = blockIdx.x * 128 + tid;
        int r = g_rows[eg], c = g_cols[eg];
        row_s[tid] = r; col_s[tid] = c;
        float2 xr = *(const float2*)&x[2 * r];
        float2 xc = *(const float2*)&x[2 * c];
        float dx = xr.x - xc.x, dy = xr.y - xc.y;
        rd_s[tid]  = dx * dx + dy * dy;
        p2a_s[tid] = dx * dx - dy * dy;
        p2b_s[tid] = 2.f * dx * dy;
    }
    for (int idx = tid; idx < 8192; idx += 256) {
        int n = idx >> 6, kp = idx & 63;
        uint32_t vh = ((const uint32_t*)g_Bhi)[idx];
        uint32_t vl = ((const uint32_t*)g_Blo)[idx];
        int off = n * EK2_ASTRIDE + kp * 4;
        *(uint32_t*)(A_hi + off) = vh;
        *(uint32_t*)(A_lo + off) = vl;
    }
    __syncthreads();

    uint32_t bh[2][8][2], bl[2][8][2];
    {
        uint32_t hbase = smem_u32(A_hi);
        uint32_t lbase = smem_u32(A_lo);
        int roff = (lane & 7) * EK2_ASTRIDE + ((lane >> 3) & 1) * 16;
#pragma unroll
        for (int nt = 0; nt < 2; nt++)
#pragma unroll
            for (int k = 0; k < 8; k++) {
                uint32_t a = (wid * 16 + nt * 8) * EK2_ASTRIDE + k * 32 + roff;
                ldmx2(bh[nt][k][0], bh[nt][k][1], hbase + a);
                ldmx2(bl[nt][k][0], bl[nt][k][1], lbase + a);
            }
    }
    __syncthreads();

#pragma unroll
    for (int s = 0; s < 16; s++) {
        int item = tid + s * 256;
        int e = item >> 5, j = (item & 31) << 2;
        int r = row_s[e], c = col_s[e];
        float rd = rd_s[e];
        float4 a  = *(const float4*)&g_m1[r * HH + j];
        float4 b  = *(const float4*)&g_m2[c * HH + j];
        float4 w  = *(const float4*)&wd_s[j];
        float4 bb = *(const float4*)&b1_s[j];
        float v0 = fmaxf(a.x + b.x + rd * w.x + bb.x, 0.f);
        float v1 = fmaxf(a.y + b.y + rd * w.y + bb.y, 0.f);
        float v2 = fmaxf(a.z + b.z + rd * w.z + bb.z, 0.f);
        float v3 = fmaxf(a.w + b.w + rd * w.w + bb.w, 0.f);
        uint2 hv, lv;
        hilo4(v0, v1, v2, v3, hv, lv);
        int off = e * EK2_ASTRIDE + j * 2;
        *(uint2*)(A_hi + off) = hv;
        *(uint2*)(A_lo + off) = lv;
    }
    __syncthreads();

    {
        uint32_t hbase = smem_u32(A_hi);
        uint32_t lbase = smem_u32(A_lo);
        int aroff = (lane & 15) * EK2_ASTRIDE + ((lane >> 4) & 1) * 16;
#pragma unroll
        for (int m = 0; m < 8; m++) {
            float acc[2][4];
#pragma unroll
            for (int nt = 0; nt < 2; nt++)
#pragma unroll
                for (int q = 0; q < 4; q++) acc[nt][q] = 0.f;
#pragma unroll
            for (int k = 0; k < 8; k++) {
                uint32_t a = (m * 16) * EK2_ASTRIDE + k * 32 + aroff;
                uint32_t ah[4], al[4];
                ldmx4(ah, hbase + a);
                ldmx4(al, lbase + a);
#pragma unroll
                for (int nt = 0; nt < 2; nt++) {
                    mma_bf16(acc[nt], ah, bh[nt][k][0], bh[nt][k][1]);
                    mma_bf16(acc[nt], ah, bl[nt][k][0], bl[nt][k][1]);
                    mma_bf16(acc[nt], al, bh[nt][k][0], bh[nt][k][1]);
                }
            }
            int r0 = m * 16 + (lane >> 2);
            float p0 = 0.f, p1 = 0.f;
#pragma unroll
            for (int nt = 0; nt < 2; nt++) {
                int n = wid * 16 + nt * 8 + (lane & 3) * 2;
                p0 += fmaxf(acc[nt][0] + bc_s[n], 0.f) * cw2_s[n]
                    + fmaxf(acc[nt][1] + bc_s[n + 1], 0.f) * cw2_s[n + 1];
                p1 += fmaxf(acc[nt][2] + bc_s[n], 0.f) * cw2_s[n]
                    + fmaxf(acc[nt][3] + bc_s[n + 1], 0.f) * cw2_s[n + 1];
            }
            p0 += __shfl_xor_sync(0xffffffffu, p0, 1);
            p0 += __shfl_xor_sync(0xffffffffu, p0, 2);
            p1 += __shfl_xor_sync(0xffffffffu, p1, 1);
            p1 += __shfl_xor_sync(0xffffffffu, p1, 2);
            if ((lane & 3) == 0) {
                atomicAdd(&coordp[r0], p0);
                atomicAdd(&coordp[r0 + 8], p1);
            }
        }
    }
    __syncthreads();
    if (tid < 128) {
        float csum = coordp[tid] + cb2[0];
        red_add_v2(&g_scat[2 * row_s[tid]], p2a_s[tid] * csum, p2b_s[tid] * csum);
    }
}

__global__ void copy_x_kernel(const float* __restrict__ x, float* __restrict__ outx) {
    int i = blockIdx.x * blockDim.x + threadIdx.x;
    if (i < NN * 2) outx[i] = x[i];
}

// ---------------- launcher ---------------------------------------------------
extern "C" void kernel_launch(void* const* d_in, const int* in_sizes, int n_in,
                              void* d_out, int out_size) {
    const float* h0   = (const float*)d_in[0];
    const float* x    = (const float*)d_in[1];
    const int*   ei   = (const int*)d_in[2];
    const float* embW = (const float*)d_in[3];
    const float* embB = (const float*)d_in[4];
    const float* eW1  = (const float*)d_in[5];
    const float* eb1  = (const float*)d_in[6];
    const float* eW2  = (const float*)d_in[7];
    const float* eb2  = (const float*)d_in[8];
    const float* nW1  = (const float*)d_in[9];
    const float* nb1  = (const float*)d_in[10];
    const float* nW2  = (const float*)d_in[11];
    const float* nb2  = (const float*)d_in[12];
    const float* vW1  = (const float*)d_in[13];
    const float* vb1  = (const float*)d_in[14];
    const float* vW2  = (const float*)d_in[15];
    const float* vb2  = (const float*)d_in[16];
    const float* cW1  = (const float*)d_in[17];
    const float* cb1  = (const float*)d_in[18];
    const float* cW2  = (const float*)d_in[19];
    const float* cb2  = (const float*)d_in[20];

    float* out   = (float*)d_out;
    float* out_h = out;
    float* out_x = out + NN * HH;
    float* out_v = out + NN * HH + NN * 2;

    float *p_h, *p_macc;
    cudaGetSymbolAddress((void**)&p_h,    g_h);
    cudaGetSymbolAddress((void**)&p_macc, g_macc);

    cudaFuncSetAttribute(node_mma_m12, cudaFuncAttributeMaxDynamicSharedMemorySize, NM_SMEM);
    cudaFuncSetAttribute(node_mma_th, cudaFuncAttributeMaxDynamicSharedMemorySize, NM_SMEM);
    cudaFuncSetAttribute(node_mma_v, cudaFuncAttributeMaxDynamicSharedMemorySize, NM_SMEM);
    cudaFuncSetAttribute(edge2_kernel, cudaFuncAttributeMaxDynamicSharedMemorySize, EK2_SMEM);

    const int GB = (NN + 127) / 128;

    // side streams + events, created fresh every call and DESTROYED before
    // return (the harness verifies device-free-memory returns to baseline).
    cudaStream_t s1, s2;
    cudaStreamCreateWithFlags(&s1, cudaStreamNonBlocking);
    cudaStreamCreateWithFlags(&s2, cudaStreamNonBlocking);
    cudaEvent_t eFork, eSort, eFork2, eEdge, eX;
    cudaEventCreateWithFlags(&eFork,  cudaEventDisableTiming);
    cudaEventCreateWithFlags(&eSort,  cudaEventDisableTiming);
    cudaEventCreateWithFlags(&eFork2, cudaEventDisableTiming);
    cudaEventCreateWithFlags(&eEdge,  cudaEventDisableTiming);
    cudaEventCreateWithFlags(&eX,     cudaEventDisableTiming);

    // fork from capture stream
    cudaEventRecord(eFork, 0);

    // --- branch s1: sort pipeline ---
    cudaStreamWaitEvent(s1, eFork, 0);
    zero_cnt_scat_kernel<<<(NN * 2 + 255) / 256, 256, 0, s1>>>();
    count_kernel<<<(EE + 255) / 256, 256, 0, s1>>>(ei);
    scan1_kernel<<<SCAN_B, 256, 0, s1>>>();
    scan2_kernel<<<1, 256, 0, s1>>>();
    scan3_kernel<<<SCAN_B, 256, 0, s1>>>();
    scatter_kernel<<<(EE + 255) / 256, 256, 0, s1>>>(ei);
    cudaEventRecord(eSort, s1);

    // --- branch s2: copy x out ---
    cudaStreamWaitEvent(s2, eFork, 0);
    copy_x_kernel<<<(NN * 2 + 255) / 256, 256, 0, s2>>>(x, out_x);
    cudaEventRecord(eX, s2);

    // --- main: weight prep + embed ---
    {
        dim3 g(128, 7);
        prep_all_kernel<<<g, 128>>>(eW1, nW1, nW2, vW1, eW2, cW1, eb2, cb1);
    }
    embed_kernel<<<NN / 2, 256>>>(h0, embW, embB);

    // ---- layer 0 ----
    node_mma_m12<<<GB, 256, NM_SMEM>>>(p_h);
    cudaStreamWaitEvent(0, eSort, 0);
    macc_gather_kernel<<<(NN * 32 + 255) / 256, 256>>>(x, eW1, eb1);
    node_mma_th<<<GB, 256, NM_SMEM>>>(p_h, p_macc, nb1, nb2, p_h);

    // ---- layer 1 ----
    node_mma_m12<<<GB, 256, NM_SMEM>>>(p_h);
    // fork edge2 onto s1 (independent of macc/th: writes only g_scat)
    cudaEventRecord(eFork2, 0);
    cudaStreamWaitEvent(s1, eFork2, 0);
    edge2_kernel<<<EE / 128, 256, EK2_SMEM, s1>>>(x, eW1, eb1, cW2, cb2);
    cudaEventRecord(eEdge, s1);
    // main continues with gather + th concurrently
    macc_gather_kernel<<<(NN * 32 + 255) / 256, 256>>>(x, eW1, eb1);
    node_mma_th<<<GB, 256, NM_SMEM>>>(p_h, p_macc, nb1, nb2, out_h);

    // join: v epilogue needs edge2's g_scat and th's out_h
    cudaStreamWaitEvent(0, eEdge, 0);
    node_mma_v<<<GB, 256, NM_SMEM>>>(out_h, vb1, vW2, vb2, out_v);
    cudaStreamWaitEvent(0, eX, 0);

    // cleanup: both side streams are joined into the capture stream above, so
    // they are no longer capturing and can be destroyed; releases the ~2MB the
    // allocation guard flagged in R10.
    cudaEventDestroy(eFork);
    cudaEventDestroy(eSort);
    cudaEventDestroy(eFork2);
    cudaEventDestroy(eEdge);
    cudaEventDestroy(eX);
    cudaStreamDestroy(s1);
    cudaStreamDestroy(s2);
}

// round 13
// speedup vs baseline: 4.8282x; 1.1649x over previous
#include <cuda_runtime.h>
#include <cuda_bf16.h>
#include <cstdint>

#define NN 50000
#define EE 800000
#define HH 128
#define PP 16
#define SCAN_B 196   // ceil(NN/256)

typedef __nv_bfloat16 bf16;

// ---------------- scratch (device globals; no allocation allowed) -----------
__device__ float g_h[NN * HH];
__device__ float g_m1[NN * HH];
__device__ float g_m2[NN * HH];
__device__ float g_macc[NN * HH];
__device__ float g_scat[NN * 2];
__device__ int   g_cnt[NN];
__device__ int   g_off[NN + 1];
__device__ int   g_cur[NN];
__device__ int   g_bsum[SCAN_B];
__device__ int   g_rows[EE];
__device__ int   g_cols[EE];
__device__ float g_bc[HH];
__device__ float g_bme[HH];
// transposed bf16 hi/lo weights: B[n][k] = W[k][n]
__device__ bf16 g_Bhi[HH * HH];      // Wc (coord)
__device__ bf16 g_Blo[HH * HH];
__device__ bf16 g_BeW1a_h[HH * HH], g_BeW1a_l[HH * HH];
__device__ bf16 g_BeW1b_h[HH * HH], g_BeW1b_l[HH * HH];
__device__ bf16 g_BnW1a_h[HH * HH], g_BnW1a_l[HH * HH];
__device__ bf16 g_BnW2_h[HH * HH],  g_BnW2_l[HH * HH];
__device__ bf16 g_BvW1_h[HH * HH],  g_BvW1_l[HH * HH];
__device__ bf16 g_BWme_h[HH * HH],  g_BWme_l[HH * HH];
// B fragment tables: [matrix][hi/lo][ (cg*8+k)*32 + lane ], cg = colgroup (n/8)
// matrices: 0 eW1a, 1 eW1b, 2 nW1a, 3 nW2, 4 vW1, 5 Wc, 6 Wme
__device__ uint2 g_F[7][2][4096];

// ---------------- PTX helpers ------------------------------------------------
__device__ __forceinline__ void red_add_v2(float* p, float a, float b) {
    asm volatile("red.global.add.v2.f32 [%0], {%1,%2};"
                 :: "l"(p), "f"(a), "f"(b) : "memory");
}
__device__ __forceinline__ uint32_t smem_u32(const void* p) {
    uint32_t a;
    asm("{ .reg .u64 t; cvta.to.shared.u64 t, %1; cvt.u32.u64 %0, t; }" : "=r"(a) : "l"(p));
    return a;
}
__device__ __forceinline__ void ldmx4(uint32_t* r, uint32_t a) {
    asm volatile("ldmatrix.sync.aligned.m8n8.x4.shared.b16 {%0,%1,%2,%3}, [%4];"
                 : "=r"(r[0]), "=r"(r[1]), "=r"(r[2]), "=r"(r[3]) : "r"(a));
}
__device__ __forceinline__ void ldmx2(uint32_t& r0, uint32_t& r1, uint32_t a) {
    asm volatile("ldmatrix.sync.aligned.m8n8.x2.shared.b16 {%0,%1}, [%2];"
                 : "=r"(r0), "=r"(r1) : "r"(a));
}
__device__ __forceinline__ void mma_bf16(float* c, const uint32_t* a, uint32_t b0, uint32_t b1) {
    asm volatile(
        "mma.sync.aligned.m16n8k16.row.col.f32.bf16.bf16.f32 "
        "{%0,%1,%2,%3}, {%4,%5,%6,%7}, {%8,%9}, {%0,%1,%2,%3};"
        : "+f"(c[0]), "+f"(c[1]), "+f"(c[2]), "+f"(c[3])
        : "r"(a[0]), "r"(a[1]), "r"(a[2]), "r"(a[3]), "r"(b0), "r"(b1));
}
__device__ __forceinline__ void hilo4(float v0, float v1, float v2, float v3,
                                      uint2& hv, uint2& lv) {
    bf16 h0 = __float2bfloat16(v0), h1 = __float2bfloat16(v1);
    bf16 h2 = __float2bfloat16(v2), h3 = __float2bfloat16(v3);
    bf16 l0 = __float2bfloat16(v0 - __bfloat162float(h0));
    bf16 l1 = __float2bfloat16(v1 - __bfloat162float(h1));
    bf16 l2 = __float2bfloat16(v2 - __bfloat162float(h2));
    bf16 l3 = __float2bfloat16(v3 - __bfloat162float(h3));
    hv.x = ((uint32_t)__bfloat16_as_ushort(h1) << 16) | __bfloat16_as_ushort(h0);
    hv.y = ((uint32_t)__bfloat16_as_ushort(h3) << 16) | __bfloat16_as_ushort(h2);
    lv.x = ((uint32_t)__bfloat16_as_ushort(l1) << 16) | __bfloat16_as_ushort(l0);
    lv.y = ((uint32_t)__bfloat16_as_ushort(l3) << 16) | __bfloat16_as_ushort(l2);
}
__device__ __forceinline__ void hilo2(float a, float b, uint32_t& h, uint32_t& l) {
    bf16 ha = __float2bfloat16(a), hb = __float2bfloat16(b);
    bf16 la = __float2bfloat16(a - __bfloat162float(ha));
    bf16 lb = __float2bfloat16(b - __bfloat162float(hb));
    h = ((uint32_t)__bfloat16_as_ushort(hb) << 16) | __bfloat16_as_ushort(ha);
    l = ((uint32_t)__bfloat16_as_ushort(lb) << 16) | __bfloat16_as_ushort(la);
}

// ---------------- sort pipeline ----------------------------------------------
__global__ void zero_cnt_scat_kernel() {
    int i = blockIdx.x * blockDim.x + threadIdx.x;
    if (i < NN) g_cnt[i] = 0;
    if (i < NN * 2) g_scat[i] = 0.f;
}

__global__ void count_kernel(const int* __restrict__ ei) {
    int e = blockIdx.x * blockDim.x + threadIdx.x;
    if (e < EE) atomicAdd(&g_cnt[ei[e]], 1);
}

__global__ void scan1_kernel() {
    __shared__ int sm[256];
    int b = blockIdx.x, t = threadIdx.x, i = b * 256 + t;
    int v = (i < NN) ? g_cnt[i] : 0;
    sm[t] = v; __syncthreads();
    for (int o = 128; o; o >>= 1) {
        if (t < o) sm[t] += sm[t + o];
        __syncthreads();
    }
    if (t == 0) g_bsum[b] = sm[0];
}

__global__ void scan2_kernel() {
    __shared__ int sm[256];
    int t = threadIdx.x;
    int v = (t < SCAN_B) ? g_bsum[t] : 0;
    sm[t] = v; __syncthreads();
    for (int o = 1; o < 256; o <<= 1) {
        int add = (t >= o) ? sm[t - o] : 0;
        __syncthreads();
        sm[t] += add;
        __syncthreads();
    }
    if (t < SCAN_B) g_bsum[t] = sm[t] - v;
    if (t == 0) g_off[NN] = EE;
}

__global__ void scan3_kernel() {
    __shared__ int sm[256];
    int b = blockIdx.x, t = threadIdx.x, i = b * 256 + t;
    int v = (i < NN) ? g_cnt[i] : 0;
    sm[t] = v; __syncthreads();
    for (int o = 1; o < 256; o <<= 1) {
        int add = (t >= o) ? sm[t - o] : 0;
        __syncthreads();
        sm[t] += add;
        __syncthreads();
    }
    if (i < NN) {
        int off = g_bsum[b] + sm[t] - v;
        g_off[i] = off;
        g_cur[i] = off;
    }
}

__global__ void scatter_kernel(const int* __restrict__ ei) {
    int e = blockIdx.x * blockDim.x + threadIdx.x;
    if (e < EE) {
        int r = ei[e];
        int pos = atomicAdd(&g_cur[r], 1);
        g_rows[pos] = r;
        g_cols[pos] = ei[EE + e];
    }
}

// ---------------- weight prep -------------------------------------------------
// phase 1: transposed hi/lo into global (grid (128, 7), block 128)
__global__ void prep_all_kernel(const float* __restrict__ eW1, const float* __restrict__ nW1,
                                const float* __restrict__ nW2, const float* __restrict__ vW1,
                                const float* __restrict__ eW2, const float* __restrict__ cW1,
                                const float* __restrict__ eb2, const float* __restrict__ cb1) {
    int i = blockIdx.x, j = threadIdx.x;
    int task = blockIdx.y;
    if (task < 5) {
        const float* W;
        bf16 *oh, *ol;
        switch (task) {
            case 0: W = eW1;            oh = g_BeW1a_h; ol = g_BeW1a_l; break;
            case 1: W = eW1 + 128 * HH; oh = g_BeW1b_h; ol = g_BeW1b_l; break;
            case 2: W = nW1;            oh = g_BnW1a_h; ol = g_BnW1a_l; break;
            case 3: W = nW2;            oh = g_BnW2_h;  ol = g_BnW2_l;  break;
            default: W = vW1;           oh = g_BvW1_h;  ol = g_BvW1_l;  break;
        }
        float s = W[i * HH + j];
        bf16 hi = __float2bfloat16(s);
        bf16 lo = __float2bfloat16(s - __bfloat162float(hi));
        oh[j * HH + i] = hi;
        ol[j * HH + i] = lo;
    } else if (task == 5) {
        float s = 0.f;
        for (int k = 0; k < HH; k++) s += eW2[i * HH + k] * cW1[k * HH + j];
        bf16 hi = __float2bfloat16(s);
        bf16 lo = __float2bfloat16(s - __bfloat162float(hi));
        g_Bhi[j * HH + i] = hi;
        g_Blo[j * HH + i] = lo;
        if (i == 0) {
            float t = 0.f;
            for (int k = 0; k < HH; k++) t += eb2[k] * cW1[k * HH + j];
            g_bc[j] = t + cb1[j];
        }
    } else {
        const float* nW1b = nW1 + 128 * HH;
        float s = 0.f;
        for (int k = 0; k < HH; k++) s += eW2[i * HH + k] * nW1b[k * HH + j];
        bf16 hi = __float2bfloat16(s);
        bf16 lo = __float2bfloat16(s - __bfloat162float(hi));
        g_BWme_h[j * HH + i] = hi;
        g_BWme_l[j * HH + i] = lo;
        if (i == 0) {
            float t = 0.f;
            for (int k = 0; k < HH; k++) t += eb2[k] * nW1b[k * HH + j];
            g_bme[j] = t;
        }
    }
}

#define NM_ST 272
// phase 2: ldmatrix the transposed weights once, store B fragments (grid 7, block 256)
__global__ void prep_frag_kernel() {
    extern __shared__ char smc[];
    char* S_hi = smc;
    char* S_lo = smc + 34816;
    int task = blockIdx.x, tid = threadIdx.x, wid = tid >> 5, lane = tid & 31;
    const bf16 *Bh, *Bl;
    switch (task) {
        case 0: Bh = g_BeW1a_h; Bl = g_BeW1a_l; break;
        case 1: Bh = g_BeW1b_h; Bl = g_BeW1b_l; break;
        case 2: Bh = g_BnW1a_h; Bl = g_BnW1a_l; break;
        case 3: Bh = g_BnW2_h;  Bl = g_BnW2_l;  break;
        case 4: Bh = g_BvW1_h;  Bl = g_BvW1_l;  break;
        case 5: Bh = g_Bhi;     Bl = g_Blo;     break;
        default: Bh = g_BWme_h; Bl = g_BWme_l;  break;
    }
    for (int idx = tid; idx < 8192; idx += 256) {
        int n = idx >> 6, kp = idx & 63;
        int off = n * NM_ST + kp * 4;
        *(uint32_t*)(S_hi + off) = ((const uint32_t*)Bh)[idx];
        *(uint32_t*)(S_lo + off) = ((const uint32_t*)Bl)[idx];
    }
    __syncthreads();
    uint32_t hbase = smem_u32(S_hi), lbase = smem_u32(S_lo);
    int roff = (lane & 7) * NM_ST + ((lane >> 3) & 1) * 16;
#pragma unroll
    for (int nt = 0; nt < 2; nt++)
#pragma unroll
        for (int k = 0; k < 8; k++) {
            uint32_t a = (wid * 16 + nt * 8) * NM_ST + k * 32 + roff;
            uint32_t h0, h1, l0, l1;
            ldmx2(h0, h1, hbase + a);
            ldmx2(l0, l1, lbase + a);
            int cg = wid * 2 + nt;
            g_F[task][0][(cg * 8 + k) * 32 + lane] = make_uint2(h0, h1);
            g_F[task][1][(cg * 8 + k) * 32 + lane] = make_uint2(l0, l1);
        }
}

__global__ void embed_kernel(const float* __restrict__ h0, const float* __restrict__ W,
                             const float* __restrict__ b) {
    int row = blockIdx.x * 2 + (threadIdx.x >> 7);
    int j = threadIdx.x & 127;
    if (row >= NN) return;
    float s = b[j];
#pragma unroll
    for (int k = 0; k < PP; k++) s += h0[row * PP + k] * W[k * HH + j];
    g_h[row * HH + j] = s;
}

// ---------------- 512-thread node MMA machinery -------------------------------
// A tile (128 rows) hi/lo in smem; B from fragment tables; 16 warps, warp w
// owns output cols [w*8, w*8+8).
#define NM_A_HI 0
#define NM_A_LO 34816
#define NM_MISC 69632
#define NM_SMEM (NM_MISC + 4096)

__device__ __forceinline__ void stage_A512(char* A_hi, char* A_lo, const float* A,
                                           int m0, int tid) {
    for (int idx = tid; idx < 128 * 32; idx += 512) {
        int r = idx >> 5, c4 = (idx & 31) << 2;
        int gr = m0 + r;
        float4 v = (gr < NN) ? *(const float4*)&A[gr * HH + c4]
                             : make_float4(0.f, 0.f, 0.f, 0.f);
        uint2 hv, lv;
        hilo4(v.x, v.y, v.z, v.w, hv, lv);
        int off = r * NM_ST + c4 * 2;
        *(uint2*)(A_hi + off) = hv;
        *(uint2*)(A_lo + off) = lv;
    }
}
__device__ __forceinline__ void load_F8(uint32_t bh[8][2], uint32_t bl[8][2],
                                        const uint2* Fh, const uint2* Fl,
                                        int wid, int lane) {
#pragma unroll
    for (int k = 0; k < 8; k++) {
        uint2 v = __ldg(&Fh[(wid * 8 + k) * 32 + lane]);
        bh[k][0] = v.x; bh[k][1] = v.y;
        uint2 u = __ldg(&Fl[(wid * 8 + k) * 32 + lane]);
        bl[k][0] = u.x; bl[k][1] = u.y;
    }
}
__device__ __forceinline__ void mma_all8(float acc[8][4], uint32_t ah_base, uint32_t al_base,
                                         uint32_t bh[8][2], uint32_t bl[8][2], int lane) {
    int aroff = (lane & 15) * NM_ST + ((lane >> 4) & 1) * 16;
#pragma unroll
    for (int m = 0; m < 8; m++) {
#pragma unroll
        for (int k = 0; k < 8; k++) {
            uint32_t a = (m * 16) * NM_ST + k * 32 + aroff;
            uint32_t ahf[4], alf[4];
            ldmx4(ahf, ah_base + a);
            ldmx4(alf, al_base + a);
            mma_bf16(acc[m], ahf, bh[k][0], bh[k][1]);
            mma_bf16(acc[m], ahf, bl[k][0], bl[k][1]);
            mma_bf16(acc[m], alf, bh[k][0], bh[k][1]);
        }
    }
}
#define ZERO_ACC8(acc) \
    _Pragma("unroll") for (int m = 0; m < 8; m++) \
    _Pragma("unroll") for (int q = 0; q < 4; q++) acc[m][q] = 0.f;

// ---------------- m1/m2 dual-output GEMM -------------------------------------
__global__ void __launch_bounds__(512, 1)
node_mma_m12(const float* __restrict__ A) {
    extern __shared__ char smc[];
    char* A_hi = smc + NM_A_HI;
    char* A_lo = smc + NM_A_LO;
    const int tid = threadIdx.x;
    const int wid = tid >> 5, lane = tid & 31;
    const int m0 = blockIdx.x * 128;
    const uint32_t ah_base = smem_u32(A_hi), al_base = smem_u32(A_lo);

    stage_A512(A_hi, A_lo, A, m0, tid);
    __syncthreads();

    uint32_t bh[8][2], bl[8][2];
    float acc[8][4];
    for (int s = 0; s < 2; s++) {
        load_F8(bh, bl, g_F[s][0], g_F[s][1], wid, lane);
        ZERO_ACC8(acc);
        mma_all8(acc, ah_base, al_base, bh, bl, lane);
        float* C = s ? g_m2 : g_m1;
        int n = wid * 8 + (lane & 3) * 2;
#pragma unroll
        for (int m = 0; m < 8; m++) {
            int r0 = m0 + m * 16 + (lane >> 2);
            int r1 = r0 + 8;
            if (r0 < NN) *(float2*)&C[r0 * HH + n] = make_float2(acc[m][0], acc[m][1]);
            if (r1 < NN) *(float2*)&C[r1 * HH + n] = make_float2(acc[m][2], acc[m][3]);
        }
    }
}

// ---------------- fused t-GEMM + h-GEMM --------------------------------------
__global__ void __launch_bounds__(512, 1)
node_mma_th(const float* __restrict__ Ah, const float* __restrict__ Amacc,
            const float* __restrict__ nb1, const float* __restrict__ nb2,
            float* __restrict__ hdst) {
    extern __shared__ char smc[];
    char* A_hi = smc + NM_A_HI;
    char* A_lo = smc + NM_A_LO;
    float* bs  = (float*)(smc + NM_MISC);
    float* bs2 = bs + 128;
    const int tid = threadIdx.x;
    const int wid = tid >> 5, lane = tid & 31;
    const int m0 = blockIdx.x * 128;
    const uint32_t ah_base = smem_u32(A_hi), al_base = smem_u32(A_lo);

    if (tid < 128) { bs[tid] = nb1[tid]; bs2[tid] = g_bme[tid]; }

    uint32_t bh[8][2], bl[8][2];
    float acc[8][4];
    ZERO_ACC8(acc);

    stage_A512(A_hi, A_lo, Ah, m0, tid);
    __syncthreads();
    load_F8(bh, bl, g_F[2][0], g_F[2][1], wid, lane);
    mma_all8(acc, ah_base, al_base, bh, bl, lane);
    __syncthreads();
    stage_A512(A_hi, A_lo, Amacc, m0, tid);
    __syncthreads();
    load_F8(bh, bl, g_F[6][0], g_F[6][1], wid, lane);
    mma_all8(acc, ah_base, al_base, bh, bl, lane);
    __syncthreads();

    // write T = relu(acc + nb1 + cnt*bme) into A smem as hi/lo
    {
        int n = wid * 8 + (lane & 3) * 2;
#pragma unroll
        for (int m = 0; m < 8; m++) {
            int r0l = m * 16 + (lane >> 2);
            int r1l = r0l + 8;
            int r0 = m0 + r0l, r1 = m0 + r1l;
            float cm0 = (r0 < NN) ? (float)g_cnt[r0] : 0.f;
            float cm1 = (r1 < NN) ? (float)g_cnt[r1] : 0.f;
            float o0 = fmaxf(acc[m][0] + bs[n] + cm0 * bs2[n], 0.f);
            float o1 = fmaxf(acc[m][1] + bs[n + 1] + cm0 * bs2[n + 1], 0.f);
            float o2 = fmaxf(acc[m][2] + bs[n] + cm1 * bs2[n], 0.f);
            float o3 = fmaxf(acc[m][3] + bs[n + 1] + cm1 * bs2[n + 1], 0.f);
            uint32_t hv, lv;
            hilo2(o0, o1, hv, lv);
            *(uint32_t*)(A_hi + r0l * NM_ST + n * 2) = hv;
            *(uint32_t*)(A_lo + r0l * NM_ST + n * 2) = lv;
            hilo2(o2, o3, hv, lv);
            *(uint32_t*)(A_hi + r1l * NM_ST + n * 2) = hv;
            *(uint32_t*)(A_lo + r1l * NM_ST + n * 2) = lv;
        }
    }
    __syncthreads();

    load_F8(bh, bl, g_F[3][0], g_F[3][1], wid, lane);
    ZERO_ACC8(acc);
    mma_all8(acc, ah_base, al_base, bh, bl, lane);

    {
        int n = wid * 8 + (lane & 3) * 2;
        float b0 = __ldg(&nb2[n]), b1 = __ldg(&nb2[n + 1]);
#pragma unroll
        for (int m = 0; m < 8; m++) {
            int r0 = m0 + m * 16 + (lane >> 2);
            int r1 = r0 + 8;
            if (r0 < NN) {
                float2 rv = *(const float2*)&Ah[r0 * HH + n];
                *(float2*)&hdst[r0 * HH + n] =
                    make_float2(acc[m][0] + b0 + rv.x, acc[m][1] + b1 + rv.y);
            }
            if (r1 < NN) {
                float2 rv = *(const float2*)&Ah[r1 * HH + n];
                *(float2*)&hdst[r1 * HH + n] =
                    make_float2(acc[m][2] + b0 + rv.x, acc[m][3] + b1 + rv.y);
            }
        }
    }
}

// ---------------- fused vW1-GEMM + v epilogue --------------------------------
__global__ void __launch_bounds__(512, 1)
node_mma_v(const float* __restrict__ A, const float* __restrict__ vb1,
           const float* __restrict__ vW2, const float* __restrict__ vb2,
           float* __restrict__ outv) {
    extern __shared__ char smc[];
    char* A_hi = smc + NM_A_HI;
    char* A_lo = smc + NM_A_LO;
    float* bs = (float*)(smc + NM_MISC);
    float* w2 = bs + 128;
    float* vp = w2 + 256;
    const int tid = threadIdx.x;
    const int wid = tid >> 5, lane = tid & 31;
    const int m0 = blockIdx.x * 128;
    const uint32_t ah_base = smem_u32(A_hi), al_base = smem_u32(A_lo);

    if (tid < 128) bs[tid] = vb1[tid];
    if (tid < 256) { w2[tid] = vW2[tid]; vp[tid] = 0.f; }

    stage_A512(A_hi, A_lo, A, m0, tid);
    __syncthreads();

    uint32_t bh[8][2], bl[8][2];
    load_F8(bh, bl, g_F[4][0], g_F[4][1], wid, lane);
    float acc[8][4];
    ZERO_ACC8(acc);
    mma_all8(acc, ah_base, al_base, bh, bl, lane);

    {
        int n = wid * 8 + (lane & 3) * 2;
#pragma unroll
        for (int m = 0; m < 8; m++) {
            int r0l = m * 16 + (lane >> 2);
            int r1l = r0l + 8;
            float o0 = fmaxf(acc[m][0] + bs[n], 0.f);
            float o1 = fmaxf(acc[m][1] + bs[n + 1], 0.f);
            float o2 = fmaxf(acc[m][2] + bs[n], 0.f);
            float o3 = fmaxf(acc[m][3] + bs[n + 1], 0.f);
            float c00 = o0 * w2[n * 2 + 0] + o1 * w2[(n + 1) * 2 + 0];
            float c01 = o0 * w2[n * 2 + 1] + o1 * w2[(n + 1) * 2 + 1];
            float c10 = o2 * w2[n * 2 + 0] + o3 * w2[(n + 1) * 2 + 0];
            float c11 = o2 * w2[n * 2 + 1] + o3 * w2[(n + 1) * 2 + 1];
            c00 += __shfl_xor_sync(0xffffffffu, c00, 1);
            c00 += __shfl_xor_sync(0xffffffffu, c00, 2);
            c01 += __shfl_xor_sync(0xffffffffu, c01, 1);
            c01 += __shfl_xor_sync(0xffffffffu, c01, 2);
            c10 += __shfl_xor_sync(0xffffffffu, c10, 1);
            c10 += __shfl_xor_sync(0xffffffffu, c10, 2);
            c11 += __shfl_xor_sync(0xffffffffu, c11, 1);
            c11 += __shfl_xor_sync(0xffffffffu, c11, 2);
            if ((lane & 3) == 0) {
                atomicAdd(&vp[2 * r0l + 0], c00);
                atomicAdd(&vp[2 * r0l + 1], c01);
                atomicAdd(&vp[2 * r1l + 0], c10);
                atomicAdd(&vp[2 * r1l + 1], c11);
            }
        }
    }
    __syncthreads();
    if (tid < 128) {
        int row = m0 + tid;
        if (row < NN) {
            float d = fmaxf((float)g_cnt[row], 1.f);
            float v0 = vp[2 * tid] + vb2[0] + g_scat[2 * row] / d;
            float v1 = vp[2 * tid + 1] + vb2[1] + g_scat[2 * row + 1] / d;
            float n = fmaxf(sqrtf(v0 * v0 + v1 * v1), 1e-12f);
            outv[2 * row] = v0 / n;
            outv[2 * row + 1] = v1 / n;
        }
    }
}

// ---------------- macc gather: one warp per node (no atomics) ----------------
__global__ void macc_gather_kernel(const float* __restrict__ x,
                                   const float* __restrict__ eW1,
                                   const float* __restrict__ eb1) {
    int warp = (blockIdx.x * blockDim.x + threadIdx.x) >> 5;
    int lane = threadIdx.x & 31;
    if (warp >= NN) return;
    int r = warp;
    int j = lane << 2;
    float4 m1v = *(const float4*)&g_m1[r * HH + j];
    float4 wd  = *(const float4*)&eW1[256 * HH + j];
    float4 b1  = *(const float4*)&eb1[j];
    float2 xr  = *(const float2*)&x[2 * r];
    float4 acc = make_float4(0.f, 0.f, 0.f, 0.f);
    int s = g_off[r], e = g_off[r + 1];
    for (int idx = s; idx < e; idx++) {
        int c = __ldg(&g_cols[idx]);
        float2 xc = *(const float2*)&x[2 * c];
        float dx = xr.x - xc.x, dy = xr.y - xc.y;
        float rd = dx * dx + dy * dy;
        float4 m2v = *(const float4*)&g_m2[c * HH + j];
        acc.x += fmaxf(m1v.x + m2v.x + rd * wd.x + b1.x, 0.f);
        acc.y += fmaxf(m1v.y + m2v.y + rd * wd.y + b1.y, 0.f);
        acc.z += fmaxf(m1v.z + m2v.z + rd * wd.z + b1.z, 0.f);
        acc.w += fmaxf(m1v.w + m2v.w + rd * wd.w + b1.w, 0.f);
    }
    *(float4*)&g_macc[r * HH + j] = acc;
}

// ---------------- coord kernel (layer 2 only, mma.sync) ----------------------
#define EK2_ASTRIDE 272
#define EK2_A_HI 0
#define EK2_A_LO 34816
#define EK2_MISC 69632
#define EK2_SMEM (EK2_MISC + 5120)

__global__ void __launch_bounds__(256)
edge2_kernel(const float* __restrict__ x,
             const float* __restrict__ eW1, const float* __restrict__ eb1,
             const float* __restrict__ cW2, const float* __restrict__ cb2) {
    extern __shared__ char smc[];
    char* A_hi = smc + EK2_A_HI;
    char* A_lo = smc + EK2_A_LO;
    float* misc   = (float*)(smc + EK2_MISC);
    float* wd_s   = misc;
    float* b1_s   = misc + 128;
    float* bc_s   = misc + 256;
    float* cw2_s  = misc + 384;
    float* p2a_s  = misc + 512;
    float* p2b_s  = misc + 640;
    float* rd_s   = misc + 768;
    float* coordp = misc + 896;
    int* row_s = (int*)(misc + 1024);
    int* col_s = (int*)(misc + 1152);

    const int tid = threadIdx.x;
    const int wid = tid >> 5, lane = tid & 31;

    if (tid < 128) {
        wd_s[tid]  = eW1[256 * HH + tid];
        b1_s[tid]  = eb1[tid];
        bc_s[tid]  = g_bc[tid];
        cw2_s[tid] = cW2[tid];
        coordp[tid] = 0.f;
        int eg = blockIdx.x * 128 + tid;
        int r = g_rows[eg], c = g_cols[eg];
        row_s[tid] = r; col_s[tid] = c;
        float2 xr = *(const float2*)&x[2 * r];
        float2 xc = *(const float2*)&x[2 * c];
        float dx = xr.x - xc.x, dy = xr.y - xc.y;
        rd_s[tid]  = dx * dx + dy * dy;
        p2a_s[tid] = dx * dx - dy * dy;
        p2b_s[tid] = 2.f * dx * dy;
    }
    // B fragments straight from the table (matrix 5 = Wc), 8-warp mapping
    uint32_t bh[2][8][2], bl[2][8][2];
#pragma unroll
    for (int nt = 0; nt < 2; nt++)
#pragma unroll
        for (int k = 0; k < 8; k++) {
            int cg = wid * 2 + nt;
            uint2 v = __ldg(&g_F[5][0][(cg * 8 + k) * 32 + lane]);
            bh[nt][k][0] = v.x; bh[nt][k][1] = v.y;
            uint2 u = __ldg(&g_F[5][1][(cg * 8 + k) * 32 + lane]);
            bl[nt][k][0] = u.x; bl[nt][k][1] = u.y;
        }
    __syncthreads();

    // phase 1: preact, write A tiles
#pragma unroll
    for (int s = 0; s < 16; s++) {
        int item = tid + s * 256;
        int e = item >> 5, j = (item & 31) << 2;
        int r = row_s[e], c = col_s[e];
        float rd = rd_s[e];
        float4 a  = *(const float4*)&g_m1[r * HH + j];
        float4 b  = *(const float4*)&g_m2[c * HH + j];
        float4 w  = *(const float4*)&wd_s[j];
        float4 bb = *(const float4*)&b1_s[j];
        float v0 = fmaxf(a.x + b.x + rd * w.x + bb.x, 0.f);
        float v1 = fmaxf(a.y + b.y + rd * w.y + bb.y, 0.f);
        float v2 = fmaxf(a.z + b.z + rd * w.z + bb.z, 0.f);
        float v3 = fmaxf(a.w + b.w + rd * w.w + bb.w, 0.f);
        uint2 hv, lv;
        hilo4(v0, v1, v2, v3, hv, lv);
        int off = e * EK2_ASTRIDE + j * 2;
        *(uint2*)(A_hi + off) = hv;
        *(uint2*)(A_lo + off) = lv;
    }
    __syncthreads();

    // phase 2: C = A @ Wc via mma, fused coord dot + scatter
    {
        uint32_t hbase = smem_u32(A_hi);
        uint32_t lbase = smem_u32(A_lo);
        int aroff = (lane & 15) * EK2_ASTRIDE + ((lane >> 4) & 1) * 16;
#pragma unroll
        for (int m = 0; m < 8; m++) {
            float acc[2][4];
#pragma unroll
            for (int nt = 0; nt < 2; nt++)
#pragma unroll
                for (int q = 0; q < 4; q++) acc[nt][q] = 0.f;
#pragma unroll
            for (int k = 0; k < 8; k++) {
                uint32_t a = (m * 16) * EK2_ASTRIDE + k * 32 + aroff;
                uint32_t ah[4], al[4];
                ldmx4(ah, hbase + a);
                ldmx4(al, lbase + a);
#pragma unroll
                for (int nt = 0; nt < 2; nt++) {
                    mma_bf16(acc[nt], ah, bh[nt][k][0], bh[nt][k][1]);
                    mma_bf16(acc[nt], ah, bl[nt][k][0], bl[nt][k][1]);
                    mma_bf16(acc[nt], al, bh[nt][k][0], bh[nt][k][1]);
                }
            }
            int r0 = m * 16 + (lane >> 2);
            float p0 = 0.f, p1 = 0.f;
#pragma unroll
            for (int nt = 0; nt < 2; nt++) {
                int n = wid * 16 + nt * 8 + (lane & 3) * 2;
                p0 += fmaxf(acc[nt][0] + bc_s[n], 0.f) * cw2_s[n]
                    + fmaxf(acc[nt][1] + bc_s[n + 1], 0.f) * cw2_s[n + 1];
                p1 += fmaxf(acc[nt][2] + bc_s[n], 0.f) * cw2_s[n]
                    + fmaxf(acc[nt][3] + bc_s[n + 1], 0.f) * cw2_s[n + 1];
            }
            p0 += __shfl_xor_sync(0xffffffffu, p0, 1);
            p0 += __shfl_xor_sync(0xffffffffu, p0, 2);
            p1 += __shfl_xor_sync(0xffffffffu, p1, 1);
            p1 += __shfl_xor_sync(0xffffffffu, p1, 2);
            if ((lane & 3) == 0) {
                atomicAdd(&coordp[r0], p0);
                atomicAdd(&coordp[r0 + 8], p1);
            }
        }
    }
    __syncthreads();
    if (tid < 128) {
        float csum = coordp[tid] + cb2[0];
        red_add_v2(&g_scat[2 * row_s[tid]], p2a_s[tid] * csum, p2b_s[tid] * csum);
    }
}

__global__ void copy_x_kernel(const float* __restrict__ x, float* __restrict__ outx) {
    int i = blockIdx.x * blockDim.x + threadIdx.x;
    if (i < NN * 2) outx[i] = x[i];
}

// ---------------- launcher ---------------------------------------------------
extern "C" void kernel_launch(void* const* d_in, const int* in_sizes, int n_in,
                              void* d_out, int out_size) {
    const float* h0   = (const float*)d_in[0];
    const float* x    = (const float*)d_in[1];
    const int*   ei   = (const int*)d_in[2];
    const float* embW = (const float*)d_in[3];
    const float* embB = (const float*)d_in[4];
    const float* eW1  = (const float*)d_in[5];
    const float* eb1  = (const float*)d_in[6];
    const float* eW2  = (const float*)d_in[7];
    const float* eb2  = (const float*)d_in[8];
    const float* nW1  = (const float*)d_in[9];
    const float* nb1  = (const float*)d_in[10];
    const float* nW2  = (const float*)d_in[11];
    const float* nb2  = (const float*)d_in[12];
    const float* vW1  = (const float*)d_in[13];
    const float* vb1  = (const float*)d_in[14];
    const float* vW2  = (const float*)d_in[15];
    const float* vb2  = (const float*)d_in[16];
    const float* cW1  = (const float*)d_in[17];
    const float* cb1  = (const float*)d_in[18];
    const float* cW2  = (const float*)d_in[19];
    const float* cb2  = (const float*)d_in[20];

    float* out   = (float*)d_out;
    float* out_h = out;
    float* out_x = out + NN * HH;
    float* out_v = out + NN * HH + NN * 2;

    float *p_h, *p_macc;
    cudaGetSymbolAddress((void**)&p_h,    g_h);
    cudaGetSymbolAddress((void**)&p_macc, g_macc);

    cudaFuncSetAttribute(node_mma_m12, cudaFuncAttributeMaxDynamicSharedMemorySize, NM_SMEM);
    cudaFuncSetAttribute(node_mma_th, cudaFuncAttributeMaxDynamicSharedMemorySize, NM_SMEM);
    cudaFuncSetAttribute(node_mma_v, cudaFuncAttributeMaxDynamicSharedMemorySize, NM_SMEM);
    cudaFuncSetAttribute(edge2_kernel, cudaFuncAttributeMaxDynamicSharedMemorySize, EK2_SMEM);
    cudaFuncSetAttribute(prep_frag_kernel, cudaFuncAttributeMaxDynamicSharedMemorySize, 69632);

    const int GB = (NN + 127) / 128;

    // side streams + events, created fresh every call and destroyed before return
    cudaStream_t s1, s2;
    cudaStreamCreateWithFlags(&s1, cudaStreamNonBlocking);
    cudaStreamCreateWithFlags(&s2, cudaStreamNonBlocking);
    cudaEvent_t eFork, eSort, eFork2, eEdge, eX;
    cudaEventCreateWithFlags(&eFork,  cudaEventDisableTiming);
    cudaEventCreateWithFlags(&eSort,  cudaEventDisableTiming);
    cudaEventCreateWithFlags(&eFork2, cudaEventDisableTiming);
    cudaEventCreateWithFlags(&eEdge,  cudaEventDisableTiming);
    cudaEventCreateWithFlags(&eX,     cudaEventDisableTiming);

    cudaEventRecord(eFork, 0);

    // --- branch s1: sort pipeline ---
    cudaStreamWaitEvent(s1, eFork, 0);
    zero_cnt_scat_kernel<<<(NN * 2 + 255) / 256, 256, 0, s1>>>();
    count_kernel<<<(EE + 255) / 256, 256, 0, s1>>>(ei);
    scan1_kernel<<<SCAN_B, 256, 0, s1>>>();
    scan2_kernel<<<1, 256, 0, s1>>>();
    scan3_kernel<<<SCAN_B, 256, 0, s1>>>();
    scatter_kernel<<<(EE + 255) / 256, 256, 0, s1>>>(ei);
    cudaEventRecord(eSort, s1);

    // --- branch s2: copy x out ---
    cudaStreamWaitEvent(s2, eFork, 0);
    copy_x_kernel<<<(NN * 2 + 255) / 256, 256, 0, s2>>>(x, out_x);
    cudaEventRecord(eX, s2);

    // --- main: weight prep (transpose, then fragment tables) + embed ---
    {
        dim3 g(128, 7);
        prep_all_kernel<<<g, 128>>>(eW1, nW1, nW2, vW1, eW2, cW1, eb2, cb1);
    }
    prep_frag_kernel<<<7, 256, 69632>>>();
    embed_kernel<<<NN / 2, 256>>>(h0, embW, embB);

    // ---- layer 0 ----
    node_mma_m12<<<GB, 512, NM_SMEM>>>(p_h);
    cudaStreamWaitEvent(0, eSort, 0);
    macc_gather_kernel<<<(NN * 32 + 255) / 256, 256>>>(x, eW1, eb1);
    node_mma_th<<<GB, 512, NM_SMEM>>>(p_h, p_macc, nb1, nb2, p_h);

    // ---- layer 1 ----
    node_mma_m12<<<GB, 512, NM_SMEM>>>(p_h);
    cudaEventRecord(eFork2, 0);
    cudaStreamWaitEvent(s1, eFork2, 0);
    edge2_kernel<<<EE / 128, 256, EK2_SMEM, s1>>>(x, eW1, eb1, cW2, cb2);
    cudaEventRecord(eEdge, s1);
    macc_gather_kernel<<<(NN * 32 + 255) / 256, 256>>>(x, eW1, eb1);
    node_mma_th<<<GB, 512, NM_SMEM>>>(p_h, p_macc, nb1, nb2, out_h);

    // join: v epilogue needs edge2's g_scat and th's out_h
    cudaStreamWaitEvent(0, eEdge, 0);
    node_mma_v<<<GB, 512, NM_SMEM>>>(out_h, vb1, vW2, vb2, out_v);
    cudaStreamWaitEvent(0, eX, 0);

    // cleanup (allocation guard: return device memory to baseline)
    cudaEventDestroy(eFork);
    cudaEventDestroy(eSort);
    cudaEventDestroy(eFork2);
    cudaEventDestroy(eEdge);
    cudaEventDestroy(eX);
    cudaStreamDestroy(s1);
    cudaStreamDestroy(s2);
}